// round 11
// baseline (speedup 1.0000x reference)
#include <cuda_runtime.h>
#include <cuda_bf16.h>
#include <cstdint>

// Problem dims
#define BB 2
#define TT 2048
#define HH 16
#define DD 64
#define EE 1024   // HH*DD
#define OO 1024

// Scratch (device globals)
__device__ float g_qkv[(size_t)3 * BB * TT * EE];     // q | k | v contiguous
__device__ float g_mh[(size_t)BB * TT * EE];
__device__ float g_vt[(size_t)BB * TT * EE];          // V transposed: [b][h][d][m]
__device__ float g_pkt[(size_t)EE * OO];              // proj kernel transposed: [o][k]
__device__ float g_rowsum[(size_t)BB * HH * TT];      // exp row sums -> inverses
__device__ float g_out_scratch[(size_t)BB * TT * OO];
__device__ float g_attn_scratch[(size_t)BB * HH * TT * TT];

// ---------------------------------------------------------------------------
// PTX helpers (baseline features only: sm_80-era, legal at compute_103)
// ---------------------------------------------------------------------------
__device__ __forceinline__ uint32_t smem_u32(const void* p) {
    uint32_t a;
    asm("{ .reg .u64 t; cvta.to.shared.u64 t, %1; cvt.u32.u64 %0, t; }" : "=r"(a) : "l"(p));
    return a;
}
#define CP_ASYNC16(dst_u32, src_ptr) \
    asm volatile("cp.async.cg.shared.global [%0], [%1], 16;" :: "r"(dst_u32), "l"(src_ptr))
#define CP_COMMIT() asm volatile("cp.async.commit_group;" ::: "memory")
#define CP_WAIT1()  asm volatile("cp.async.wait_group 1;" ::: "memory")
#define CP_WAIT0()  asm volatile("cp.async.wait_group 0;" ::: "memory")

__device__ __forceinline__ void mma16816(float* c, const uint32_t* a, const uint32_t* b) {
    asm volatile(
        "mma.sync.aligned.m16n8k16.row.col.f32.bf16.bf16.f32 "
        "{%0,%1,%2,%3}, {%4,%5,%6,%7}, {%8,%9}, {%0,%1,%2,%3};"
        : "+f"(c[0]), "+f"(c[1]), "+f"(c[2]), "+f"(c[3])
        : "r"(a[0]), "r"(a[1]), "r"(a[2]), "r"(a[3]), "r"(b[0]), "r"(b[1]));
}

__device__ __forceinline__ void ldsm_x4(uint32_t& r0, uint32_t& r1, uint32_t& r2, uint32_t& r3,
                                        uint32_t addr) {
    asm volatile("ldmatrix.sync.aligned.m8n8.x4.shared.b16 {%0,%1,%2,%3}, [%4];"
                 : "=r"(r0), "=r"(r1), "=r"(r2), "=r"(r3) : "r"(addr));
}

__device__ __forceinline__ void split_store(float4 x, uint32_t* dh, uint32_t* dl) {
    __nv_bfloat162 h0 = __floats2bfloat162_rn(x.x, x.y);
    __nv_bfloat162 h1 = __floats2bfloat162_rn(x.z, x.w);
    float l0 = x.x - __bfloat162float(h0.x);
    float l1 = x.y - __bfloat162float(h0.y);
    float l2 = x.z - __bfloat162float(h1.x);
    float l3 = x.w - __bfloat162float(h1.y);
    __nv_bfloat162 lo0 = __floats2bfloat162_rn(l0, l1);
    __nv_bfloat162 lo1 = __floats2bfloat162_rn(l2, l3);
    *(uint2*)dh = make_uint2(*(uint32_t*)&h0, *(uint32_t*)&h1);
    *(uint2*)dl = make_uint2(*(uint32_t*)&lo0, *(uint32_t*)&lo1);
}

__device__ __forceinline__ uint32_t packbf(float a, float b) {
    __nv_bfloat162 h = __floats2bfloat162_rn(a, b);
    return *(uint32_t*)&h;
}

// ---------------------------------------------------------------------------
// cp.async double-buffered tensor-core GEMM with ldmatrix fragment loads:
//   C[M,N] = alpha * A[M,K] * B[N,K]^T (+bias)
// MODE 0: plain epilogue.   MODE 3: rowsum only (exp sums, NO C store).
// BATCH3=1: blockIdx.z selects (A,A1,A2)/(B,B1,B2), C += z*sC1.
// ---------------------------------------------------------------------------
template <int NTILE, int BATCH3, int MODE>
__global__ __launch_bounds__(256, 2) void mma_gemm(
    const float* __restrict__ A, const float* __restrict__ A1q, const float* __restrict__ A2q,
    int lda, int zdiv, long long sA1, long long sA2,
    const float* __restrict__ Bm, const float* __restrict__ B1q, const float* __restrict__ B2q,
    int ldb, long long sB1, long long sB2,
    float* __restrict__ C, int ldc, long long sC1, long long sC2,
    int K, float alpha, const float* __restrict__ bias,
    float* rowsum)
{
    constexpr int WROW  = 20;
    constexpr int ROWS  = 128 + NTILE;
    constexpr int NLOOP = ROWS / 32;
    constexpr int RAWW  = ROWS * 32;
    constexpr int WM    = (NTILE == 128) ? 2 : 4;
    constexpr int MI    = 128 / (WM * 16);
    constexpr int NI    = 4;
    constexpr int AHL   = 128 * WROW;
    constexpr int BOFF  = 2 * AHL;
    constexpr int BHL   = NTILE * WROW;

    extern __shared__ char smem[];
    float*    raw0p = (float*)smem;
    float*    raw1p = (float*)(smem + RAWW * 4);
    uint32_t* bw    = (uint32_t*)(smem + 2 * RAWW * 4);
    const uint32_t raw0a = smem_u32(raw0p);
    const uint32_t raw1a = raw0a + RAWW * 4;
    const uint32_t bwa   = raw0a + 2 * RAWW * 4;

    const int z = blockIdx.z;
    if (BATCH3) {
        A  = (z == 0) ? A  : (z == 1 ? A1q : A2q);
        Bm = (z == 0) ? Bm : (z == 1 ? B1q : B2q);
        C += (long long)z * sC1;
    } else {
        const int z1 = z / zdiv, z2 = z % zdiv;
        A  += (long long)z1 * sA1 + (long long)z2 * sA2;
        Bm += (long long)z1 * sB1 + (long long)z2 * sB2;
        if (MODE == 0) C += (long long)z1 * sC1 + (long long)z2 * sC2;
    }
    float* rowsumz = (MODE == 3) ? rowsum + (long long)z * TT : nullptr;

    const int m0 = blockIdx.y * 128;
    const int n0 = blockIdx.x * NTILE;

    const int tid  = threadIdx.x;
    const int warp = tid >> 5;
    const int lane = tid & 31;
    const int wm   = warp % WM;
    const int wn   = warp / WM;
    const int g    = lane >> 2;
    const int tg   = lane & 3;

    uint32_t a_addr[2][MI], b_addr[2][2];
    {
        const int lm  = lane & 7;
        const int l8  = (lane >> 3) & 1;
        const int l16 = lane >> 4;
        const int bm  = lane >> 3;
#pragma unroll
        for (int kk2 = 0; kk2 < 2; kk2++) {
#pragma unroll
            for (int mi = 0; mi < MI; mi++) {
                const int row = wm * (MI * 16) + mi * 16 + lm + l8 * 8;
                const int off = kk2 * 8 + l16 * 4;
                a_addr[kk2][mi] = bwa + (uint32_t)(row * WROW + off) * 4;
            }
#pragma unroll
            for (int np = 0; np < 2; np++) {
                const int nrow = wn * 32 + np * 16 + (bm >> 1) * 8 + lm;
                const int koff = kk2 * 8 + (bm & 1) * 4;
                b_addr[kk2][np] = bwa + (uint32_t)(BOFF + nrow * WROW + koff) * 4;
            }
        }
    }

    float acc[MI][NI][4];
#pragma unroll
    for (int mi = 0; mi < MI; mi++)
#pragma unroll
        for (int ni = 0; ni < NI; ni++)
#pragma unroll
            for (int r = 0; r < 4; r++) acc[mi][ni][r] = 0.f;

#pragma unroll
    for (int i = 0; i < NLOOP; i++) {
        const int idx = tid + i * 256;
        const bool isA = idx < 1024;
        const int r = isA ? (idx >> 3) : ((idx - 1024) >> 3);
        const int c = (idx & 7) * 4;
        const float* src = isA ? &A[(long long)(m0 + r) * lda + c]
                               : &Bm[(long long)(n0 + r) * ldb + c];
        CP_ASYNC16(raw0a + idx * 16, src);
    }
    CP_COMMIT();

    const int NIT = K / 32;

    for (int it = 0; it < NIT; it++) {
        const bool more = (it + 1) < NIT;
        const int kbn = (it + 1) * 32;
        if (more) {
            const uint32_t rdst = ((it + 1) & 1) ? raw1a : raw0a;
#pragma unroll
            for (int i = 0; i < NLOOP; i++) {
                const int idx = tid + i * 256;
                const bool isA = idx < 1024;
                const int r = isA ? (idx >> 3) : ((idx - 1024) >> 3);
                const int c = (idx & 7) * 4;
                const float* src = isA ? &A[(long long)(m0 + r) * lda + kbn + c]
                                       : &Bm[(long long)(n0 + r) * ldb + kbn + c];
                CP_ASYNC16(rdst + idx * 16, src);
            }
            CP_COMMIT();
            CP_WAIT1();
        } else {
            CP_WAIT0();
        }

        {
            const float* rbuf = (it & 1) ? raw1p : raw0p;
#pragma unroll
            for (int i = 0; i < NLOOP; i++) {
                const int idx = tid + i * 256;
                const bool isA = idx < 1024;
                const int r = isA ? (idx >> 3) : ((idx - 1024) >> 3);
                const int c = (idx & 7) * 4;
                float4 x = *(const float4*)(rbuf + idx * 4);
                const uint32_t w = r * WROW + (c >> 1);
                uint32_t* dh = bw + (isA ? 0 : BOFF) + w;
                uint32_t* dl = dh + (isA ? AHL : BHL);
                split_store(x, dh, dl);
            }
        }
        __syncthreads();

        {
#pragma unroll
            for (int kk2 = 0; kk2 < 2; kk2++) {
                uint32_t bh[NI][2], bl[NI][2];
#pragma unroll
                for (int np = 0; np < 2; np++) {
                    ldsm_x4(bh[np * 2][0], bh[np * 2][1], bh[np * 2 + 1][0], bh[np * 2 + 1][1],
                            b_addr[kk2][np]);
                    ldsm_x4(bl[np * 2][0], bl[np * 2][1], bl[np * 2 + 1][0], bl[np * 2 + 1][1],
                            b_addr[kk2][np] + BHL * 4);
                }
#pragma unroll
                for (int mi = 0; mi < MI; mi++) {
                    uint32_t ah[4], al[4];
                    ldsm_x4(ah[0], ah[1], ah[2], ah[3], a_addr[kk2][mi]);
                    ldsm_x4(al[0], al[1], al[2], al[3], a_addr[kk2][mi] + AHL * 4);
#pragma unroll
                    for (int ni = 0; ni < NI; ni++) {
                        mma16816(acc[mi][ni], ah, bh[ni]);
                        mma16816(acc[mi][ni], ah, bl[ni]);
                        mma16816(acc[mi][ni], al, bh[ni]);
                    }
                }
            }
        }
        if (more) __syncthreads();
    }

    // ---- epilogue ----
#pragma unroll
    for (int mi = 0; mi < MI; mi++) {
        const int r0 = m0 + wm * (MI * 16) + mi * 16 + g;
        const int r1 = r0 + 8;
        float p0 = 0.f, p1 = 0.f;
#pragma unroll
        for (int ni = 0; ni < NI; ni++) {
            const int c = n0 + wn * 32 + ni * 8 + tg * 2;
            if (MODE == 3) {
                p0 += __expf(acc[mi][ni][0] * alpha) + __expf(acc[mi][ni][1] * alpha);
                p1 += __expf(acc[mi][ni][2] * alpha) + __expf(acc[mi][ni][3] * alpha);
            } else {
                float2 bv = make_float2(0.f, 0.f);
                if (bias) bv = *(const float2*)&bias[c];
                float2 o0, o1;
                o0.x = acc[mi][ni][0] * alpha + bv.x;
                o0.y = acc[mi][ni][1] * alpha + bv.y;
                o1.x = acc[mi][ni][2] * alpha + bv.x;
                o1.y = acc[mi][ni][3] * alpha + bv.y;
                *(float2*)&C[(long long)r0 * ldc + c] = o0;
                *(float2*)&C[(long long)r1 * ldc + c] = o1;
            }
        }
        if (MODE == 3) {
            p0 += __shfl_xor_sync(0xffffffffu, p0, 1);
            p0 += __shfl_xor_sync(0xffffffffu, p0, 2);
            p1 += __shfl_xor_sync(0xffffffffu, p1, 1);
            p1 += __shfl_xor_sync(0xffffffffu, p1, 2);
            if (tg == 0) {
                atomicAdd(&rowsumz[r0], p0);
                atomicAdd(&rowsumz[r1], p1);
            }
        }
    }
}

// ---------------------------------------------------------------------------
// Fused flash-style kernel: per (z, m-tile 128):
//   loop over 16 n-tiles: logits MMA -> normalized exp -> attn write (ONLY
//   attn pass) -> P fragments rebuilt from accumulators -> P@V^T MMA -> mh.
// Warp layout: 8 warps x (16m x 128n): each warp owns full k-slice, no
// cross-warp reduction for mh.
// ---------------------------------------------------------------------------
__global__ __launch_bounds__(256, 1) void flash_av(
    const float* __restrict__ Qg, const float* __restrict__ Kg,
    const float* __restrict__ Vt, const float* __restrict__ invr,
    float* __restrict__ attn, float* __restrict__ mh)
{
    constexpr int QROW = 36;       // words per Q/K smem row (64 bf16 + pad)
    constexpr int VROW = 68;       // words per V smem row (128 bf16 + pad)
    constexpr int QH = 0, QL = 4608, KH = 9216, KL = 13824;
    constexpr int VH = 18432, VL = 22784, RAW = 27136;
    constexpr float ALPHA = 0.125f;

    extern __shared__ char smem[];
    uint32_t* sw = (uint32_t*)smem;
    float* rawf = (float*)(sw + RAW);
    const uint32_t sb = smem_u32(sw);
    const uint32_t rawa = sb + RAW * 4;

    const int z = blockIdx.y;
    const int b = z / HH, h = z % HH;
    const int m0 = blockIdx.x * 128;

    const float* Qb = Qg + ((long long)b * TT) * EE + h * DD;
    const float* Kb = Kg + ((long long)b * TT) * EE + h * DD;
    const float* Vb = Vt + (long long)z * DD * TT;
    float* attnz = attn + (long long)z * TT * TT;
    const float* invz = invr + (long long)z * TT;

    const int tid = threadIdx.x, w = tid >> 5, lane = tid & 31;
    const int g = lane >> 2, tg = lane & 3;
    const int lm = lane & 7, l8 = (lane >> 3) & 1, l16 = lane >> 4, bm = lane >> 3;
    const int krow = (bm >> 1) * 8 + lm;
    const int koffB = (bm & 1) * 4;

    const float inv0 = invz[m0 + w * 16 + g];
    const float inv1 = invz[m0 + w * 16 + g + 8];

    uint32_t qa[4];
#pragma unroll
    for (int kk = 0; kk < 4; kk++)
        qa[kk] = sb + (uint32_t)(QH + (w * 16 + lm + l8 * 8) * QROW + kk * 8 + l16 * 4) * 4;

    float macc[8][4];
#pragma unroll
    for (int i = 0; i < 8; i++)
#pragma unroll
        for (int r = 0; r < 4; r++) macc[i][r] = 0.f;

    // ---- stage Q once ----
#pragma unroll
    for (int i = 0; i < 8; i++) {
        const int idx = tid + i * 256;
        const int r = idx >> 4, c = (idx & 15) * 4;
        CP_ASYNC16(rawa + idx * 16, Qb + (long long)(m0 + r) * EE + c);
    }
    CP_COMMIT(); CP_WAIT0();
#pragma unroll
    for (int i = 0; i < 8; i++) {
        const int idx = tid + i * 256;
        const int r = idx >> 4, c = (idx & 15) * 4;
        float4 x = *(const float4*)(rawf + idx * 4);
        uint32_t* dh = sw + QH + r * QROW + (c >> 1);
        split_store(x, dh, dh + (QL - QH));
    }
    __syncthreads();

    // ---- prologue: stage K/V tile 0 ----
#pragma unroll
    for (int i = 0; i < 8; i++) {
        const int idx = tid + i * 256;
        const int r = idx >> 4, c = (idx & 15) * 4;
        CP_ASYNC16(rawa + idx * 16, Kb + (long long)r * EE + c);
    }
#pragma unroll
    for (int i = 0; i < 8; i++) {
        const int idx = tid + i * 256;
        const int r = idx >> 5, c = (idx & 31) * 4;
        CP_ASYNC16(rawa + (8192 + idx * 4) * 4, Vb + (long long)r * TT + c);
    }
    CP_COMMIT();

    for (int nt = 0; nt < 16; nt++) {
        CP_WAIT0();   // own raw groups arrived
        // convert own groups: K tile
#pragma unroll
        for (int i = 0; i < 8; i++) {
            const int idx = tid + i * 256;
            const int r = idx >> 4, c = (idx & 15) * 4;
            float4 x = *(const float4*)(rawf + idx * 4);
            uint32_t* dh = sw + KH + r * QROW + (c >> 1);
            split_store(x, dh, dh + (KL - KH));
        }
        // V tile
#pragma unroll
        for (int i = 0; i < 8; i++) {
            const int idx = tid + i * 256;
            const int r = idx >> 5, c = (idx & 31) * 4;
            float4 x = *(const float4*)(rawf + (8192 + idx * 4));
            uint32_t* dh = sw + VH + r * VROW + (c >> 1);
            split_store(x, dh, dh + (VL - VH));
        }
        __syncthreads();   // smem tiles visible to all; raw self-consumed

        // issue prefetch of next K/V tile (into freed raw)
        if (nt + 1 < 16) {
            const int nb = (nt + 1) * 128;
#pragma unroll
            for (int i = 0; i < 8; i++) {
                const int idx = tid + i * 256;
                const int r = idx >> 4, c = (idx & 15) * 4;
                CP_ASYNC16(rawa + idx * 16, Kb + (long long)(nb + r) * EE + c);
            }
#pragma unroll
            for (int i = 0; i < 8; i++) {
                const int idx = tid + i * 256;
                const int r = idx >> 5, c = (idx & 31) * 4;
                CP_ASYNC16(rawa + (8192 + idx * 4) * 4, Vb + (long long)r * TT + nb + c);
            }
            CP_COMMIT();
        }

        // ---- logits MMA: lacc[16][4] ----
        float lacc[16][4];
#pragma unroll
        for (int ni = 0; ni < 16; ni++)
#pragma unroll
            for (int r = 0; r < 4; r++) lacc[ni][r] = 0.f;

#pragma unroll
        for (int kk = 0; kk < 4; kk++) {
            uint32_t ah[4], al[4];
            ldsm_x4(ah[0], ah[1], ah[2], ah[3], qa[kk]);
            ldsm_x4(al[0], al[1], al[2], al[3], qa[kk] + (QL - QH) * 4);
#pragma unroll
            for (int np = 0; np < 8; np++) {
                const uint32_t addr = sb + (uint32_t)(KH + (np * 16 + krow) * QROW + kk * 8 + koffB) * 4;
                uint32_t bh0[2], bh1[2], bl0[2], bl1[2];
                ldsm_x4(bh0[0], bh0[1], bh1[0], bh1[1], addr);
                ldsm_x4(bl0[0], bl0[1], bl1[0], bl1[1], addr + (KL - KH) * 4);
                mma16816(lacc[np * 2],     ah, bh0);
                mma16816(lacc[np * 2],     ah, bl0);
                mma16816(lacc[np * 2],     al, bh0);
                mma16816(lacc[np * 2 + 1], ah, bh1);
                mma16816(lacc[np * 2 + 1], ah, bl1);
                mma16816(lacc[np * 2 + 1], al, bh1);
            }
        }

        // ---- exp, attn write, P@V per k16 chunk ----
        const int row0 = m0 + w * 16 + g;
#pragma unroll
        for (int kv = 0; kv < 8; kv++) {
            float p0 = __expf(lacc[2 * kv][0] * ALPHA) * inv0;
            float p1 = __expf(lacc[2 * kv][1] * ALPHA) * inv0;
            float p2 = __expf(lacc[2 * kv][2] * ALPHA) * inv1;
            float p3 = __expf(lacc[2 * kv][3] * ALPHA) * inv1;
            float p4 = __expf(lacc[2 * kv + 1][0] * ALPHA) * inv0;
            float p5 = __expf(lacc[2 * kv + 1][1] * ALPHA) * inv0;
            float p6 = __expf(lacc[2 * kv + 1][2] * ALPHA) * inv1;
            float p7 = __expf(lacc[2 * kv + 1][3] * ALPHA) * inv1;

            const int col = nt * 128 + kv * 16 + tg * 2;
            *(float2*)&attnz[(long long)row0 * TT + col]           = make_float2(p0, p1);
            *(float2*)&attnz[(long long)(row0 + 8) * TT + col]     = make_float2(p2, p3);
            *(float2*)&attnz[(long long)row0 * TT + col + 8]       = make_float2(p4, p5);
            *(float2*)&attnz[(long long)(row0 + 8) * TT + col + 8] = make_float2(p6, p7);

            // A fragments for P@V (C-frag -> A-frag identity)
            uint32_t ph[4], pl[4];
            ph[0] = packbf(p0, p1); ph[1] = packbf(p2, p3);
            ph[2] = packbf(p4, p5); ph[3] = packbf(p6, p7);
            {
                __nv_bfloat162 h;
                h = *(__nv_bfloat162*)&ph[0];
                pl[0] = packbf(p0 - __bfloat162float(h.x), p1 - __bfloat162float(h.y));
                h = *(__nv_bfloat162*)&ph[1];
                pl[1] = packbf(p2 - __bfloat162float(h.x), p3 - __bfloat162float(h.y));
                h = *(__nv_bfloat162*)&ph[2];
                pl[2] = packbf(p4 - __bfloat162float(h.x), p5 - __bfloat162float(h.y));
                h = *(__nv_bfloat162*)&ph[3];
                pl[3] = packbf(p6 - __bfloat162float(h.x), p7 - __bfloat162float(h.y));
            }

#pragma unroll
            for (int dnp = 0; dnp < 4; dnp++) {
                const uint32_t addrv = sb + (uint32_t)(VH + (dnp * 16 + krow) * VROW + kv * 8 + koffB) * 4;
                uint32_t vh0[2], vh1[2], vl0[2], vl1[2];
                ldsm_x4(vh0[0], vh0[1], vh1[0], vh1[1], addrv);
                ldsm_x4(vl0[0], vl0[1], vl1[0], vl1[1], addrv + (VL - VH) * 4);
                mma16816(macc[dnp * 2],     ph, vh0);
                mma16816(macc[dnp * 2],     ph, vl0);
                mma16816(macc[dnp * 2],     pl, vh0);
                mma16816(macc[dnp * 2 + 1], ph, vh1);
                mma16816(macc[dnp * 2 + 1], ph, vl1);
                mma16816(macc[dnp * 2 + 1], pl, vh1);
            }
        }
        __syncthreads();   // all warps done reading K/V smem before next convert
    }

    // ---- write mh ----
    float* mhb = mh + ((long long)b * TT) * EE + h * DD;
    const int row0 = m0 + w * 16 + g;
#pragma unroll
    for (int ni = 0; ni < 8; ni++) {
        const int col = ni * 8 + tg * 2;
        *(float2*)&mhb[(long long)row0 * EE + col]       = make_float2(macc[ni][0], macc[ni][1]);
        *(float2*)&mhb[(long long)(row0 + 8) * EE + col] = make_float2(macc[ni][2], macc[ni][3]);
    }
}

// ---------------------------------------------------------------------------
// rowsum helpers
// ---------------------------------------------------------------------------
__global__ void zero_rowsum(float* rs) {
    rs[blockIdx.x * 256 + threadIdx.x] = 0.f;
}
__global__ void invert_rowsum(float* rs) {
    const int i = blockIdx.x * 256 + threadIdx.x;
    rs[i] = 1.f / rs[i];
}

// ---------------------------------------------------------------------------
// Transposes
// ---------------------------------------------------------------------------
__global__ __launch_bounds__(256) void transpose_v(const float* __restrict__ v,
                                                   float* __restrict__ vt)
{
    __shared__ float tile[32][33];
    const int z = blockIdx.z;
    const int b = z / HH, h = z % HH;
    const int m0 = blockIdx.x * 32;
    const int d0 = blockIdx.y * 32;
    const int tx = threadIdx.x & 31;
    const int ty0 = threadIdx.x >> 5;
#pragma unroll
    for (int ty = ty0; ty < 32; ty += 8)
        tile[ty][tx] = v[((long long)b * TT + m0 + ty) * EE + h * DD + d0 + tx];
    __syncthreads();
#pragma unroll
    for (int ty = ty0; ty < 32; ty += 8)
        vt[(((long long)z) * DD + d0 + ty) * TT + m0 + tx] = tile[tx][ty];
}

__global__ __launch_bounds__(256) void transpose_pk(const float* __restrict__ pk,
                                                    float* __restrict__ pkt)
{
    __shared__ float tile[32][33];
    const int k0 = blockIdx.x * 32;
    const int o0 = blockIdx.y * 32;
    const int tx = threadIdx.x & 31;
    const int ty0 = threadIdx.x >> 5;
#pragma unroll
    for (int ty = ty0; ty < 32; ty += 8)
        tile[ty][tx] = pk[(long long)(k0 + ty) * OO + o0 + tx];
    __syncthreads();
#pragma unroll
    for (int ty = ty0; ty < 32; ty += 8)
        pkt[(long long)(o0 + ty) * EE + k0 + tx] = tile[tx][ty];
}

// ---------------------------------------------------------------------------
// Launch
// ---------------------------------------------------------------------------
extern "C" void kernel_launch(void* const* d_in, const int* in_sizes, int n_in,
                              void* d_out, int out_size)
{
    const float* query = (const float*)d_in[0];
    const float* key   = (const float*)d_in[1];
    const float* value = (const float*)d_in[2];
    const float* Wq    = (const float*)d_in[3];
    const float* Wk    = (const float*)d_in[4];
    const float* Wv    = (const float*)d_in[5];
    const float* pk    = (const float*)d_in[6];
    const float* pb    = (const float*)d_in[7];

    float *qkvp, *mhp, *vtp, *pktp, *rsp, *outs, *attns;
    cudaGetSymbolAddress((void**)&qkvp,  g_qkv);
    cudaGetSymbolAddress((void**)&mhp,   g_mh);
    cudaGetSymbolAddress((void**)&vtp,   g_vt);
    cudaGetSymbolAddress((void**)&pktp,  g_pkt);
    cudaGetSymbolAddress((void**)&rsp,   g_rowsum);
    cudaGetSymbolAddress((void**)&outs,  g_out_scratch);
    cudaGetSymbolAddress((void**)&attns, g_attn_scratch);

    const long long qkvN = (long long)BB * TT * EE;
    float* qp = qkvp;
    float* kp = qkvp + qkvN;
    float* vp = qkvp + 2 * qkvN;

    const long long outN  = (long long)BB * TT * OO;
    const long long attnN = (long long)BB * HH * TT * TT;

    float* outP  = (float*)d_out;
    float* attnP;
    if ((long long)out_size >= outN + attnN) {
        attnP = outP + outN;
    } else if ((long long)out_size == attnN) {
        attnP = (float*)d_out;
        outP  = outs;
    } else {
        attnP = attns;
    }

    constexpr int SMEM128 = (2 * 256 * 32 + 256 * 40) * 4;  // 106496
    constexpr int SMEMFL  = 43520 * 4;                       // 174080
    cudaFuncSetAttribute(mma_gemm<128, 1, 0>, cudaFuncAttributeMaxDynamicSharedMemorySize, SMEM128);
    cudaFuncSetAttribute(mma_gemm<128, 0, 0>, cudaFuncAttributeMaxDynamicSharedMemorySize, SMEM128);
    cudaFuncSetAttribute(mma_gemm<128, 0, 3>, cudaFuncAttributeMaxDynamicSharedMemorySize, SMEM128);
    cudaFuncSetAttribute(flash_av, cudaFuncAttributeMaxDynamicSharedMemorySize, SMEMFL);

    // 0) zero row sums (graph-replay safe)
    zero_rowsum<<<(BB * HH * TT) / 256, 256>>>(rsp);

    // 1) Q/K/V projections, batched over z = 0,1,2
    {
        dim3 grid(EE / 128, (BB * TT) / 128, 3);
        mma_gemm<128, 1, 0><<<grid, 256, SMEM128>>>(
            query, key, value, EE, 1, 0, 0,
            Wq, Wk, Wv, EE, 0, 0,
            qkvp, EE, qkvN, 0,
            EE, 1.f, nullptr, nullptr);
    }

    // transposes: V -> [b][h][d][m], pk -> [o][k]
    {
        dim3 gv(TT / 32, DD / 32, BB * HH);
        transpose_v<<<gv, 256>>>(vp, vtp);
        dim3 gp(EE / 32, OO / 32, 1);
        transpose_pk<<<gp, 256>>>(pk, pktp);
    }

    // 2) Pass A: row sums of exp(0.125 * q @ k^T) -- NO attn write
    {
        dim3 grid(TT / 128, TT / 128, BB * HH);
        mma_gemm<128, 0, 3><<<grid, 256, SMEM128>>>(
            qp, nullptr, nullptr, EE, HH, (long long)TT * EE, DD,
            kp, nullptr, nullptr, EE,     (long long)TT * EE, DD,
            nullptr, TT, 0, 0,
            DD, 0.125f, nullptr, rsp);
    }

    // 3) invert row sums
    invert_rowsum<<<(BB * HH * TT) / 256, 256>>>(rsp);

    // 4) Pass B: fused logits+softmax+AV; writes normalized attn ONCE + mh
    {
        dim3 grid(TT / 128, BB * HH);
        flash_av<<<grid, 256, SMEMFL>>>(qp, kp, vtp, rsp, attnP, mhp);
    }

    // 5) out = mh @ pkT^T + bias
    {
        dim3 grid(OO / 128, (BB * TT) / 128, 1);
        mma_gemm<128, 0, 0><<<grid, 256, SMEM128>>>(
            mhp, nullptr, nullptr, EE, 1, 0, 0,
            pktp, nullptr, nullptr, EE, 0, 0,
            outP, OO, 0, 0, EE, 1.f, pb, nullptr);
    }
}

// round 12
// speedup vs baseline: 1.1321x; 1.1321x over previous
#include <cuda_runtime.h>
#include <cuda_bf16.h>
#include <cuda_fp16.h>
#include <cstdint>

// Problem dims
#define BB 2
#define TT 2048
#define HH 16
#define DD 64
#define EE 1024   // HH*DD
#define OO 1024

// Scratch (device globals)
__device__ float g_qkv[(size_t)3 * BB * TT * EE];     // q | k | v contiguous
__device__ float g_mh[(size_t)BB * TT * EE];
__device__ float g_vt[(size_t)BB * TT * EE];          // V transposed: [b][h][d][m]
__device__ float g_pkt[(size_t)EE * OO];              // proj kernel transposed: [o][k]
__device__ float g_rowsum[(size_t)BB * HH * TT];      // exp row sums -> inverses
__device__ __half g_exph[(size_t)BB * HH * TT * TT];  // fp16 exp(logits) intermediate
__device__ float g_out_scratch[(size_t)BB * TT * OO];
__device__ float g_attn_scratch[(size_t)BB * HH * TT * TT];

// ---------------------------------------------------------------------------
// PTX helpers (baseline features only: sm_80-era, legal at compute_103)
// ---------------------------------------------------------------------------
__device__ __forceinline__ uint32_t smem_u32(const void* p) {
    uint32_t a;
    asm("{ .reg .u64 t; cvta.to.shared.u64 t, %1; cvt.u32.u64 %0, t; }" : "=r"(a) : "l"(p));
    return a;
}
#define CP_ASYNC16(dst_u32, src_ptr) \
    asm volatile("cp.async.cg.shared.global [%0], [%1], 16;" :: "r"(dst_u32), "l"(src_ptr))
#define CP_COMMIT() asm volatile("cp.async.commit_group;" ::: "memory")
#define CP_WAIT1()  asm volatile("cp.async.wait_group 1;" ::: "memory")
#define CP_WAIT0()  asm volatile("cp.async.wait_group 0;" ::: "memory")

__device__ __forceinline__ void mma16816(float* c, const uint32_t* a, const uint32_t* b) {
    asm volatile(
        "mma.sync.aligned.m16n8k16.row.col.f32.bf16.bf16.f32 "
        "{%0,%1,%2,%3}, {%4,%5,%6,%7}, {%8,%9}, {%0,%1,%2,%3};"
        : "+f"(c[0]), "+f"(c[1]), "+f"(c[2]), "+f"(c[3])
        : "r"(a[0]), "r"(a[1]), "r"(a[2]), "r"(a[3]), "r"(b[0]), "r"(b[1]));
}

__device__ __forceinline__ void ldsm_x4(uint32_t& r0, uint32_t& r1, uint32_t& r2, uint32_t& r3,
                                        uint32_t addr) {
    asm volatile("ldmatrix.sync.aligned.m8n8.x4.shared.b16 {%0,%1,%2,%3}, [%4];"
                 : "=r"(r0), "=r"(r1), "=r"(r2), "=r"(r3) : "r"(addr));
}

__device__ __forceinline__ void split_store(float4 x, uint32_t* dh, uint32_t* dl) {
    __nv_bfloat162 h0 = __floats2bfloat162_rn(x.x, x.y);
    __nv_bfloat162 h1 = __floats2bfloat162_rn(x.z, x.w);
    float l0 = x.x - __bfloat162float(h0.x);
    float l1 = x.y - __bfloat162float(h0.y);
    float l2 = x.z - __bfloat162float(h1.x);
    float l3 = x.w - __bfloat162float(h1.y);
    __nv_bfloat162 lo0 = __floats2bfloat162_rn(l0, l1);
    __nv_bfloat162 lo1 = __floats2bfloat162_rn(l2, l3);
    *(uint2*)dh = make_uint2(*(uint32_t*)&h0, *(uint32_t*)&h1);
    *(uint2*)dl = make_uint2(*(uint32_t*)&lo0, *(uint32_t*)&lo1);
}

__device__ __forceinline__ uint32_t packbf(float a, float b) {
    __nv_bfloat162 h = __floats2bfloat162_rn(a, b);
    return *(uint32_t*)&h;
}

// ---------------------------------------------------------------------------
// cp.async double-buffered tensor-core GEMM with ldmatrix fragment loads:
//   C[M,N] = alpha * A[M,K] * B[N,K]^T (+bias)
// MODE 0: plain epilogue (writes C).
// MODE 1: epilogue writes fp16 exp(alpha*acc) to EH; fp16-rounded row sums
//         atomicAdd'ed into rowsum. C unused.
// BATCH3=1: blockIdx.z selects (A,A1,A2)/(B,B1,B2), C += z*sC1.
// ---------------------------------------------------------------------------
template <int NTILE, int BATCH3, int MODE>
__global__ __launch_bounds__(256, 2) void mma_gemm(
    const float* __restrict__ A, const float* __restrict__ A1q, const float* __restrict__ A2q,
    int lda, int zdiv, long long sA1, long long sA2,
    const float* __restrict__ Bm, const float* __restrict__ B1q, const float* __restrict__ B2q,
    int ldb, long long sB1, long long sB2,
    float* __restrict__ C, int ldc, long long sC1, long long sC2,
    int K, float alpha, const float* __restrict__ bias,
    float* rowsum, __half* EH)
{
    constexpr int WROW  = 20;
    constexpr int ROWS  = 128 + NTILE;
    constexpr int NLOOP = ROWS / 32;
    constexpr int RAWW  = ROWS * 32;
    constexpr int WM    = (NTILE == 128) ? 2 : 4;
    constexpr int MI    = 128 / (WM * 16);
    constexpr int NI    = 4;
    constexpr int AHL   = 128 * WROW;
    constexpr int BOFF  = 2 * AHL;
    constexpr int BHL   = NTILE * WROW;

    extern __shared__ char smem[];
    float*    raw0p = (float*)smem;
    float*    raw1p = (float*)(smem + RAWW * 4);
    uint32_t* bw    = (uint32_t*)(smem + 2 * RAWW * 4);
    const uint32_t raw0a = smem_u32(raw0p);
    const uint32_t raw1a = raw0a + RAWW * 4;
    const uint32_t bwa   = raw0a + 2 * RAWW * 4;

    const int z = blockIdx.z;
    if (BATCH3) {
        A  = (z == 0) ? A  : (z == 1 ? A1q : A2q);
        Bm = (z == 0) ? Bm : (z == 1 ? B1q : B2q);
        C += (long long)z * sC1;
    } else {
        const int z1 = z / zdiv, z2 = z % zdiv;
        A  += (long long)z1 * sA1 + (long long)z2 * sA2;
        Bm += (long long)z1 * sB1 + (long long)z2 * sB2;
        if (MODE == 0) C += (long long)z1 * sC1 + (long long)z2 * sC2;
    }
    float*  rowsumz = (MODE == 1) ? rowsum + (long long)z * TT : nullptr;
    __half* EHz     = (MODE == 1) ? EH + (long long)z * TT * TT : nullptr;

    const int m0 = blockIdx.y * 128;
    const int n0 = blockIdx.x * NTILE;

    const int tid  = threadIdx.x;
    const int warp = tid >> 5;
    const int lane = tid & 31;
    const int wm   = warp % WM;
    const int wn   = warp / WM;
    const int g    = lane >> 2;
    const int tg   = lane & 3;

    uint32_t a_addr[2][MI], b_addr[2][2];
    {
        const int lm  = lane & 7;
        const int l8  = (lane >> 3) & 1;
        const int l16 = lane >> 4;
        const int bm  = lane >> 3;
#pragma unroll
        for (int kk2 = 0; kk2 < 2; kk2++) {
#pragma unroll
            for (int mi = 0; mi < MI; mi++) {
                const int row = wm * (MI * 16) + mi * 16 + lm + l8 * 8;
                const int off = kk2 * 8 + l16 * 4;
                a_addr[kk2][mi] = bwa + (uint32_t)(row * WROW + off) * 4;
            }
#pragma unroll
            for (int np = 0; np < 2; np++) {
                const int nrow = wn * 32 + np * 16 + (bm >> 1) * 8 + lm;
                const int koff = kk2 * 8 + (bm & 1) * 4;
                b_addr[kk2][np] = bwa + (uint32_t)(BOFF + nrow * WROW + koff) * 4;
            }
        }
    }

    float acc[MI][NI][4];
#pragma unroll
    for (int mi = 0; mi < MI; mi++)
#pragma unroll
        for (int ni = 0; ni < NI; ni++)
#pragma unroll
            for (int r = 0; r < 4; r++) acc[mi][ni][r] = 0.f;

#pragma unroll
    for (int i = 0; i < NLOOP; i++) {
        const int idx = tid + i * 256;
        const bool isA = idx < 1024;
        const int r = isA ? (idx >> 3) : ((idx - 1024) >> 3);
        const int c = (idx & 7) * 4;
        const float* src = isA ? &A[(long long)(m0 + r) * lda + c]
                               : &Bm[(long long)(n0 + r) * ldb + c];
        CP_ASYNC16(raw0a + idx * 16, src);
    }
    CP_COMMIT();

    const int NIT = K / 32;

    for (int it = 0; it < NIT; it++) {
        const bool more = (it + 1) < NIT;
        const int kbn = (it + 1) * 32;
        if (more) {
            const uint32_t rdst = ((it + 1) & 1) ? raw1a : raw0a;
#pragma unroll
            for (int i = 0; i < NLOOP; i++) {
                const int idx = tid + i * 256;
                const bool isA = idx < 1024;
                const int r = isA ? (idx >> 3) : ((idx - 1024) >> 3);
                const int c = (idx & 7) * 4;
                const float* src = isA ? &A[(long long)(m0 + r) * lda + kbn + c]
                                       : &Bm[(long long)(n0 + r) * ldb + kbn + c];
                CP_ASYNC16(rdst + idx * 16, src);
            }
            CP_COMMIT();
            CP_WAIT1();
        } else {
            CP_WAIT0();
        }

        {
            const float* rbuf = (it & 1) ? raw1p : raw0p;
#pragma unroll
            for (int i = 0; i < NLOOP; i++) {
                const int idx = tid + i * 256;
                const bool isA = idx < 1024;
                const int r = isA ? (idx >> 3) : ((idx - 1024) >> 3);
                const int c = (idx & 7) * 4;
                float4 x = *(const float4*)(rbuf + idx * 4);
                const uint32_t w = r * WROW + (c >> 1);
                uint32_t* dh = bw + (isA ? 0 : BOFF) + w;
                uint32_t* dl = dh + (isA ? AHL : BHL);
                split_store(x, dh, dl);
            }
        }
        __syncthreads();

        {
#pragma unroll
            for (int kk2 = 0; kk2 < 2; kk2++) {
                uint32_t bh[NI][2], bl[NI][2];
#pragma unroll
                for (int np = 0; np < 2; np++) {
                    ldsm_x4(bh[np * 2][0], bh[np * 2][1], bh[np * 2 + 1][0], bh[np * 2 + 1][1],
                            b_addr[kk2][np]);
                    ldsm_x4(bl[np * 2][0], bl[np * 2][1], bl[np * 2 + 1][0], bl[np * 2 + 1][1],
                            b_addr[kk2][np] + BHL * 4);
                }
#pragma unroll
                for (int mi = 0; mi < MI; mi++) {
                    uint32_t ah[4], al[4];
                    ldsm_x4(ah[0], ah[1], ah[2], ah[3], a_addr[kk2][mi]);
                    ldsm_x4(al[0], al[1], al[2], al[3], a_addr[kk2][mi] + AHL * 4);
#pragma unroll
                    for (int ni = 0; ni < NI; ni++) {
                        mma16816(acc[mi][ni], ah, bh[ni]);
                        mma16816(acc[mi][ni], ah, bl[ni]);
                        mma16816(acc[mi][ni], al, bh[ni]);
                    }
                }
            }
        }
        if (more) __syncthreads();
    }

    // ---- epilogue ----
#pragma unroll
    for (int mi = 0; mi < MI; mi++) {
        const int r0 = m0 + wm * (MI * 16) + mi * 16 + g;
        const int r1 = r0 + 8;
        float p0 = 0.f, p1 = 0.f;
#pragma unroll
        for (int ni = 0; ni < NI; ni++) {
            const int c = n0 + wn * 32 + ni * 8 + tg * 2;
            if (MODE == 1) {
                __half q0 = __float2half_rn(__expf(acc[mi][ni][0] * alpha));
                __half q1 = __float2half_rn(__expf(acc[mi][ni][1] * alpha));
                __half q2 = __float2half_rn(__expf(acc[mi][ni][2] * alpha));
                __half q3 = __float2half_rn(__expf(acc[mi][ni][3] * alpha));
                *(__half2*)&EHz[(long long)r0 * TT + c] = __halves2half2(q0, q1);
                *(__half2*)&EHz[(long long)r1 * TT + c] = __halves2half2(q2, q3);
                p0 += __half2float(q0) + __half2float(q1);
                p1 += __half2float(q2) + __half2float(q3);
            } else {
                float2 bv = make_float2(0.f, 0.f);
                if (bias) bv = *(const float2*)&bias[c];
                float2 o0, o1;
                o0.x = acc[mi][ni][0] * alpha + bv.x;
                o0.y = acc[mi][ni][1] * alpha + bv.y;
                o1.x = acc[mi][ni][2] * alpha + bv.x;
                o1.y = acc[mi][ni][3] * alpha + bv.y;
                *(float2*)&C[(long long)r0 * ldc + c] = o0;
                *(float2*)&C[(long long)r1 * ldc + c] = o1;
            }
        }
        if (MODE == 1) {
            p0 += __shfl_xor_sync(0xffffffffu, p0, 1);
            p0 += __shfl_xor_sync(0xffffffffu, p0, 2);
            p1 += __shfl_xor_sync(0xffffffffu, p1, 1);
            p1 += __shfl_xor_sync(0xffffffffu, p1, 2);
            if (tg == 0) {
                atomicAdd(&rowsumz[r0], p0);
                atomicAdd(&rowsumz[r1], p1);
            }
        }
    }
}

// ---------------------------------------------------------------------------
// AV kernel: mh[b,m,h,:] = softmax(attn)[m,:] @ V^T, attn from fp16 exp.
// A = exph (fp16, 128 rows x K=2048), B = Vt (fp32, 64 rows).
// Normalizes A rows by invr during staging and writes fp32 normalized attn.
// CTA 128x64, k-slab 32, 256 threads (4m x 2n warps), 2 CTAs/SM.
// ---------------------------------------------------------------------------
__global__ __launch_bounds__(256, 2) void mma_av(
    const __half* __restrict__ exph, const float* __restrict__ Vt,
    const float* __restrict__ invr,
    float* __restrict__ attn, float* __restrict__ mh)
{
    constexpr int WROW = 20;
    constexpr int AHL  = 128 * WROW;   // 2560 words
    constexpr int BOFF = 2 * AHL;      // 5120
    constexpr int BHL  = 64 * WROW;    // 1280
    constexpr int RAWB = 16384;        // bytes per raw slab (A 8KB + B 8KB)
    constexpr int MI = 2, NI = 4;

    extern __shared__ char smem[];
    char* raw0 = smem;
    char* raw1 = smem + RAWB;
    uint32_t* bw = (uint32_t*)(smem + 2 * RAWB);
    const uint32_t raw0a = smem_u32(smem);
    const uint32_t raw1a = raw0a + RAWB;
    const uint32_t bwa   = raw0a + 2 * RAWB;

    const int z = blockIdx.y;
    const int b = z / HH, h = z % HH;
    const int m0 = blockIdx.x * 128;

    const __half* EHz = exph + (long long)z * TT * TT;
    const float*  Vz  = Vt + (long long)z * DD * TT;
    float* AWz = attn + (long long)z * TT * TT;
    float* mhz = mh + (long long)b * TT * EE + h * DD;
    const float* invz = invr + (long long)z * TT;

    const int tid  = threadIdx.x;
    const int warp = tid >> 5;
    const int lane = tid & 31;
    const int wm   = warp & 3;
    const int wn   = warp >> 2;
    const int g    = lane >> 2;
    const int tg   = lane & 3;

    // this thread's two A rows (staging): tid>>2 and +64
    const float inv0s = invz[m0 + (tid >> 2)];
    const float inv1s = invz[m0 + (tid >> 2) + 64];

    uint32_t a_addr[2][MI], b_addr[2][2];
    {
        const int lm  = lane & 7;
        const int l8  = (lane >> 3) & 1;
        const int l16 = lane >> 4;
        const int bm  = lane >> 3;
#pragma unroll
        for (int kk2 = 0; kk2 < 2; kk2++) {
#pragma unroll
            for (int mi = 0; mi < MI; mi++) {
                const int row = wm * 32 + mi * 16 + lm + l8 * 8;
                const int off = kk2 * 8 + l16 * 4;
                a_addr[kk2][mi] = bwa + (uint32_t)(row * WROW + off) * 4;
            }
#pragma unroll
            for (int np = 0; np < 2; np++) {
                const int nrow = wn * 32 + np * 16 + (bm >> 1) * 8 + lm;
                const int koff = kk2 * 8 + (bm & 1) * 4;
                b_addr[kk2][np] = bwa + (uint32_t)(BOFF + nrow * WROW + koff) * 4;
            }
        }
    }

    float acc[MI][NI][4];
#pragma unroll
    for (int mi = 0; mi < MI; mi++)
#pragma unroll
        for (int ni = 0; ni < NI; ni++)
#pragma unroll
            for (int r = 0; r < 4; r++) acc[mi][ni][r] = 0.f;

    // group map: idx 0..511 A (row=idx>>2, c8=(idx&3)*8 halves);
    //            idx 512..1023 B (j=idx-512, row=j>>3, c4=(j&7)*4 floats)
    // ---- prologue: slab 0 ----
#pragma unroll
    for (int i = 0; i < 4; i++) {
        const int idx = tid + i * 256;
        if (idx < 512) {
            const int r = idx >> 2, c8 = (idx & 3) * 8;
            CP_ASYNC16(raw0a + idx * 16, EHz + (long long)(m0 + r) * TT + c8);
        } else {
            const int j = idx - 512;
            const int r = j >> 3, c4 = (j & 7) * 4;
            CP_ASYNC16(raw0a + 8192 + j * 16, Vz + (long long)r * TT + c4);
        }
    }
    CP_COMMIT();

    const int NIT = TT / 32;   // 64

    for (int it = 0; it < NIT; it++) {
        const bool more = (it + 1) < NIT;
        const int kbn = (it + 1) * 32;
        if (more) {
            const uint32_t rdst = ((it + 1) & 1) ? raw1a : raw0a;
#pragma unroll
            for (int i = 0; i < 4; i++) {
                const int idx = tid + i * 256;
                if (idx < 512) {
                    const int r = idx >> 2, c8 = (idx & 3) * 8;
                    CP_ASYNC16(rdst + idx * 16, EHz + (long long)(m0 + r) * TT + kbn + c8);
                } else {
                    const int j = idx - 512;
                    const int r = j >> 3, c4 = (j & 7) * 4;
                    CP_ASYNC16(rdst + 8192 + j * 16, Vz + (long long)r * TT + kbn + c4);
                }
            }
            CP_COMMIT();
            CP_WAIT1();
        } else {
            CP_WAIT0();
        }

        // ---- convert own groups ----
        {
            const char* rbuf = (it & 1) ? raw1 : raw0;
            const int kb = it * 32;
#pragma unroll
            for (int i = 0; i < 4; i++) {
                const int idx = tid + i * 256;
                if (idx < 512) {
                    const int r = idx >> 2, c8 = (idx & 3) * 8;
                    uint4 hv = *(const uint4*)(rbuf + idx * 16);
                    const __half2* h2 = (const __half2*)&hv;
                    const float inv = (i == 0) ? inv0s : inv1s;
                    float2 f0 = __half22float2(h2[0]);
                    float2 f1 = __half22float2(h2[1]);
                    float2 f2 = __half22float2(h2[2]);
                    float2 f3 = __half22float2(h2[3]);
                    f0.x *= inv; f0.y *= inv; f1.x *= inv; f1.y *= inv;
                    f2.x *= inv; f2.y *= inv; f3.x *= inv; f3.y *= inv;
                    float* dst = &AWz[(long long)(m0 + r) * TT + kb + c8];
                    *(float4*)dst       = make_float4(f0.x, f0.y, f1.x, f1.y);
                    *(float4*)(dst + 4) = make_float4(f2.x, f2.y, f3.x, f3.y);
                    uint32_t w0 = packbf(f0.x, f0.y), w1 = packbf(f1.x, f1.y);
                    uint32_t w2 = packbf(f2.x, f2.y), w3 = packbf(f3.x, f3.y);
                    __nv_bfloat162 t;
                    t = *(__nv_bfloat162*)&w0;
                    uint32_t l0 = packbf(f0.x - __bfloat162float(t.x), f0.y - __bfloat162float(t.y));
                    t = *(__nv_bfloat162*)&w1;
                    uint32_t l1 = packbf(f1.x - __bfloat162float(t.x), f1.y - __bfloat162float(t.y));
                    t = *(__nv_bfloat162*)&w2;
                    uint32_t l2 = packbf(f2.x - __bfloat162float(t.x), f2.y - __bfloat162float(t.y));
                    t = *(__nv_bfloat162*)&w3;
                    uint32_t l3 = packbf(f3.x - __bfloat162float(t.x), f3.y - __bfloat162float(t.y));
                    uint32_t* dh = bw + r * WROW + (idx & 3) * 4;
                    *(uint2*)dh       = make_uint2(w0, w1);
                    *(uint2*)(dh + 2) = make_uint2(w2, w3);
                    uint32_t* dl = dh + AHL;
                    *(uint2*)dl       = make_uint2(l0, l1);
                    *(uint2*)(dl + 2) = make_uint2(l2, l3);
                } else {
                    const int j = idx - 512;
                    const int r = j >> 3, c4 = (j & 7) * 4;
                    float4 x = *(const float4*)(rbuf + 8192 + j * 16);
                    uint32_t* dh = bw + BOFF + r * WROW + (c4 >> 1);
                    split_store(x, dh, dh + BHL);
                }
            }
        }
        __syncthreads();

        // ---- MMA ----
        {
#pragma unroll
            for (int kk2 = 0; kk2 < 2; kk2++) {
                uint32_t bh[NI][2], bl[NI][2];
#pragma unroll
                for (int np = 0; np < 2; np++) {
                    ldsm_x4(bh[np * 2][0], bh[np * 2][1], bh[np * 2 + 1][0], bh[np * 2 + 1][1],
                            b_addr[kk2][np]);
                    ldsm_x4(bl[np * 2][0], bl[np * 2][1], bl[np * 2 + 1][0], bl[np * 2 + 1][1],
                            b_addr[kk2][np] + BHL * 4);
                }
#pragma unroll
                for (int mi = 0; mi < MI; mi++) {
                    uint32_t ah[4], al[4];
                    ldsm_x4(ah[0], ah[1], ah[2], ah[3], a_addr[kk2][mi]);
                    ldsm_x4(al[0], al[1], al[2], al[3], a_addr[kk2][mi] + AHL * 4);
#pragma unroll
                    for (int ni = 0; ni < NI; ni++) {
                        mma16816(acc[mi][ni], ah, bh[ni]);
                        mma16816(acc[mi][ni], ah, bl[ni]);
                        mma16816(acc[mi][ni], al, bh[ni]);
                    }
                }
            }
        }
        if (more) __syncthreads();
    }

    // ---- epilogue: write mh ----
#pragma unroll
    for (int mi = 0; mi < MI; mi++) {
        const int r0 = m0 + wm * 32 + mi * 16 + g;
        const int r1 = r0 + 8;
#pragma unroll
        for (int ni = 0; ni < NI; ni++) {
            const int c = wn * 32 + ni * 8 + tg * 2;
            *(float2*)&mhz[(long long)r0 * EE + c] = make_float2(acc[mi][ni][0], acc[mi][ni][1]);
            *(float2*)&mhz[(long long)r1 * EE + c] = make_float2(acc[mi][ni][2], acc[mi][ni][3]);
        }
    }
}

// ---------------------------------------------------------------------------
// rowsum helpers
// ---------------------------------------------------------------------------
__global__ void zero_rowsum(float* rs) {
    rs[blockIdx.x * 256 + threadIdx.x] = 0.f;
}
__global__ void invert_rowsum(float* rs) {
    const int i = blockIdx.x * 256 + threadIdx.x;
    rs[i] = 1.f / rs[i];
}

// ---------------------------------------------------------------------------
// Transposes
// ---------------------------------------------------------------------------
__global__ __launch_bounds__(256) void transpose_v(const float* __restrict__ v,
                                                   float* __restrict__ vt)
{
    __shared__ float tile[32][33];
    const int z = blockIdx.z;
    const int b = z / HH, h = z % HH;
    const int m0 = blockIdx.x * 32;
    const int d0 = blockIdx.y * 32;
    const int tx = threadIdx.x & 31;
    const int ty0 = threadIdx.x >> 5;
#pragma unroll
    for (int ty = ty0; ty < 32; ty += 8)
        tile[ty][tx] = v[((long long)b * TT + m0 + ty) * EE + h * DD + d0 + tx];
    __syncthreads();
#pragma unroll
    for (int ty = ty0; ty < 32; ty += 8)
        vt[(((long long)z) * DD + d0 + ty) * TT + m0 + tx] = tile[tx][ty];
}

__global__ __launch_bounds__(256) void transpose_pk(const float* __restrict__ pk,
                                                    float* __restrict__ pkt)
{
    __shared__ float tile[32][33];
    const int k0 = blockIdx.x * 32;
    const int o0 = blockIdx.y * 32;
    const int tx = threadIdx.x & 31;
    const int ty0 = threadIdx.x >> 5;
#pragma unroll
    for (int ty = ty0; ty < 32; ty += 8)
        tile[ty][tx] = pk[(long long)(k0 + ty) * OO + o0 + tx];
    __syncthreads();
#pragma unroll
    for (int ty = ty0; ty < 32; ty += 8)
        pkt[(long long)(o0 + ty) * EE + k0 + tx] = tile[tx][ty];
}

// ---------------------------------------------------------------------------
// Launch
// ---------------------------------------------------------------------------
extern "C" void kernel_launch(void* const* d_in, const int* in_sizes, int n_in,
                              void* d_out, int out_size)
{
    const float* query = (const float*)d_in[0];
    const float* key   = (const float*)d_in[1];
    const float* value = (const float*)d_in[2];
    const float* Wq    = (const float*)d_in[3];
    const float* Wk    = (const float*)d_in[4];
    const float* Wv    = (const float*)d_in[5];
    const float* pk    = (const float*)d_in[6];
    const float* pb    = (const float*)d_in[7];

    float *qkvp, *mhp, *vtp, *pktp, *rsp, *outs, *attns;
    __half* ehp;
    cudaGetSymbolAddress((void**)&qkvp,  g_qkv);
    cudaGetSymbolAddress((void**)&mhp,   g_mh);
    cudaGetSymbolAddress((void**)&vtp,   g_vt);
    cudaGetSymbolAddress((void**)&pktp,  g_pkt);
    cudaGetSymbolAddress((void**)&rsp,   g_rowsum);
    cudaGetSymbolAddress((void**)&ehp,   g_exph);
    cudaGetSymbolAddress((void**)&outs,  g_out_scratch);
    cudaGetSymbolAddress((void**)&attns, g_attn_scratch);

    const long long qkvN = (long long)BB * TT * EE;
    float* qp = qkvp;
    float* kp = qkvp + qkvN;
    float* vp = qkvp + 2 * qkvN;

    const long long outN  = (long long)BB * TT * OO;
    const long long attnN = (long long)BB * HH * TT * TT;

    float* outP  = (float*)d_out;
    float* attnP;
    if ((long long)out_size >= outN + attnN) {
        attnP = outP + outN;
    } else if ((long long)out_size == attnN) {
        attnP = (float*)d_out;
        outP  = outs;
    } else {
        attnP = attns;
    }

    constexpr int SMEM128 = (2 * 256 * 32 + 256 * 40) * 4;  // 106496
    constexpr int SMEMAV  = 2 * 16384 + 7680 * 4;           // 63488
    cudaFuncSetAttribute(mma_gemm<128, 1, 0>, cudaFuncAttributeMaxDynamicSharedMemorySize, SMEM128);
    cudaFuncSetAttribute(mma_gemm<128, 0, 0>, cudaFuncAttributeMaxDynamicSharedMemorySize, SMEM128);
    cudaFuncSetAttribute(mma_gemm<128, 0, 1>, cudaFuncAttributeMaxDynamicSharedMemorySize, SMEM128);
    cudaFuncSetAttribute(mma_av, cudaFuncAttributeMaxDynamicSharedMemorySize, SMEMAV);

    // 0) zero row sums (graph-replay safe)
    zero_rowsum<<<(BB * HH * TT) / 256, 256>>>(rsp);

    // 1) Q/K/V projections, batched over z = 0,1,2
    {
        dim3 grid(EE / 128, (BB * TT) / 128, 3);
        mma_gemm<128, 1, 0><<<grid, 256, SMEM128>>>(
            query, key, value, EE, 1, 0, 0,
            Wq, Wk, Wv, EE, 0, 0,
            qkvp, EE, qkvN, 0,
            EE, 1.f, nullptr, nullptr, nullptr);
    }

    // transposes: V -> [b][h][d][m], pk -> [o][k]
    {
        dim3 gv(TT / 32, DD / 32, BB * HH);
        transpose_v<<<gv, 256>>>(vp, vtp);
        dim3 gp(EE / 32, OO / 32, 1);
        transpose_pk<<<gp, 256>>>(pk, pktp);
    }

    // 2) exph = fp16(exp(0.125 * q @ k^T)); fp16-rounded row sums via atomics
    {
        dim3 grid(TT / 128, TT / 128, BB * HH);
        mma_gemm<128, 0, 1><<<grid, 256, SMEM128>>>(
            qp, nullptr, nullptr, EE, HH, (long long)TT * EE, DD,
            kp, nullptr, nullptr, EE,     (long long)TT * EE, DD,
            nullptr, TT, 0, 0,
            DD, 0.125f, nullptr, rsp, ehp);
    }

    // 3) invert row sums
    invert_rowsum<<<(BB * HH * TT) / 256, 256>>>(rsp);

    // 4) mh = softmax(attn) @ vT^T ; writes normalized fp32 attn once
    {
        dim3 grid(TT / 128, BB * HH);
        mma_av<<<grid, 256, SMEMAV>>>(ehp, vtp, rsp, attnP, mhp);
    }

    // 5) out = mh @ pkT^T + bias
    {
        dim3 grid(OO / 128, (BB * TT) / 128, 1);
        mma_gemm<128, 0, 0><<<grid, 256, SMEM128>>>(
            mhp, nullptr, nullptr, EE, 1, 0, 0,
            pktp, nullptr, nullptr, EE, 0, 0,
            outP, OO, 0, 0, EE, 1.f, pb, nullptr, nullptr);
    }
}

// round 13
// speedup vs baseline: 1.1731x; 1.0362x over previous
#include <cuda_runtime.h>
#include <cuda_bf16.h>
#include <cuda_fp16.h>
#include <cstdint>

// Problem dims
#define BB 2
#define TT 2048
#define HH 16
#define DD 64
#define EE 1024   // HH*DD
#define OO 1024

// Scratch (device globals)
__device__ float g_qkv[(size_t)3 * BB * TT * EE];     // q | k | v contiguous
__device__ float g_mh[(size_t)BB * TT * EE];
__device__ float g_vt[(size_t)BB * TT * EE];          // V transposed: [b][h][d][m]
__device__ float g_pkt[(size_t)EE * OO];              // proj kernel transposed: [o][k]
__device__ float g_rowsum[(size_t)BB * HH * TT];      // exp row sums -> inverses
__device__ __half g_exph[(size_t)BB * HH * TT * TT];  // fp16 exp(logits) intermediate
__device__ float g_out_scratch[(size_t)BB * TT * OO];
__device__ float g_attn_scratch[(size_t)BB * HH * TT * TT];

// ---------------------------------------------------------------------------
// PTX helpers (baseline features only: sm_80-era, legal at compute_103)
// ---------------------------------------------------------------------------
__device__ __forceinline__ uint32_t smem_u32(const void* p) {
    uint32_t a;
    asm("{ .reg .u64 t; cvta.to.shared.u64 t, %1; cvt.u32.u64 %0, t; }" : "=r"(a) : "l"(p));
    return a;
}
#define CP_ASYNC16(dst_u32, src_ptr) \
    asm volatile("cp.async.cg.shared.global [%0], [%1], 16;" :: "r"(dst_u32), "l"(src_ptr))
#define CP_COMMIT() asm volatile("cp.async.commit_group;" ::: "memory")
#define CP_WAIT1()  asm volatile("cp.async.wait_group 1;" ::: "memory")
#define CP_WAIT0()  asm volatile("cp.async.wait_group 0;" ::: "memory")

__device__ __forceinline__ void mma16816(float* c, const uint32_t* a, const uint32_t* b) {
    asm volatile(
        "mma.sync.aligned.m16n8k16.row.col.f32.bf16.bf16.f32 "
        "{%0,%1,%2,%3}, {%4,%5,%6,%7}, {%8,%9}, {%0,%1,%2,%3};"
        : "+f"(c[0]), "+f"(c[1]), "+f"(c[2]), "+f"(c[3])
        : "r"(a[0]), "r"(a[1]), "r"(a[2]), "r"(a[3]), "r"(b[0]), "r"(b[1]));
}

__device__ __forceinline__ void mma16816h(float* c, const uint32_t* a, const uint32_t* b) {
    asm volatile(
        "mma.sync.aligned.m16n8k16.row.col.f32.f16.f16.f32 "
        "{%0,%1,%2,%3}, {%4,%5,%6,%7}, {%8,%9}, {%0,%1,%2,%3};"
        : "+f"(c[0]), "+f"(c[1]), "+f"(c[2]), "+f"(c[3])
        : "r"(a[0]), "r"(a[1]), "r"(a[2]), "r"(a[3]), "r"(b[0]), "r"(b[1]));
}

__device__ __forceinline__ void ldsm_x4(uint32_t& r0, uint32_t& r1, uint32_t& r2, uint32_t& r3,
                                        uint32_t addr) {
    asm volatile("ldmatrix.sync.aligned.m8n8.x4.shared.b16 {%0,%1,%2,%3}, [%4];"
                 : "=r"(r0), "=r"(r1), "=r"(r2), "=r"(r3) : "r"(addr));
}

__device__ __forceinline__ void split_store(float4 x, uint32_t* dh, uint32_t* dl) {
    __nv_bfloat162 h0 = __floats2bfloat162_rn(x.x, x.y);
    __nv_bfloat162 h1 = __floats2bfloat162_rn(x.z, x.w);
    float l0 = x.x - __bfloat162float(h0.x);
    float l1 = x.y - __bfloat162float(h0.y);
    float l2 = x.z - __bfloat162float(h1.x);
    float l3 = x.w - __bfloat162float(h1.y);
    __nv_bfloat162 lo0 = __floats2bfloat162_rn(l0, l1);
    __nv_bfloat162 lo1 = __floats2bfloat162_rn(l2, l3);
    *(uint2*)dh = make_uint2(*(uint32_t*)&h0, *(uint32_t*)&h1);
    *(uint2*)dl = make_uint2(*(uint32_t*)&lo0, *(uint32_t*)&lo1);
}

// fp16 hi/lo split (for V in the AV GEMM)
__device__ __forceinline__ void split_store_f16(float4 x, uint32_t* dh, uint32_t* dl) {
    __half2 h0 = __floats2half2_rn(x.x, x.y);
    __half2 h1 = __floats2half2_rn(x.z, x.w);
    float2 f0 = __half22float2(h0);
    float2 f1 = __half22float2(h1);
    __half2 l0 = __floats2half2_rn(x.x - f0.x, x.y - f0.y);
    __half2 l1 = __floats2half2_rn(x.z - f1.x, x.w - f1.y);
    *(uint2*)dh = make_uint2(*(uint32_t*)&h0, *(uint32_t*)&h1);
    *(uint2*)dl = make_uint2(*(uint32_t*)&l0, *(uint32_t*)&l1);
}

// ---------------------------------------------------------------------------
// cp.async double-buffered tensor-core GEMM with ldmatrix fragment loads:
//   C[M,N] = alpha * A[M,K] * B[N,K]^T (+bias)
// MODE 0: plain epilogue (writes C).
// MODE 1: epilogue writes fp16 exp(alpha*acc) to EH; fp16-rounded row sums
//         atomicAdd'ed into rowsum. C unused.
// BATCH3=1: blockIdx.z selects (A,A1,A2)/(B,B1,B2), C += z*sC1.
// ---------------------------------------------------------------------------
template <int NTILE, int BATCH3, int MODE>
__global__ __launch_bounds__(256, 2) void mma_gemm(
    const float* __restrict__ A, const float* __restrict__ A1q, const float* __restrict__ A2q,
    int lda, int zdiv, long long sA1, long long sA2,
    const float* __restrict__ Bm, const float* __restrict__ B1q, const float* __restrict__ B2q,
    int ldb, long long sB1, long long sB2,
    float* __restrict__ C, int ldc, long long sC1, long long sC2,
    int K, float alpha, const float* __restrict__ bias,
    float* rowsum, __half* EH)
{
    constexpr int WROW  = 20;
    constexpr int ROWS  = 128 + NTILE;
    constexpr int NLOOP = ROWS / 32;
    constexpr int RAWW  = ROWS * 32;
    constexpr int WM    = (NTILE == 128) ? 2 : 4;
    constexpr int MI    = 128 / (WM * 16);
    constexpr int NI    = 4;
    constexpr int AHL   = 128 * WROW;
    constexpr int BOFF  = 2 * AHL;
    constexpr int BHL   = NTILE * WROW;

    extern __shared__ char smem[];
    float*    raw0p = (float*)smem;
    float*    raw1p = (float*)(smem + RAWW * 4);
    uint32_t* bw    = (uint32_t*)(smem + 2 * RAWW * 4);
    const uint32_t raw0a = smem_u32(raw0p);
    const uint32_t raw1a = raw0a + RAWW * 4;
    const uint32_t bwa   = raw0a + 2 * RAWW * 4;

    const int z = blockIdx.z;
    if (BATCH3) {
        A  = (z == 0) ? A  : (z == 1 ? A1q : A2q);
        Bm = (z == 0) ? Bm : (z == 1 ? B1q : B2q);
        C += (long long)z * sC1;
    } else {
        const int z1 = z / zdiv, z2 = z % zdiv;
        A  += (long long)z1 * sA1 + (long long)z2 * sA2;
        Bm += (long long)z1 * sB1 + (long long)z2 * sB2;
        if (MODE == 0) C += (long long)z1 * sC1 + (long long)z2 * sC2;
    }
    float*  rowsumz = (MODE == 1) ? rowsum + (long long)z * TT : nullptr;
    __half* EHz     = (MODE == 1) ? EH + (long long)z * TT * TT : nullptr;

    const int m0 = blockIdx.y * 128;
    const int n0 = blockIdx.x * NTILE;

    const int tid  = threadIdx.x;
    const int warp = tid >> 5;
    const int lane = tid & 31;
    const int wm   = warp % WM;
    const int wn   = warp / WM;
    const int g    = lane >> 2;
    const int tg   = lane & 3;

    uint32_t a_addr[2][MI], b_addr[2][2];
    {
        const int lm  = lane & 7;
        const int l8  = (lane >> 3) & 1;
        const int l16 = lane >> 4;
        const int bm  = lane >> 3;
#pragma unroll
        for (int kk2 = 0; kk2 < 2; kk2++) {
#pragma unroll
            for (int mi = 0; mi < MI; mi++) {
                const int row = wm * (MI * 16) + mi * 16 + lm + l8 * 8;
                const int off = kk2 * 8 + l16 * 4;
                a_addr[kk2][mi] = bwa + (uint32_t)(row * WROW + off) * 4;
            }
#pragma unroll
            for (int np = 0; np < 2; np++) {
                const int nrow = wn * 32 + np * 16 + (bm >> 1) * 8 + lm;
                const int koff = kk2 * 8 + (bm & 1) * 4;
                b_addr[kk2][np] = bwa + (uint32_t)(BOFF + nrow * WROW + koff) * 4;
            }
        }
    }

    float acc[MI][NI][4];
#pragma unroll
    for (int mi = 0; mi < MI; mi++)
#pragma unroll
        for (int ni = 0; ni < NI; ni++)
#pragma unroll
            for (int r = 0; r < 4; r++) acc[mi][ni][r] = 0.f;

#pragma unroll
    for (int i = 0; i < NLOOP; i++) {
        const int idx = tid + i * 256;
        const bool isA = idx < 1024;
        const int r = isA ? (idx >> 3) : ((idx - 1024) >> 3);
        const int c = (idx & 7) * 4;
        const float* src = isA ? &A[(long long)(m0 + r) * lda + c]
                               : &Bm[(long long)(n0 + r) * ldb + c];
        CP_ASYNC16(raw0a + idx * 16, src);
    }
    CP_COMMIT();

    const int NIT = K / 32;

    for (int it = 0; it < NIT; it++) {
        const bool more = (it + 1) < NIT;
        const int kbn = (it + 1) * 32;
        if (more) {
            const uint32_t rdst = ((it + 1) & 1) ? raw1a : raw0a;
#pragma unroll
            for (int i = 0; i < NLOOP; i++) {
                const int idx = tid + i * 256;
                const bool isA = idx < 1024;
                const int r = isA ? (idx >> 3) : ((idx - 1024) >> 3);
                const int c = (idx & 7) * 4;
                const float* src = isA ? &A[(long long)(m0 + r) * lda + kbn + c]
                                       : &Bm[(long long)(n0 + r) * ldb + kbn + c];
                CP_ASYNC16(rdst + idx * 16, src);
            }
            CP_COMMIT();
            CP_WAIT1();
        } else {
            CP_WAIT0();
        }

        {
            const float* rbuf = (it & 1) ? raw1p : raw0p;
#pragma unroll
            for (int i = 0; i < NLOOP; i++) {
                const int idx = tid + i * 256;
                const bool isA = idx < 1024;
                const int r = isA ? (idx >> 3) : ((idx - 1024) >> 3);
                const int c = (idx & 7) * 4;
                float4 x = *(const float4*)(rbuf + idx * 4);
                const uint32_t w = r * WROW + (c >> 1);
                uint32_t* dh = bw + (isA ? 0 : BOFF) + w;
                uint32_t* dl = dh + (isA ? AHL : BHL);
                split_store(x, dh, dl);
            }
        }
        __syncthreads();

        {
#pragma unroll
            for (int kk2 = 0; kk2 < 2; kk2++) {
                uint32_t bh[NI][2], bl[NI][2];
#pragma unroll
                for (int np = 0; np < 2; np++) {
                    ldsm_x4(bh[np * 2][0], bh[np * 2][1], bh[np * 2 + 1][0], bh[np * 2 + 1][1],
                            b_addr[kk2][np]);
                    ldsm_x4(bl[np * 2][0], bl[np * 2][1], bl[np * 2 + 1][0], bl[np * 2 + 1][1],
                            b_addr[kk2][np] + BHL * 4);
                }
#pragma unroll
                for (int mi = 0; mi < MI; mi++) {
                    uint32_t ah[4], al[4];
                    ldsm_x4(ah[0], ah[1], ah[2], ah[3], a_addr[kk2][mi]);
                    ldsm_x4(al[0], al[1], al[2], al[3], a_addr[kk2][mi] + AHL * 4);
#pragma unroll
                    for (int ni = 0; ni < NI; ni++) {
                        mma16816(acc[mi][ni], ah, bh[ni]);
                        mma16816(acc[mi][ni], ah, bl[ni]);
                        mma16816(acc[mi][ni], al, bh[ni]);
                    }
                }
            }
        }
        if (more) __syncthreads();
    }

    // ---- epilogue ----
#pragma unroll
    for (int mi = 0; mi < MI; mi++) {
        const int r0 = m0 + wm * (MI * 16) + mi * 16 + g;
        const int r1 = r0 + 8;
        float p0 = 0.f, p1 = 0.f;
#pragma unroll
        for (int ni = 0; ni < NI; ni++) {
            const int c = n0 + wn * 32 + ni * 8 + tg * 2;
            if (MODE == 1) {
                __half q0 = __float2half_rn(__expf(acc[mi][ni][0] * alpha));
                __half q1 = __float2half_rn(__expf(acc[mi][ni][1] * alpha));
                __half q2 = __float2half_rn(__expf(acc[mi][ni][2] * alpha));
                __half q3 = __float2half_rn(__expf(acc[mi][ni][3] * alpha));
                *(__half2*)&EHz[(long long)r0 * TT + c] = __halves2half2(q0, q1);
                *(__half2*)&EHz[(long long)r1 * TT + c] = __halves2half2(q2, q3);
                p0 += __half2float(q0) + __half2float(q1);
                p1 += __half2float(q2) + __half2float(q3);
            } else {
                float2 bv = make_float2(0.f, 0.f);
                if (bias) bv = *(const float2*)&bias[c];
                float2 o0, o1;
                o0.x = acc[mi][ni][0] * alpha + bv.x;
                o0.y = acc[mi][ni][1] * alpha + bv.y;
                o1.x = acc[mi][ni][2] * alpha + bv.x;
                o1.y = acc[mi][ni][3] * alpha + bv.y;
                *(float2*)&C[(long long)r0 * ldc + c] = o0;
                *(float2*)&C[(long long)r1 * ldc + c] = o1;
            }
        }
        if (MODE == 1) {
            p0 += __shfl_xor_sync(0xffffffffu, p0, 1);
            p0 += __shfl_xor_sync(0xffffffffu, p0, 2);
            p1 += __shfl_xor_sync(0xffffffffu, p1, 1);
            p1 += __shfl_xor_sync(0xffffffffu, p1, 2);
            if (tg == 0) {
                atomicAdd(&rowsumz[r0], p0);
                atomicAdd(&rowsumz[r1], p1);
            }
        }
    }
}

// ---------------------------------------------------------------------------
// AV kernel v2: mh[b,m,h,:] = inv_row * (exph[m,:] @ V^T)
//   A = exph (fp16) cp.async'ed DIRECTLY into ldmatrix layout (no convert!)
//   B = Vt (fp32) split into fp16 hi/lo
//   f16 MMA: 2 per (mi,ni) instead of 3; normalization folded into epilogue;
//   convert phase writes normalized fp32 attn from the smem A copy.
// CTA 128x64, k-slab 32, 256 threads (4m x 2n warps), 2 CTAs/SM.
// ---------------------------------------------------------------------------
__global__ __launch_bounds__(256, 2) void mma_av(
    const __half* __restrict__ exph, const float* __restrict__ Vt,
    const float* __restrict__ invr,
    float* __restrict__ attn, float* __restrict__ mh)
{
    constexpr int WROW = 20;              // words per smem row (A: 32 halves+pad)
    constexpr int AW0 = 0, AW1 = 2560;    // double-buffered A (fp16, MMA layout)
    constexpr int BR0 = 5120, BR1 = 7168; // raw V slabs (fp32, 8KB each)
    constexpr int BVH = 9216, BVL = 10496;// V fp16 hi/lo (1280 words each)
    constexpr int MI = 2, NI = 4;

    extern __shared__ char smem[];
    uint32_t* sw = (uint32_t*)smem;
    const uint32_t sb = smem_u32(smem);

    const int z = blockIdx.y;
    const int b = z / HH, h = z % HH;
    const int m0 = blockIdx.x * 128;

    const __half* EHz = exph + (long long)z * TT * TT;
    const float*  Vz  = Vt + (long long)z * DD * TT;
    float* AWz = attn + (long long)z * TT * TT;
    float* mhz = mh + (long long)b * TT * EE + h * DD;
    const float* invz = invr + (long long)z * TT;

    const int tid  = threadIdx.x;
    const int warp = tid >> 5;
    const int lane = tid & 31;
    const int wm   = warp & 3;
    const int wn   = warp >> 2;
    const int g    = lane >> 2;
    const int tg   = lane & 3;

    // staging rows for attn writeback (this thread's A groups)
    const float inv0s = invz[m0 + (tid >> 2)];
    const float inv1s = invz[m0 + (tid >> 2) + 64];

    uint32_t a_off[2][MI];     // byte offsets within one A buffer
    uint32_t b_addr[2][2];
    {
        const int lm  = lane & 7;
        const int l8  = (lane >> 3) & 1;
        const int l16 = lane >> 4;
        const int bm  = lane >> 3;
#pragma unroll
        for (int kk2 = 0; kk2 < 2; kk2++) {
#pragma unroll
            for (int mi = 0; mi < MI; mi++) {
                const int row = wm * 32 + mi * 16 + lm + l8 * 8;
                a_off[kk2][mi] = (uint32_t)(row * WROW + kk2 * 8 + l16 * 4) * 4;
            }
#pragma unroll
            for (int np = 0; np < 2; np++) {
                const int nrow = wn * 32 + np * 16 + (bm >> 1) * 8 + lm;
                const int koff = kk2 * 8 + (bm & 1) * 4;
                b_addr[kk2][np] = sb + (uint32_t)(BVH + nrow * WROW + koff) * 4;
            }
        }
    }

    float acc[MI][NI][4];
#pragma unroll
    for (int mi = 0; mi < MI; mi++)
#pragma unroll
        for (int ni = 0; ni < NI; ni++)
#pragma unroll
            for (int r = 0; r < 4; r++) acc[mi][ni][r] = 0.f;

    // group map per slab: idx<512 A (row=idx>>2, chunk=idx&3 of 8 halves);
    //                     idx>=512 B (j=idx-512, row=j>>3, c4=(j&7)*4 floats)
    // ---- prologue: slab 0 ----
#pragma unroll
    for (int i = 0; i < 4; i++) {
        const int idx = tid + i * 256;
        if (idx < 512) {
            const int r = idx >> 2, ch = idx & 3;
            CP_ASYNC16(sb + AW0 * 4 + r * 80 + ch * 16, EHz + (long long)(m0 + r) * TT + ch * 8);
        } else {
            const int j = idx - 512;
            const int r = j >> 3, c4 = (j & 7) * 4;
            CP_ASYNC16(sb + BR0 * 4 + j * 16, Vz + (long long)r * TT + c4);
        }
    }
    CP_COMMIT();

    const int NIT = TT / 32;   // 64

    for (int it = 0; it < NIT; it++) {
        const bool more = (it + 1) < NIT;
        const int kbn = (it + 1) * 32;
        if (more) {
            const uint32_t adst = sb + (((it + 1) & 1) ? AW1 : AW0) * 4;
            const uint32_t bdst = sb + (((it + 1) & 1) ? BR1 : BR0) * 4;
#pragma unroll
            for (int i = 0; i < 4; i++) {
                const int idx = tid + i * 256;
                if (idx < 512) {
                    const int r = idx >> 2, ch = idx & 3;
                    CP_ASYNC16(adst + r * 80 + ch * 16, EHz + (long long)(m0 + r) * TT + kbn + ch * 8);
                } else {
                    const int j = idx - 512;
                    const int r = j >> 3, c4 = (j & 7) * 4;
                    CP_ASYNC16(bdst + j * 16, Vz + (long long)r * TT + kbn + c4);
                }
            }
            CP_COMMIT();
            CP_WAIT1();
        } else {
            CP_WAIT0();
        }

        // ---- convert phase: normalized attn write from A smem; V split ----
        {
            const uint32_t acur = (it & 1) ? AW1 : AW0;
            const uint32_t bcur = (it & 1) ? BR1 : BR0;
            const int kb = it * 32;
#pragma unroll
            for (int i = 0; i < 2; i++) {   // A groups (attn writeback)
                const int idx = tid + i * 256;
                const int r = idx >> 2, ch = idx & 3;
                uint4 hv = *(const uint4*)(sw + acur + r * WROW + ch * 4);
                const __half2* h2 = (const __half2*)&hv;
                const float inv = i ? inv1s : inv0s;
                float2 f0 = __half22float2(h2[0]);
                float2 f1 = __half22float2(h2[1]);
                float2 f2 = __half22float2(h2[2]);
                float2 f3 = __half22float2(h2[3]);
                float* dst = &AWz[(long long)(m0 + r) * TT + kb + ch * 8];
                *(float4*)dst       = make_float4(f0.x * inv, f0.y * inv, f1.x * inv, f1.y * inv);
                *(float4*)(dst + 4) = make_float4(f2.x * inv, f2.y * inv, f3.x * inv, f3.y * inv);
            }
#pragma unroll
            for (int i = 0; i < 2; i++) {   // B groups (V fp16 hi/lo)
                const int j = tid + i * 256;
                const int r = j >> 3, c4 = (j & 7) * 4;
                float4 x = *(const float4*)(sw + bcur + j * 4);
                uint32_t* dh = sw + BVH + r * WROW + (c4 >> 1);
                split_store_f16(x, dh, dh + (BVL - BVH));
            }
        }
        __syncthreads();

        // ---- MMA (f16): raw exph @ (Vh + Vl) ----
        {
            const uint32_t abase = sb + ((it & 1) ? AW1 : AW0) * 4;
#pragma unroll
            for (int kk2 = 0; kk2 < 2; kk2++) {
                uint32_t bh[NI][2], bl[NI][2];
#pragma unroll
                for (int np = 0; np < 2; np++) {
                    ldsm_x4(bh[np * 2][0], bh[np * 2][1], bh[np * 2 + 1][0], bh[np * 2 + 1][1],
                            b_addr[kk2][np]);
                    ldsm_x4(bl[np * 2][0], bl[np * 2][1], bl[np * 2 + 1][0], bl[np * 2 + 1][1],
                            b_addr[kk2][np] + (BVL - BVH) * 4);
                }
#pragma unroll
                for (int mi = 0; mi < MI; mi++) {
                    uint32_t ah[4];
                    ldsm_x4(ah[0], ah[1], ah[2], ah[3], abase + a_off[kk2][mi]);
#pragma unroll
                    for (int ni = 0; ni < NI; ni++) {
                        mma16816h(acc[mi][ni], ah, bh[ni]);
                        mma16816h(acc[mi][ni], ah, bl[ni]);
                    }
                }
            }
        }
        if (more) __syncthreads();
    }

    // ---- epilogue: scale by inv_row, write mh ----
#pragma unroll
    for (int mi = 0; mi < MI; mi++) {
        const int r0 = m0 + wm * 32 + mi * 16 + g;
        const int r1 = r0 + 8;
        const float i0 = invz[r0];
        const float i1 = invz[r1];
#pragma unroll
        for (int ni = 0; ni < NI; ni++) {
            const int c = wn * 32 + ni * 8 + tg * 2;
            *(float2*)&mhz[(long long)r0 * EE + c] =
                make_float2(acc[mi][ni][0] * i0, acc[mi][ni][1] * i0);
            *(float2*)&mhz[(long long)r1 * EE + c] =
                make_float2(acc[mi][ni][2] * i1, acc[mi][ni][3] * i1);
        }
    }
}

// ---------------------------------------------------------------------------
// rowsum helpers
// ---------------------------------------------------------------------------
__global__ void zero_rowsum(float* rs) {
    rs[blockIdx.x * 256 + threadIdx.x] = 0.f;
}
__global__ void invert_rowsum(float* rs) {
    const int i = blockIdx.x * 256 + threadIdx.x;
    rs[i] = 1.f / rs[i];
}

// ---------------------------------------------------------------------------
// Transposes
// ---------------------------------------------------------------------------
__global__ __launch_bounds__(256) void transpose_v(const float* __restrict__ v,
                                                   float* __restrict__ vt)
{
    __shared__ float tile[32][33];
    const int z = blockIdx.z;
    const int b = z / HH, h = z % HH;
    const int m0 = blockIdx.x * 32;
    const int d0 = blockIdx.y * 32;
    const int tx = threadIdx.x & 31;
    const int ty0 = threadIdx.x >> 5;
#pragma unroll
    for (int ty = ty0; ty < 32; ty += 8)
        tile[ty][tx] = v[((long long)b * TT + m0 + ty) * EE + h * DD + d0 + tx];
    __syncthreads();
#pragma unroll
    for (int ty = ty0; ty < 32; ty += 8)
        vt[(((long long)z) * DD + d0 + ty) * TT + m0 + tx] = tile[tx][ty];
}

__global__ __launch_bounds__(256) void transpose_pk(const float* __restrict__ pk,
                                                    float* __restrict__ pkt)
{
    __shared__ float tile[32][33];
    const int k0 = blockIdx.x * 32;
    const int o0 = blockIdx.y * 32;
    const int tx = threadIdx.x & 31;
    const int ty0 = threadIdx.x >> 5;
#pragma unroll
    for (int ty = ty0; ty < 32; ty += 8)
        tile[ty][tx] = pk[(long long)(k0 + ty) * OO + o0 + tx];
    __syncthreads();
#pragma unroll
    for (int ty = ty0; ty < 32; ty += 8)
        pkt[(long long)(o0 + ty) * EE + k0 + tx] = tile[tx][ty];
}

// ---------------------------------------------------------------------------
// Launch
// ---------------------------------------------------------------------------
extern "C" void kernel_launch(void* const* d_in, const int* in_sizes, int n_in,
                              void* d_out, int out_size)
{
    const float* query = (const float*)d_in[0];
    const float* key   = (const float*)d_in[1];
    const float* value = (const float*)d_in[2];
    const float* Wq    = (const float*)d_in[3];
    const float* Wk    = (const float*)d_in[4];
    const float* Wv    = (const float*)d_in[5];
    const float* pk    = (const float*)d_in[6];
    const float* pb    = (const float*)d_in[7];

    float *qkvp, *mhp, *vtp, *pktp, *rsp, *outs, *attns;
    __half* ehp;
    cudaGetSymbolAddress((void**)&qkvp,  g_qkv);
    cudaGetSymbolAddress((void**)&mhp,   g_mh);
    cudaGetSymbolAddress((void**)&vtp,   g_vt);
    cudaGetSymbolAddress((void**)&pktp,  g_pkt);
    cudaGetSymbolAddress((void**)&rsp,   g_rowsum);
    cudaGetSymbolAddress((void**)&ehp,   g_exph);
    cudaGetSymbolAddress((void**)&outs,  g_out_scratch);
    cudaGetSymbolAddress((void**)&attns, g_attn_scratch);

    const long long qkvN = (long long)BB * TT * EE;
    float* qp = qkvp;
    float* kp = qkvp + qkvN;
    float* vp = qkvp + 2 * qkvN;

    const long long outN  = (long long)BB * TT * OO;
    const long long attnN = (long long)BB * HH * TT * TT;

    float* outP  = (float*)d_out;
    float* attnP;
    if ((long long)out_size >= outN + attnN) {
        attnP = outP + outN;
    } else if ((long long)out_size == attnN) {
        attnP = (float*)d_out;
        outP  = outs;
    } else {
        attnP = attns;
    }

    constexpr int SMEM128 = (2 * 256 * 32 + 256 * 40) * 4;  // 106496
    constexpr int SMEMAV  = 11776 * 4;                      // 47104
    cudaFuncSetAttribute(mma_gemm<128, 1, 0>, cudaFuncAttributeMaxDynamicSharedMemorySize, SMEM128);
    cudaFuncSetAttribute(mma_gemm<128, 0, 0>, cudaFuncAttributeMaxDynamicSharedMemorySize, SMEM128);
    cudaFuncSetAttribute(mma_gemm<128, 0, 1>, cudaFuncAttributeMaxDynamicSharedMemorySize, SMEM128);
    cudaFuncSetAttribute(mma_av, cudaFuncAttributeMaxDynamicSharedMemorySize, SMEMAV);

    // 0) zero row sums (graph-replay safe)
    zero_rowsum<<<(BB * HH * TT) / 256, 256>>>(rsp);

    // 1) Q/K/V projections, batched over z = 0,1,2
    {
        dim3 grid(EE / 128, (BB * TT) / 128, 3);
        mma_gemm<128, 1, 0><<<grid, 256, SMEM128>>>(
            query, key, value, EE, 1, 0, 0,
            Wq, Wk, Wv, EE, 0, 0,
            qkvp, EE, qkvN, 0,
            EE, 1.f, nullptr, nullptr, nullptr);
    }

    // transposes: V -> [b][h][d][m], pk -> [o][k]
    {
        dim3 gv(TT / 32, DD / 32, BB * HH);
        transpose_v<<<gv, 256>>>(vp, vtp);
        dim3 gp(EE / 32, OO / 32, 1);
        transpose_pk<<<gp, 256>>>(pk, pktp);
    }

    // 2) exph = fp16(exp(0.125 * q @ k^T)); fp16-rounded row sums via atomics
    {
        dim3 grid(TT / 128, TT / 128, BB * HH);
        mma_gemm<128, 0, 1><<<grid, 256, SMEM128>>>(
            qp, nullptr, nullptr, EE, HH, (long long)TT * EE, DD,
            kp, nullptr, nullptr, EE,     (long long)TT * EE, DD,
            nullptr, TT, 0, 0,
            DD, 0.125f, nullptr, rsp, ehp);
    }

    // 3) invert row sums
    invert_rowsum<<<(BB * HH * TT) / 256, 256>>>(rsp);

    // 4) mh = inv * (exph @ vT^T); writes normalized fp32 attn once
    {
        dim3 grid(TT / 128, BB * HH);
        mma_av<<<grid, 256, SMEMAV>>>(ehp, vtp, rsp, attnP, mhp);
    }

    // 5) out = mh @ pkT^T + bias
    {
        dim3 grid(OO / 128, (BB * TT) / 128, 1);
        mma_gemm<128, 0, 0><<<grid, 256, SMEM128>>>(
            mhp, nullptr, nullptr, EE, 1, 0, 0,
            pktp, nullptr, nullptr, EE, 0, 0,
            outP, OO, 0, 0, EE, 1.f, pb, nullptr, nullptr);
    }
}

// round 14
// speedup vs baseline: 1.2567x; 1.0712x over previous
#include <cuda_runtime.h>
#include <cuda_bf16.h>
#include <cuda_fp16.h>
#include <cstdint>

// Problem dims
#define BB 2
#define TT 2048
#define HH 16
#define DD 64
#define EE 1024   // HH*DD
#define OO 1024

// Scratch (device globals)
__device__ float g_qkv[(size_t)3 * BB * TT * EE];     // q | k | v contiguous
__device__ float g_mh[(size_t)BB * TT * EE];
__device__ float g_vt[(size_t)BB * TT * EE];          // V transposed: [b][h][d][m]
__device__ float g_pkt[(size_t)EE * OO];              // proj kernel transposed: [o][k]
__device__ float g_rowsum[(size_t)BB * HH * TT];      // exp row sums -> inverses
__device__ __half g_exph[(size_t)BB * HH * TT * TT];  // fp16 exp(logits) intermediate
__device__ float g_out_scratch[(size_t)BB * TT * OO];
__device__ float g_attn_scratch[(size_t)BB * HH * TT * TT];

// ---------------------------------------------------------------------------
// PTX helpers (baseline features only: sm_80-era, legal at compute_103)
// ---------------------------------------------------------------------------
__device__ __forceinline__ uint32_t smem_u32(const void* p) {
    uint32_t a;
    asm("{ .reg .u64 t; cvta.to.shared.u64 t, %1; cvt.u32.u64 %0, t; }" : "=r"(a) : "l"(p));
    return a;
}
#define CP_ASYNC16(dst_u32, src_ptr) \
    asm volatile("cp.async.cg.shared.global [%0], [%1], 16;" :: "r"(dst_u32), "l"(src_ptr))
#define CP_COMMIT() asm volatile("cp.async.commit_group;" ::: "memory")
#define CP_WAIT1()  asm volatile("cp.async.wait_group 1;" ::: "memory")
#define CP_WAIT0()  asm volatile("cp.async.wait_group 0;" ::: "memory")

__device__ __forceinline__ void mma16816bf(float* c, const uint32_t* a, const uint32_t* b) {
    asm volatile(
        "mma.sync.aligned.m16n8k16.row.col.f32.bf16.bf16.f32 "
        "{%0,%1,%2,%3}, {%4,%5,%6,%7}, {%8,%9}, {%0,%1,%2,%3};"
        : "+f"(c[0]), "+f"(c[1]), "+f"(c[2]), "+f"(c[3])
        : "r"(a[0]), "r"(a[1]), "r"(a[2]), "r"(a[3]), "r"(b[0]), "r"(b[1]));
}
__device__ __forceinline__ void mma16816h(float* c, const uint32_t* a, const uint32_t* b) {
    asm volatile(
        "mma.sync.aligned.m16n8k16.row.col.f32.f16.f16.f32 "
        "{%0,%1,%2,%3}, {%4,%5,%6,%7}, {%8,%9}, {%0,%1,%2,%3};"
        : "+f"(c[0]), "+f"(c[1]), "+f"(c[2]), "+f"(c[3])
        : "r"(a[0]), "r"(a[1]), "r"(a[2]), "r"(a[3]), "r"(b[0]), "r"(b[1]));
}

__device__ __forceinline__ void ldsm_x4(uint32_t& r0, uint32_t& r1, uint32_t& r2, uint32_t& r3,
                                        uint32_t addr) {
    asm volatile("ldmatrix.sync.aligned.m8n8.x4.shared.b16 {%0,%1,%2,%3}, [%4];"
                 : "=r"(r0), "=r"(r1), "=r"(r2), "=r"(r3) : "r"(addr));
}

// bf16 hi/lo split store
__device__ __forceinline__ void split_store_bf(float4 x, uint32_t* dh, uint32_t* dl) {
    __nv_bfloat162 h0 = __floats2bfloat162_rn(x.x, x.y);
    __nv_bfloat162 h1 = __floats2bfloat162_rn(x.z, x.w);
    float l0 = x.x - __bfloat162float(h0.x);
    float l1 = x.y - __bfloat162float(h0.y);
    float l2 = x.z - __bfloat162float(h1.x);
    float l3 = x.w - __bfloat162float(h1.y);
    __nv_bfloat162 lo0 = __floats2bfloat162_rn(l0, l1);
    __nv_bfloat162 lo1 = __floats2bfloat162_rn(l2, l3);
    *(uint2*)dh = make_uint2(*(uint32_t*)&h0, *(uint32_t*)&h1);
    *(uint2*)dl = make_uint2(*(uint32_t*)&lo0, *(uint32_t*)&lo1);
}
// fp16 hi/lo split store
__device__ __forceinline__ void split_store_f16(float4 x, uint32_t* dh, uint32_t* dl) {
    __half2 h0 = __floats2half2_rn(x.x, x.y);
    __half2 h1 = __floats2half2_rn(x.z, x.w);
    float2 f0 = __half22float2(h0);
    float2 f1 = __half22float2(h1);
    __half2 l0 = __floats2half2_rn(x.x - f0.x, x.y - f0.y);
    __half2 l1 = __floats2half2_rn(x.z - f1.x, x.w - f1.y);
    *(uint2*)dh = make_uint2(*(uint32_t*)&h0, *(uint32_t*)&h1);
    *(uint2*)dl = make_uint2(*(uint32_t*)&l0, *(uint32_t*)&l1);
}
// fp16 hi only
__device__ __forceinline__ void store_f16_hi(float4 x, uint32_t* dh) {
    __half2 h0 = __floats2half2_rn(x.x, x.y);
    __half2 h1 = __floats2half2_rn(x.z, x.w);
    *(uint2*)dh = make_uint2(*(uint32_t*)&h0, *(uint32_t*)&h1);
}

__device__ __forceinline__ float ex2f(float x) {
    float r;
    asm("ex2.approx.f32 %0, %1;" : "=f"(r) : "f"(x));
    return r;
}

// ---------------------------------------------------------------------------
// cp.async double-buffered tensor-core GEMM with ldmatrix fragment loads:
//   C[M,N] = alpha * A[M,K] * B[N,K]^T (+bias)
// MODE 0: plain epilogue (writes C).
// MODE 1: epilogue writes fp16 exp(alpha*acc) to EH; fp16-rounded row sums
//         atomicAdd'ed into rowsum. C unused.
// FMT 0: bf16 splits; FMT 1: fp16 splits.
// TERMS 3: AhBh + AhBl + AlBh. TERMS 2: AhBh + AhBl (A low never materialized).
// BATCH3=1: blockIdx.z selects (A,A1,A2)/(B,B1,B2), C += z*sC1.
// ---------------------------------------------------------------------------
template <int NTILE, int BATCH3, int MODE, int FMT, int TERMS>
__global__ __launch_bounds__(256, 2) void mma_gemm(
    const float* __restrict__ A, const float* __restrict__ A1q, const float* __restrict__ A2q,
    int lda, int zdiv, long long sA1, long long sA2,
    const float* __restrict__ Bm, const float* __restrict__ B1q, const float* __restrict__ B2q,
    int ldb, long long sB1, long long sB2,
    float* __restrict__ C, int ldc, long long sC1, long long sC2,
    int K, float alpha, const float* __restrict__ bias,
    float* rowsum, __half* EH)
{
    constexpr int WROW  = 20;
    constexpr int ROWS  = 128 + NTILE;
    constexpr int NLOOP = ROWS / 32;
    constexpr int RAWW  = ROWS * 32;
    constexpr int WM    = (NTILE == 128) ? 2 : 4;
    constexpr int MI    = 128 / (WM * 16);
    constexpr int NI    = 4;
    constexpr int AHL   = 128 * WROW;                    // A hi section (words)
    constexpr int BOFF  = (TERMS == 3) ? 2 * AHL : AHL;  // B hi start
    constexpr int BHL   = NTILE * WROW;

    extern __shared__ char smem[];
    float*    raw0p = (float*)smem;
    float*    raw1p = (float*)(smem + RAWW * 4);
    uint32_t* bw    = (uint32_t*)(smem + 2 * RAWW * 4);
    const uint32_t raw0a = smem_u32(raw0p);
    const uint32_t raw1a = raw0a + RAWW * 4;
    const uint32_t bwa   = raw0a + 2 * RAWW * 4;

    const int z = blockIdx.z;
    if (BATCH3) {
        A  = (z == 0) ? A  : (z == 1 ? A1q : A2q);
        Bm = (z == 0) ? Bm : (z == 1 ? B1q : B2q);
        C += (long long)z * sC1;
    } else {
        const int z1 = z / zdiv, z2 = z % zdiv;
        A  += (long long)z1 * sA1 + (long long)z2 * sA2;
        Bm += (long long)z1 * sB1 + (long long)z2 * sB2;
        if (MODE == 0) C += (long long)z1 * sC1 + (long long)z2 * sC2;
    }
    float*  rowsumz = (MODE == 1) ? rowsum + (long long)z * TT : nullptr;
    __half* EHz     = (MODE == 1) ? EH + (long long)z * TT * TT : nullptr;

    const int m0 = blockIdx.y * 128;
    const int n0 = blockIdx.x * NTILE;

    const int tid  = threadIdx.x;
    const int warp = tid >> 5;
    const int lane = tid & 31;
    const int wm   = warp % WM;
    const int wn   = warp / WM;
    const int g    = lane >> 2;
    const int tg   = lane & 3;

    uint32_t a_addr[2][MI], b_addr[2][2];
    {
        const int lm  = lane & 7;
        const int l8  = (lane >> 3) & 1;
        const int l16 = lane >> 4;
        const int bm  = lane >> 3;
#pragma unroll
        for (int kk2 = 0; kk2 < 2; kk2++) {
#pragma unroll
            for (int mi = 0; mi < MI; mi++) {
                const int row = wm * (MI * 16) + mi * 16 + lm + l8 * 8;
                const int off = kk2 * 8 + l16 * 4;
                a_addr[kk2][mi] = bwa + (uint32_t)(row * WROW + off) * 4;
            }
#pragma unroll
            for (int np = 0; np < 2; np++) {
                const int nrow = wn * 32 + np * 16 + (bm >> 1) * 8 + lm;
                const int koff = kk2 * 8 + (bm & 1) * 4;
                b_addr[kk2][np] = bwa + (uint32_t)(BOFF + nrow * WROW + koff) * 4;
            }
        }
    }

    float acc[MI][NI][4];
#pragma unroll
    for (int mi = 0; mi < MI; mi++)
#pragma unroll
        for (int ni = 0; ni < NI; ni++)
#pragma unroll
            for (int r = 0; r < 4; r++) acc[mi][ni][r] = 0.f;

#pragma unroll
    for (int i = 0; i < NLOOP; i++) {
        const int idx = tid + i * 256;
        const bool isA = idx < 1024;
        const int r = isA ? (idx >> 3) : ((idx - 1024) >> 3);
        const int c = (idx & 7) * 4;
        const float* src = isA ? &A[(long long)(m0 + r) * lda + c]
                               : &Bm[(long long)(n0 + r) * ldb + c];
        CP_ASYNC16(raw0a + idx * 16, src);
    }
    CP_COMMIT();

    const int NIT = K / 32;

    for (int it = 0; it < NIT; it++) {
        const bool more = (it + 1) < NIT;
        const int kbn = (it + 1) * 32;
        if (more) {
            const uint32_t rdst = ((it + 1) & 1) ? raw1a : raw0a;
#pragma unroll
            for (int i = 0; i < NLOOP; i++) {
                const int idx = tid + i * 256;
                const bool isA = idx < 1024;
                const int r = isA ? (idx >> 3) : ((idx - 1024) >> 3);
                const int c = (idx & 7) * 4;
                const float* src = isA ? &A[(long long)(m0 + r) * lda + kbn + c]
                                       : &Bm[(long long)(n0 + r) * ldb + kbn + c];
                CP_ASYNC16(rdst + idx * 16, src);
            }
            CP_COMMIT();
            CP_WAIT1();
        } else {
            CP_WAIT0();
        }

        {
            const float* rbuf = (it & 1) ? raw1p : raw0p;
#pragma unroll
            for (int i = 0; i < NLOOP; i++) {
                const int idx = tid + i * 256;
                const bool isA = idx < 1024;
                const int r = isA ? (idx >> 3) : ((idx - 1024) >> 3);
                const int c = (idx & 7) * 4;
                float4 x = *(const float4*)(rbuf + idx * 4);
                const uint32_t w = r * WROW + (c >> 1);
                if (isA) {
                    uint32_t* dh = bw + w;
                    if (TERMS == 3) {
                        if (FMT == 0) split_store_bf(x, dh, dh + AHL);
                        else          split_store_f16(x, dh, dh + AHL);
                    } else {
                        store_f16_hi(x, dh);
                    }
                } else {
                    uint32_t* dh = bw + BOFF + w;
                    if (FMT == 0) split_store_bf(x, dh, dh + BHL);
                    else          split_store_f16(x, dh, dh + BHL);
                }
            }
        }
        __syncthreads();

        {
#pragma unroll
            for (int kk2 = 0; kk2 < 2; kk2++) {
                uint32_t bh[NI][2], bl[NI][2];
#pragma unroll
                for (int np = 0; np < 2; np++) {
                    ldsm_x4(bh[np * 2][0], bh[np * 2][1], bh[np * 2 + 1][0], bh[np * 2 + 1][1],
                            b_addr[kk2][np]);
                    ldsm_x4(bl[np * 2][0], bl[np * 2][1], bl[np * 2 + 1][0], bl[np * 2 + 1][1],
                            b_addr[kk2][np] + BHL * 4);
                }
#pragma unroll
                for (int mi = 0; mi < MI; mi++) {
                    uint32_t ah[4], al[4];
                    ldsm_x4(ah[0], ah[1], ah[2], ah[3], a_addr[kk2][mi]);
                    if (TERMS == 3)
                        ldsm_x4(al[0], al[1], al[2], al[3], a_addr[kk2][mi] + AHL * 4);
#pragma unroll
                    for (int ni = 0; ni < NI; ni++) {
                        if (FMT == 0) {
                            mma16816bf(acc[mi][ni], ah, bh[ni]);
                            mma16816bf(acc[mi][ni], ah, bl[ni]);
                            if (TERMS == 3) mma16816bf(acc[mi][ni], al, bh[ni]);
                        } else {
                            mma16816h(acc[mi][ni], ah, bh[ni]);
                            mma16816h(acc[mi][ni], ah, bl[ni]);
                            if (TERMS == 3) mma16816h(acc[mi][ni], al, bh[ni]);
                        }
                    }
                }
            }
        }
        if (more) __syncthreads();
    }

    // ---- epilogue ----
    const float a2 = alpha * 1.44269504f;   // fold log2(e) for ex2
#pragma unroll
    for (int mi = 0; mi < MI; mi++) {
        const int r0 = m0 + wm * (MI * 16) + mi * 16 + g;
        const int r1 = r0 + 8;
        float p0 = 0.f, p1 = 0.f;
#pragma unroll
        for (int ni = 0; ni < NI; ni++) {
            const int c = n0 + wn * 32 + ni * 8 + tg * 2;
            if (MODE == 1) {
                __half q0 = __float2half_rn(ex2f(acc[mi][ni][0] * a2));
                __half q1 = __float2half_rn(ex2f(acc[mi][ni][1] * a2));
                __half q2 = __float2half_rn(ex2f(acc[mi][ni][2] * a2));
                __half q3 = __float2half_rn(ex2f(acc[mi][ni][3] * a2));
                *(__half2*)&EHz[(long long)r0 * TT + c] = __halves2half2(q0, q1);
                *(__half2*)&EHz[(long long)r1 * TT + c] = __halves2half2(q2, q3);
                p0 += __half2float(q0) + __half2float(q1);
                p1 += __half2float(q2) + __half2float(q3);
            } else {
                float2 bv = make_float2(0.f, 0.f);
                if (bias) bv = *(const float2*)&bias[c];
                float2 o0, o1;
                o0.x = acc[mi][ni][0] * alpha + bv.x;
                o0.y = acc[mi][ni][1] * alpha + bv.y;
                o1.x = acc[mi][ni][2] * alpha + bv.x;
                o1.y = acc[mi][ni][3] * alpha + bv.y;
                *(float2*)&C[(long long)r0 * ldc + c] = o0;
                *(float2*)&C[(long long)r1 * ldc + c] = o1;
            }
        }
        if (MODE == 1) {
            p0 += __shfl_xor_sync(0xffffffffu, p0, 1);
            p0 += __shfl_xor_sync(0xffffffffu, p0, 2);
            p1 += __shfl_xor_sync(0xffffffffu, p1, 1);
            p1 += __shfl_xor_sync(0xffffffffu, p1, 2);
            if (tg == 0) {
                atomicAdd(&rowsumz[r0], p0);
                atomicAdd(&rowsumz[r1], p1);
            }
        }
    }
}

// ---------------------------------------------------------------------------
// AV kernel: mh[b,m,h,:] = inv_row * (exph[m,:] @ V^T)
//   A = exph (fp16) cp.async'ed DIRECTLY into ldmatrix layout (no convert)
//   B = Vt (fp32) split into fp16 hi/lo; f16 MMA x2; normalization in epilogue;
//   convert phase writes normalized fp32 attn from the smem A copy.
// CTA 128x64, k-slab 32, 256 threads (4m x 2n warps), 2 CTAs/SM.
// ---------------------------------------------------------------------------
__global__ __launch_bounds__(256, 2) void mma_av(
    const __half* __restrict__ exph, const float* __restrict__ Vt,
    const float* __restrict__ invr,
    float* __restrict__ attn, float* __restrict__ mh)
{
    constexpr int WROW = 20;
    constexpr int AW0 = 0, AW1 = 2560;
    constexpr int BR0 = 5120, BR1 = 7168;
    constexpr int BVH = 9216, BVL = 10496;
    constexpr int MI = 2, NI = 4;

    extern __shared__ char smem[];
    uint32_t* sw = (uint32_t*)smem;
    const uint32_t sb = smem_u32(smem);

    const int z = blockIdx.y;
    const int b = z / HH, h = z % HH;
    const int m0 = blockIdx.x * 128;

    const __half* EHz = exph + (long long)z * TT * TT;
    const float*  Vz  = Vt + (long long)z * DD * TT;
    float* AWz = attn + (long long)z * TT * TT;
    float* mhz = mh + (long long)b * TT * EE + h * DD;
    const float* invz = invr + (long long)z * TT;

    const int tid  = threadIdx.x;
    const int warp = tid >> 5;
    const int lane = tid & 31;
    const int wm   = warp & 3;
    const int wn   = warp >> 2;
    const int g    = lane >> 2;
    const int tg   = lane & 3;

    const float inv0s = invz[m0 + (tid >> 2)];
    const float inv1s = invz[m0 + (tid >> 2) + 64];

    uint32_t a_off[2][MI];
    uint32_t b_addr[2][2];
    {
        const int lm  = lane & 7;
        const int l8  = (lane >> 3) & 1;
        const int l16 = lane >> 4;
        const int bm  = lane >> 3;
#pragma unroll
        for (int kk2 = 0; kk2 < 2; kk2++) {
#pragma unroll
            for (int mi = 0; mi < MI; mi++) {
                const int row = wm * 32 + mi * 16 + lm + l8 * 8;
                a_off[kk2][mi] = (uint32_t)(row * WROW + kk2 * 8 + l16 * 4) * 4;
            }
#pragma unroll
            for (int np = 0; np < 2; np++) {
                const int nrow = wn * 32 + np * 16 + (bm >> 1) * 8 + lm;
                const int koff = kk2 * 8 + (bm & 1) * 4;
                b_addr[kk2][np] = sb + (uint32_t)(BVH + nrow * WROW + koff) * 4;
            }
        }
    }

    float acc[MI][NI][4];
#pragma unroll
    for (int mi = 0; mi < MI; mi++)
#pragma unroll
        for (int ni = 0; ni < NI; ni++)
#pragma unroll
            for (int r = 0; r < 4; r++) acc[mi][ni][r] = 0.f;

#pragma unroll
    for (int i = 0; i < 4; i++) {
        const int idx = tid + i * 256;
        if (idx < 512) {
            const int r = idx >> 2, ch = idx & 3;
            CP_ASYNC16(sb + AW0 * 4 + r * 80 + ch * 16, EHz + (long long)(m0 + r) * TT + ch * 8);
        } else {
            const int j = idx - 512;
            const int r = j >> 3, c4 = (j & 7) * 4;
            CP_ASYNC16(sb + BR0 * 4 + j * 16, Vz + (long long)r * TT + c4);
        }
    }
    CP_COMMIT();

    const int NIT = TT / 32;

    for (int it = 0; it < NIT; it++) {
        const bool more = (it + 1) < NIT;
        const int kbn = (it + 1) * 32;
        if (more) {
            const uint32_t adst = sb + (((it + 1) & 1) ? AW1 : AW0) * 4;
            const uint32_t bdst = sb + (((it + 1) & 1) ? BR1 : BR0) * 4;
#pragma unroll
            for (int i = 0; i < 4; i++) {
                const int idx = tid + i * 256;
                if (idx < 512) {
                    const int r = idx >> 2, ch = idx & 3;
                    CP_ASYNC16(adst + r * 80 + ch * 16, EHz + (long long)(m0 + r) * TT + kbn + ch * 8);
                } else {
                    const int j = idx - 512;
                    const int r = j >> 3, c4 = (j & 7) * 4;
                    CP_ASYNC16(bdst + j * 16, Vz + (long long)r * TT + kbn + c4);
                }
            }
            CP_COMMIT();
            CP_WAIT1();
        } else {
            CP_WAIT0();
        }

        {
            const uint32_t acur = (it & 1) ? AW1 : AW0;
            const uint32_t bcur = (it & 1) ? BR1 : BR0;
            const int kb = it * 32;
#pragma unroll
            for (int i = 0; i < 2; i++) {
                const int idx = tid + i * 256;
                const int r = idx >> 2, ch = idx & 3;
                uint4 hv = *(const uint4*)(sw + acur + r * WROW + ch * 4);
                const __half2* h2 = (const __half2*)&hv;
                const float inv = i ? inv1s : inv0s;
                float2 f0 = __half22float2(h2[0]);
                float2 f1 = __half22float2(h2[1]);
                float2 f2 = __half22float2(h2[2]);
                float2 f3 = __half22float2(h2[3]);
                float* dst = &AWz[(long long)(m0 + r) * TT + kb + ch * 8];
                *(float4*)dst       = make_float4(f0.x * inv, f0.y * inv, f1.x * inv, f1.y * inv);
                *(float4*)(dst + 4) = make_float4(f2.x * inv, f2.y * inv, f3.x * inv, f3.y * inv);
            }
#pragma unroll
            for (int i = 0; i < 2; i++) {
                const int j = tid + i * 256;
                const int r = j >> 3, c4 = (j & 7) * 4;
                float4 x = *(const float4*)(sw + bcur + j * 4);
                uint32_t* dh = sw + BVH + r * WROW + (c4 >> 1);
                split_store_f16(x, dh, dh + (BVL - BVH));
            }
        }
        __syncthreads();

        {
            const uint32_t abase = sb + ((it & 1) ? AW1 : AW0) * 4;
#pragma unroll
            for (int kk2 = 0; kk2 < 2; kk2++) {
                uint32_t bh[NI][2], bl[NI][2];
#pragma unroll
                for (int np = 0; np < 2; np++) {
                    ldsm_x4(bh[np * 2][0], bh[np * 2][1], bh[np * 2 + 1][0], bh[np * 2 + 1][1],
                            b_addr[kk2][np]);
                    ldsm_x4(bl[np * 2][0], bl[np * 2][1], bl[np * 2 + 1][0], bl[np * 2 + 1][1],
                            b_addr[kk2][np] + (BVL - BVH) * 4);
                }
#pragma unroll
                for (int mi = 0; mi < MI; mi++) {
                    uint32_t ah[4];
                    ldsm_x4(ah[0], ah[1], ah[2], ah[3], abase + a_off[kk2][mi]);
#pragma unroll
                    for (int ni = 0; ni < NI; ni++) {
                        mma16816h(acc[mi][ni], ah, bh[ni]);
                        mma16816h(acc[mi][ni], ah, bl[ni]);
                    }
                }
            }
        }
        if (more) __syncthreads();
    }

#pragma unroll
    for (int mi = 0; mi < MI; mi++) {
        const int r0 = m0 + wm * 32 + mi * 16 + g;
        const int r1 = r0 + 8;
        const float i0 = invz[r0];
        const float i1 = invz[r1];
#pragma unroll
        for (int ni = 0; ni < NI; ni++) {
            const int c = wn * 32 + ni * 8 + tg * 2;
            *(float2*)&mhz[(long long)r0 * EE + c] =
                make_float2(acc[mi][ni][0] * i0, acc[mi][ni][1] * i0);
            *(float2*)&mhz[(long long)r1 * EE + c] =
                make_float2(acc[mi][ni][2] * i1, acc[mi][ni][3] * i1);
        }
    }
}

// ---------------------------------------------------------------------------
// rowsum helpers
// ---------------------------------------------------------------------------
__global__ void zero_rowsum(float* rs) {
    rs[blockIdx.x * 256 + threadIdx.x] = 0.f;
}
__global__ void invert_rowsum(float* rs) {
    const int i = blockIdx.x * 256 + threadIdx.x;
    rs[i] = 1.f / rs[i];
}

// ---------------------------------------------------------------------------
// Transposes
// ---------------------------------------------------------------------------
__global__ __launch_bounds__(256) void transpose_v(const float* __restrict__ v,
                                                   float* __restrict__ vt)
{
    __shared__ float tile[32][33];
    const int z = blockIdx.z;
    const int b = z / HH, h = z % HH;
    const int m0 = blockIdx.x * 32;
    const int d0 = blockIdx.y * 32;
    const int tx = threadIdx.x & 31;
    const int ty0 = threadIdx.x >> 5;
#pragma unroll
    for (int ty = ty0; ty < 32; ty += 8)
        tile[ty][tx] = v[((long long)b * TT + m0 + ty) * EE + h * DD + d0 + tx];
    __syncthreads();
#pragma unroll
    for (int ty = ty0; ty < 32; ty += 8)
        vt[(((long long)z) * DD + d0 + ty) * TT + m0 + tx] = tile[tx][ty];
}

__global__ __launch_bounds__(256) void transpose_pk(const float* __restrict__ pk,
                                                    float* __restrict__ pkt)
{
    __shared__ float tile[32][33];
    const int k0 = blockIdx.x * 32;
    const int o0 = blockIdx.y * 32;
    const int tx = threadIdx.x & 31;
    const int ty0 = threadIdx.x >> 5;
#pragma unroll
    for (int ty = ty0; ty < 32; ty += 8)
        tile[ty][tx] = pk[(long long)(k0 + ty) * OO + o0 + tx];
    __syncthreads();
#pragma unroll
    for (int ty = ty0; ty < 32; ty += 8)
        pkt[(long long)(o0 + ty) * EE + k0 + tx] = tile[tx][ty];
}

// ---------------------------------------------------------------------------
// Launch
// ---------------------------------------------------------------------------
extern "C" void kernel_launch(void* const* d_in, const int* in_sizes, int n_in,
                              void* d_out, int out_size)
{
    const float* query = (const float*)d_in[0];
    const float* key   = (const float*)d_in[1];
    const float* value = (const float*)d_in[2];
    const float* Wq    = (const float*)d_in[3];
    const float* Wk    = (const float*)d_in[4];
    const float* Wv    = (const float*)d_in[5];
    const float* pk    = (const float*)d_in[6];
    const float* pb    = (const float*)d_in[7];

    float *qkvp, *mhp, *vtp, *pktp, *rsp, *outs, *attns;
    __half* ehp;
    cudaGetSymbolAddress((void**)&qkvp,  g_qkv);
    cudaGetSymbolAddress((void**)&mhp,   g_mh);
    cudaGetSymbolAddress((void**)&vtp,   g_vt);
    cudaGetSymbolAddress((void**)&pktp,  g_pkt);
    cudaGetSymbolAddress((void**)&rsp,   g_rowsum);
    cudaGetSymbolAddress((void**)&ehp,   g_exph);
    cudaGetSymbolAddress((void**)&outs,  g_out_scratch);
    cudaGetSymbolAddress((void**)&attns, g_attn_scratch);

    const long long qkvN = (long long)BB * TT * EE;
    float* qp = qkvp;
    float* kp = qkvp + qkvN;
    float* vp = qkvp + 2 * qkvN;

    const long long outN  = (long long)BB * TT * OO;
    const long long attnN = (long long)BB * HH * TT * TT;

    float* outP  = (float*)d_out;
    float* attnP;
    if ((long long)out_size >= outN + attnN) {
        attnP = outP + outN;
    } else if ((long long)out_size == attnN) {
        attnP = (float*)d_out;
        outP  = outs;
    } else {
        attnP = attns;
    }

    constexpr int SMEM128 = (2 * 256 * 32 + 256 * 40) * 4;  // 106496 (covers both TERMS)
    constexpr int SMEMAV  = 11776 * 4;                      // 47104
    cudaFuncSetAttribute((const void*)mma_gemm<128, 1, 0, 0, 3>,
                         cudaFuncAttributeMaxDynamicSharedMemorySize, SMEM128);
    cudaFuncSetAttribute((const void*)mma_gemm<128, 0, 1, 1, 2>,
                         cudaFuncAttributeMaxDynamicSharedMemorySize, SMEM128);
    cudaFuncSetAttribute((const void*)mma_gemm<128, 0, 0, 1, 2>,
                         cudaFuncAttributeMaxDynamicSharedMemorySize, SMEM128);
    cudaFuncSetAttribute((const void*)mma_av,
                         cudaFuncAttributeMaxDynamicSharedMemorySize, SMEMAV);

    // 0) zero row sums (graph-replay safe)
    zero_rowsum<<<(BB * HH * TT) / 256, 256>>>(rsp);

    // 1) Q/K/V projections (bf16 3-term, exact), batched over z = 0,1,2
    {
        dim3 grid(EE / 128, (BB * TT) / 128, 3);
        mma_gemm<128, 1, 0, 0, 3><<<grid, 256, SMEM128>>>(
            query, key, value, EE, 1, 0, 0,
            Wq, Wk, Wv, EE, 0, 0,
            qkvp, EE, qkvN, 0,
            EE, 1.f, nullptr, nullptr, nullptr);
    }

    // transposes: V -> [b][h][d][m], pk -> [o][k]
    {
        dim3 gv(TT / 32, DD / 32, BB * HH);
        transpose_v<<<gv, 256>>>(vp, vtp);
        dim3 gp(EE / 32, OO / 32, 1);
        transpose_pk<<<gp, 256>>>(pk, pktp);
    }

    // 2) exph = fp16(exp(0.125 * q @ k^T)); fp16 2-term split
    {
        dim3 grid(TT / 128, TT / 128, BB * HH);
        mma_gemm<128, 0, 1, 1, 2><<<grid, 256, SMEM128>>>(
            qp, nullptr, nullptr, EE, HH, (long long)TT * EE, DD,
            kp, nullptr, nullptr, EE,     (long long)TT * EE, DD,
            nullptr, TT, 0, 0,
            DD, 0.125f, nullptr, rsp, ehp);
    }

    // 3) invert row sums
    invert_rowsum<<<(BB * HH * TT) / 256, 256>>>(rsp);

    // 4) mh = inv * (exph @ vT^T); writes normalized fp32 attn once
    {
        dim3 grid(TT / 128, BB * HH);
        mma_av<<<grid, 256, SMEMAV>>>(ehp, vtp, rsp, attnP, mhp);
    }

    // 5) out = mh @ pkT^T + bias (fp16 2-term)
    {
        dim3 grid(OO / 128, (BB * TT) / 128, 1);
        mma_gemm<128, 0, 0, 1, 2><<<grid, 256, SMEM128>>>(
            mhp, nullptr, nullptr, EE, 1, 0, 0,
            pktp, nullptr, nullptr, EE, 0, 0,
            outP, OO, 0, 0, EE, 1.f, pb, nullptr, nullptr);
    }
}

// round 15
// speedup vs baseline: 1.2843x; 1.0220x over previous
#include <cuda_runtime.h>
#include <cuda_bf16.h>
#include <cuda_fp16.h>
#include <cstdint>

// Problem dims
#define BB 2
#define TT 2048
#define HH 16
#define DD 64
#define EE 1024   // HH*DD
#define OO 1024

// Scratch (device globals)
__device__ float g_qkv[(size_t)3 * BB * TT * EE];     // only v third used now
__device__ float g_mh[(size_t)BB * TT * EE];
__device__ float g_vt[(size_t)BB * TT * EE];          // V transposed: [b][h][d][m]
__device__ float g_pkt[(size_t)EE * OO];              // proj kernel transposed: [o][k]
__device__ float g_rowsum[(size_t)BB * HH * TT];      // exp row sums -> inverses
__device__ __half g_exph[(size_t)BB * HH * TT * TT];  // fp16 exp(logits) intermediate
__device__ __half g_qh[(size_t)BB * TT * EE];         // q fp16 hi
__device__ __half g_kh[(size_t)BB * TT * EE];         // k fp16 hi
__device__ __half g_kl[(size_t)BB * TT * EE];         // k fp16 lo
__device__ float g_out_scratch[(size_t)BB * TT * OO];
__device__ float g_attn_scratch[(size_t)BB * HH * TT * TT];

// ---------------------------------------------------------------------------
// PTX helpers (baseline features only: sm_80-era, legal at compute_103)
// ---------------------------------------------------------------------------
__device__ __forceinline__ uint32_t smem_u32(const void* p) {
    uint32_t a;
    asm("{ .reg .u64 t; cvta.to.shared.u64 t, %1; cvt.u32.u64 %0, t; }" : "=r"(a) : "l"(p));
    return a;
}
#define CP_ASYNC16(dst_u32, src_ptr) \
    asm volatile("cp.async.cg.shared.global [%0], [%1], 16;" :: "r"(dst_u32), "l"(src_ptr))
#define CP_COMMIT() asm volatile("cp.async.commit_group;" ::: "memory")
#define CP_WAIT1()  asm volatile("cp.async.wait_group 1;" ::: "memory")
#define CP_WAIT0()  asm volatile("cp.async.wait_group 0;" ::: "memory")

__device__ __forceinline__ void mma16816bf(float* c, const uint32_t* a, const uint32_t* b) {
    asm volatile(
        "mma.sync.aligned.m16n8k16.row.col.f32.bf16.bf16.f32 "
        "{%0,%1,%2,%3}, {%4,%5,%6,%7}, {%8,%9}, {%0,%1,%2,%3};"
        : "+f"(c[0]), "+f"(c[1]), "+f"(c[2]), "+f"(c[3])
        : "r"(a[0]), "r"(a[1]), "r"(a[2]), "r"(a[3]), "r"(b[0]), "r"(b[1]));
}
__device__ __forceinline__ void mma16816h(float* c, const uint32_t* a, const uint32_t* b) {
    asm volatile(
        "mma.sync.aligned.m16n8k16.row.col.f32.f16.f16.f32 "
        "{%0,%1,%2,%3}, {%4,%5,%6,%7}, {%8,%9}, {%0,%1,%2,%3};"
        : "+f"(c[0]), "+f"(c[1]), "+f"(c[2]), "+f"(c[3])
        : "r"(a[0]), "r"(a[1]), "r"(a[2]), "r"(a[3]), "r"(b[0]), "r"(b[1]));
}

__device__ __forceinline__ void ldsm_x4(uint32_t& r0, uint32_t& r1, uint32_t& r2, uint32_t& r3,
                                        uint32_t addr) {
    asm volatile("ldmatrix.sync.aligned.m8n8.x4.shared.b16 {%0,%1,%2,%3}, [%4];"
                 : "=r"(r0), "=r"(r1), "=r"(r2), "=r"(r3) : "r"(addr));
}

__device__ __forceinline__ void split_store_bf(float4 x, uint32_t* dh, uint32_t* dl) {
    __nv_bfloat162 h0 = __floats2bfloat162_rn(x.x, x.y);
    __nv_bfloat162 h1 = __floats2bfloat162_rn(x.z, x.w);
    float l0 = x.x - __bfloat162float(h0.x);
    float l1 = x.y - __bfloat162float(h0.y);
    float l2 = x.z - __bfloat162float(h1.x);
    float l3 = x.w - __bfloat162float(h1.y);
    __nv_bfloat162 lo0 = __floats2bfloat162_rn(l0, l1);
    __nv_bfloat162 lo1 = __floats2bfloat162_rn(l2, l3);
    *(uint2*)dh = make_uint2(*(uint32_t*)&h0, *(uint32_t*)&h1);
    *(uint2*)dl = make_uint2(*(uint32_t*)&lo0, *(uint32_t*)&lo1);
}
__device__ __forceinline__ void split_store_f16(float4 x, uint32_t* dh, uint32_t* dl) {
    __half2 h0 = __floats2half2_rn(x.x, x.y);
    __half2 h1 = __floats2half2_rn(x.z, x.w);
    float2 f0 = __half22float2(h0);
    float2 f1 = __half22float2(h1);
    __half2 l0 = __floats2half2_rn(x.x - f0.x, x.y - f0.y);
    __half2 l1 = __floats2half2_rn(x.z - f1.x, x.w - f1.y);
    *(uint2*)dh = make_uint2(*(uint32_t*)&h0, *(uint32_t*)&h1);
    *(uint2*)dl = make_uint2(*(uint32_t*)&l0, *(uint32_t*)&l1);
}
__device__ __forceinline__ void store_f16_hi(float4 x, uint32_t* dh) {
    __half2 h0 = __floats2half2_rn(x.x, x.y);
    __half2 h1 = __floats2half2_rn(x.z, x.w);
    *(uint2*)dh = make_uint2(*(uint32_t*)&h0, *(uint32_t*)&h1);
}

__device__ __forceinline__ float ex2f(float x) {
    float r;
    asm("ex2.approx.f32 %0, %1;" : "=f"(r) : "f"(x));
    return r;
}

// ---------------------------------------------------------------------------
// cp.async double-buffered tensor-core GEMM (QKV + proj):
//   C[M,N] = alpha * A[M,K] * B[N,K]^T (+bias)
// MODE 0: plain fp32 epilogue.
// MODE 2 (BATCH3 QKV): z=0 -> write fp16 hi to QHo; z=1 -> fp16 hi/lo to
//   KHo/KLo; z=2 -> fp32 C (value path).
// FMT 0: bf16 splits; FMT 1: fp16 splits. TERMS 3 or 2 (A low dropped).
// ---------------------------------------------------------------------------
template <int NTILE, int BATCH3, int MODE, int FMT, int TERMS>
__global__ __launch_bounds__(256, 2) void mma_gemm(
    const float* __restrict__ A, const float* __restrict__ A1q, const float* __restrict__ A2q,
    int lda, int zdiv, long long sA1, long long sA2,
    const float* __restrict__ Bm, const float* __restrict__ B1q, const float* __restrict__ B2q,
    int ldb, long long sB1, long long sB2,
    float* __restrict__ C, int ldc, long long sC1, long long sC2,
    int K, float alpha, const float* __restrict__ bias,
    __half* QHo, __half* KHo, __half* KLo)
{
    constexpr int WROW  = 20;
    constexpr int ROWS  = 128 + NTILE;
    constexpr int NLOOP = ROWS / 32;
    constexpr int RAWW  = ROWS * 32;
    constexpr int WM    = (NTILE == 128) ? 2 : 4;
    constexpr int MI    = 128 / (WM * 16);
    constexpr int NI    = 4;
    constexpr int AHL   = 128 * WROW;
    constexpr int BOFF  = (TERMS == 3) ? 2 * AHL : AHL;
    constexpr int BHL   = NTILE * WROW;

    extern __shared__ char smem[];
    float*    raw0p = (float*)smem;
    float*    raw1p = (float*)(smem + RAWW * 4);
    uint32_t* bw    = (uint32_t*)(smem + 2 * RAWW * 4);
    const uint32_t raw0a = smem_u32(raw0p);
    const uint32_t raw1a = raw0a + RAWW * 4;
    const uint32_t bwa   = raw0a + 2 * RAWW * 4;

    const int z = blockIdx.z;
    if (BATCH3) {
        A  = (z == 0) ? A  : (z == 1 ? A1q : A2q);
        Bm = (z == 0) ? Bm : (z == 1 ? B1q : B2q);
        C += (long long)z * sC1;
    } else {
        const int z1 = z / zdiv, z2 = z % zdiv;
        A  += (long long)z1 * sA1 + (long long)z2 * sA2;
        Bm += (long long)z1 * sB1 + (long long)z2 * sB2;
        C  += (long long)z1 * sC1 + (long long)z2 * sC2;
    }

    const int m0 = blockIdx.y * 128;
    const int n0 = blockIdx.x * NTILE;

    const int tid  = threadIdx.x;
    const int warp = tid >> 5;
    const int lane = tid & 31;
    const int wm   = warp % WM;
    const int wn   = warp / WM;
    const int g    = lane >> 2;
    const int tg   = lane & 3;

    uint32_t a_addr[2][MI], b_addr[2][2];
    {
        const int lm  = lane & 7;
        const int l8  = (lane >> 3) & 1;
        const int l16 = lane >> 4;
        const int bm  = lane >> 3;
#pragma unroll
        for (int kk2 = 0; kk2 < 2; kk2++) {
#pragma unroll
            for (int mi = 0; mi < MI; mi++) {
                const int row = wm * (MI * 16) + mi * 16 + lm + l8 * 8;
                const int off = kk2 * 8 + l16 * 4;
                a_addr[kk2][mi] = bwa + (uint32_t)(row * WROW + off) * 4;
            }
#pragma unroll
            for (int np = 0; np < 2; np++) {
                const int nrow = wn * 32 + np * 16 + (bm >> 1) * 8 + lm;
                const int koff = kk2 * 8 + (bm & 1) * 4;
                b_addr[kk2][np] = bwa + (uint32_t)(BOFF + nrow * WROW + koff) * 4;
            }
        }
    }

    float acc[MI][NI][4];
#pragma unroll
    for (int mi = 0; mi < MI; mi++)
#pragma unroll
        for (int ni = 0; ni < NI; ni++)
#pragma unroll
            for (int r = 0; r < 4; r++) acc[mi][ni][r] = 0.f;

#pragma unroll
    for (int i = 0; i < NLOOP; i++) {
        const int idx = tid + i * 256;
        const bool isA = idx < 1024;
        const int r = isA ? (idx >> 3) : ((idx - 1024) >> 3);
        const int c = (idx & 7) * 4;
        const float* src = isA ? &A[(long long)(m0 + r) * lda + c]
                               : &Bm[(long long)(n0 + r) * ldb + c];
        CP_ASYNC16(raw0a + idx * 16, src);
    }
    CP_COMMIT();

    const int NIT = K / 32;

    for (int it = 0; it < NIT; it++) {
        const bool more = (it + 1) < NIT;
        const int kbn = (it + 1) * 32;
        if (more) {
            const uint32_t rdst = ((it + 1) & 1) ? raw1a : raw0a;
#pragma unroll
            for (int i = 0; i < NLOOP; i++) {
                const int idx = tid + i * 256;
                const bool isA = idx < 1024;
                const int r = isA ? (idx >> 3) : ((idx - 1024) >> 3);
                const int c = (idx & 7) * 4;
                const float* src = isA ? &A[(long long)(m0 + r) * lda + kbn + c]
                                       : &Bm[(long long)(n0 + r) * ldb + kbn + c];
                CP_ASYNC16(rdst + idx * 16, src);
            }
            CP_COMMIT();
            CP_WAIT1();
        } else {
            CP_WAIT0();
        }

        {
            const float* rbuf = (it & 1) ? raw1p : raw0p;
#pragma unroll
            for (int i = 0; i < NLOOP; i++) {
                const int idx = tid + i * 256;
                const bool isA = idx < 1024;
                const int r = isA ? (idx >> 3) : ((idx - 1024) >> 3);
                const int c = (idx & 7) * 4;
                float4 x = *(const float4*)(rbuf + idx * 4);
                const uint32_t w = r * WROW + (c >> 1);
                if (isA) {
                    uint32_t* dh = bw + w;
                    if (TERMS == 3) {
                        if (FMT == 0) split_store_bf(x, dh, dh + AHL);
                        else          split_store_f16(x, dh, dh + AHL);
                    } else {
                        store_f16_hi(x, dh);
                    }
                } else {
                    uint32_t* dh = bw + BOFF + w;
                    if (FMT == 0) split_store_bf(x, dh, dh + BHL);
                    else          split_store_f16(x, dh, dh + BHL);
                }
            }
        }
        __syncthreads();

        {
#pragma unroll
            for (int kk2 = 0; kk2 < 2; kk2++) {
                uint32_t bh[NI][2], bl[NI][2];
#pragma unroll
                for (int np = 0; np < 2; np++) {
                    ldsm_x4(bh[np * 2][0], bh[np * 2][1], bh[np * 2 + 1][0], bh[np * 2 + 1][1],
                            b_addr[kk2][np]);
                    ldsm_x4(bl[np * 2][0], bl[np * 2][1], bl[np * 2 + 1][0], bl[np * 2 + 1][1],
                            b_addr[kk2][np] + BHL * 4);
                }
#pragma unroll
                for (int mi = 0; mi < MI; mi++) {
                    uint32_t ah[4], al[4];
                    ldsm_x4(ah[0], ah[1], ah[2], ah[3], a_addr[kk2][mi]);
                    if (TERMS == 3)
                        ldsm_x4(al[0], al[1], al[2], al[3], a_addr[kk2][mi] + AHL * 4);
#pragma unroll
                    for (int ni = 0; ni < NI; ni++) {
                        if (FMT == 0) {
                            mma16816bf(acc[mi][ni], ah, bh[ni]);
                            mma16816bf(acc[mi][ni], ah, bl[ni]);
                            if (TERMS == 3) mma16816bf(acc[mi][ni], al, bh[ni]);
                        } else {
                            mma16816h(acc[mi][ni], ah, bh[ni]);
                            mma16816h(acc[mi][ni], ah, bl[ni]);
                            if (TERMS == 3) mma16816h(acc[mi][ni], al, bh[ni]);
                        }
                    }
                }
            }
        }
        if (more) __syncthreads();
    }

    // ---- epilogue ----
#pragma unroll
    for (int mi = 0; mi < MI; mi++) {
        const int r0 = m0 + wm * (MI * 16) + mi * 16 + g;
        const int r1 = r0 + 8;
#pragma unroll
        for (int ni = 0; ni < NI; ni++) {
            const int c = n0 + wn * 32 + ni * 8 + tg * 2;
            if (MODE == 2 && z == 0) {
                *(__half2*)&QHo[(long long)r0 * ldc + c] =
                    __floats2half2_rn(acc[mi][ni][0], acc[mi][ni][1]);
                *(__half2*)&QHo[(long long)r1 * ldc + c] =
                    __floats2half2_rn(acc[mi][ni][2], acc[mi][ni][3]);
            } else if (MODE == 2 && z == 1) {
                __half2 h0 = __floats2half2_rn(acc[mi][ni][0], acc[mi][ni][1]);
                __half2 h1 = __floats2half2_rn(acc[mi][ni][2], acc[mi][ni][3]);
                float2 f0 = __half22float2(h0);
                float2 f1 = __half22float2(h1);
                *(__half2*)&KHo[(long long)r0 * ldc + c] = h0;
                *(__half2*)&KHo[(long long)r1 * ldc + c] = h1;
                *(__half2*)&KLo[(long long)r0 * ldc + c] =
                    __floats2half2_rn(acc[mi][ni][0] - f0.x, acc[mi][ni][1] - f0.y);
                *(__half2*)&KLo[(long long)r1 * ldc + c] =
                    __floats2half2_rn(acc[mi][ni][2] - f1.x, acc[mi][ni][3] - f1.y);
            } else {
                float2 bv = make_float2(0.f, 0.f);
                if (bias) bv = *(const float2*)&bias[c];
                float2 o0, o1;
                o0.x = acc[mi][ni][0] * alpha + bv.x;
                o0.y = acc[mi][ni][1] * alpha + bv.y;
                o1.x = acc[mi][ni][2] * alpha + bv.x;
                o1.y = acc[mi][ni][3] * alpha + bv.y;
                *(float2*)&C[(long long)r0 * ldc + c] = o0;
                *(float2*)&C[(long long)r1 * ldc + c] = o1;
            }
        }
    }
}

// ---------------------------------------------------------------------------
// A-resident logits kernel: per (z, m-tile 128), stage qh once, stream kh/kl
// tiles via cp.async directly into ldmatrix layout (QROW=36 -> conflict-free),
// loop 16 n-tiles: f16 MMA (2-term) -> exp -> fp16 store; rowsums in regs.
// ---------------------------------------------------------------------------
__global__ __launch_bounds__(256, 2) void mma_qk(
    const __half* __restrict__ qh, const __half* __restrict__ kh,
    const __half* __restrict__ kl,
    float* __restrict__ rowsum, __half* __restrict__ EH)
{
    constexpr int QROW = 36;                    // words per row (64 halves + pad)
    constexpr int QOFF = 0;                     // qh: 128*36 = 4608 words
    constexpr int KH0 = 4608, KL0 = 9216;       // K buffer 0 (hi, lo)
    constexpr int KH1 = 13824, KL1 = 18432;     // K buffer 1
    constexpr int KLOFF = 4608;                 // lo - hi distance (words)

    extern __shared__ char smem[];
    const uint32_t sb = smem_u32(smem);

    const int z = blockIdx.y;
    const int b = z / HH, h = z % HH;
    const int m0 = blockIdx.x * 128;

    const __half* qz  = qh + ((long long)b * TT) * EE + h * DD;
    const __half* khz = kh + ((long long)b * TT) * EE + h * DD;
    const __half* klz = kl + ((long long)b * TT) * EE + h * DD;
    __half* EHz = EH + (long long)z * TT * TT;
    float* rowsumz = rowsum + (long long)z * TT;

    const int tid = threadIdx.x, warp = tid >> 5, lane = tid & 31;
    const int wm = warp & 1;     // 2 m-warps (64 rows each)
    const int wn = warp >> 1;    // 4 n-warps (32 cols each)
    const int g = lane >> 2, tg = lane & 3;
    const int lm = lane & 7, l8 = (lane >> 3) & 1, l16 = lane >> 4, bm = lane >> 3;

    // prologue: qh tile + K tile 0, one commit group
#pragma unroll
    for (int i = 0; i < 4; i++) {
        const int idx = tid + i * 256;
        const int r = idx >> 3, ch = idx & 7;
        CP_ASYNC16(sb + (uint32_t)(QOFF + r * QROW + ch * 4) * 4,
                   qz + (long long)(m0 + r) * EE + ch * 8);
    }
#pragma unroll
    for (int i = 0; i < 8; i++) {
        const int idx = tid + i * 256;
        const bool isH = idx < 1024;
        const int j = isH ? idx : idx - 1024;
        const int r = j >> 3, ch = j & 7;
        const __half* src = (isH ? khz : klz) + (long long)r * EE + ch * 8;
        CP_ASYNC16(sb + (uint32_t)((isH ? KH0 : KL0) + r * QROW + ch * 4) * 4, src);
    }
    CP_COMMIT();

    float ps[4][2];
#pragma unroll
    for (int mi = 0; mi < 4; mi++) { ps[mi][0] = 0.f; ps[mi][1] = 0.f; }

    const float A2 = 0.125f * 1.44269504f;

    for (int nt = 0; nt < 16; nt++) {
        const bool more = nt + 1 < 16;
        if (more) {
            const int nb = (nt + 1) * 128;
            const uint32_t khd = ((nt + 1) & 1) ? KH1 : KH0;
            const uint32_t kld = ((nt + 1) & 1) ? KL1 : KL0;
#pragma unroll
            for (int i = 0; i < 8; i++) {
                const int idx = tid + i * 256;
                const bool isH = idx < 1024;
                const int j = isH ? idx : idx - 1024;
                const int r = j >> 3, ch = j & 7;
                const __half* src = (isH ? khz : klz) + (long long)(nb + r) * EE + ch * 8;
                CP_ASYNC16(sb + (uint32_t)((isH ? khd : kld) + r * QROW + ch * 4) * 4, src);
            }
            CP_COMMIT();
            CP_WAIT1();
        } else {
            CP_WAIT0();
        }
        __syncthreads();

        const uint32_t khc = (nt & 1) ? KH1 : KH0;

        float acc[4][4][4];
#pragma unroll
        for (int mi = 0; mi < 4; mi++)
#pragma unroll
            for (int ni = 0; ni < 4; ni++)
#pragma unroll
                for (int r = 0; r < 4; r++) acc[mi][ni][r] = 0.f;

#pragma unroll
        for (int kk = 0; kk < 4; kk++) {
            uint32_t bh[4][2], bl[4][2];
#pragma unroll
            for (int np = 0; np < 2; np++) {
                const uint32_t addr = sb + (uint32_t)(khc +
                    (wn * 32 + np * 16 + (bm >> 1) * 8 + lm) * QROW + kk * 8 + (bm & 1) * 4) * 4;
                ldsm_x4(bh[np * 2][0], bh[np * 2][1], bh[np * 2 + 1][0], bh[np * 2 + 1][1], addr);
                ldsm_x4(bl[np * 2][0], bl[np * 2][1], bl[np * 2 + 1][0], bl[np * 2 + 1][1],
                        addr + KLOFF * 4);
            }
#pragma unroll
            for (int mi = 0; mi < 4; mi++) {
                uint32_t ah[4];
                const uint32_t aaddr = sb + (uint32_t)(QOFF +
                    (wm * 64 + mi * 16 + lm + l8 * 8) * QROW + kk * 8 + l16 * 4) * 4;
                ldsm_x4(ah[0], ah[1], ah[2], ah[3], aaddr);
#pragma unroll
                for (int ni = 0; ni < 4; ni++) {
                    mma16816h(acc[mi][ni], ah, bh[ni]);
                    mma16816h(acc[mi][ni], ah, bl[ni]);
                }
            }
        }

        // exp + fp16 store + rowsum accumulation
#pragma unroll
        for (int mi = 0; mi < 4; mi++) {
            const int r0 = m0 + wm * 64 + mi * 16 + g;
            const int r1 = r0 + 8;
#pragma unroll
            for (int ni = 0; ni < 4; ni++) {
                const int c = nt * 128 + wn * 32 + ni * 8 + tg * 2;
                __half q0 = __float2half_rn(ex2f(acc[mi][ni][0] * A2));
                __half q1 = __float2half_rn(ex2f(acc[mi][ni][1] * A2));
                __half q2 = __float2half_rn(ex2f(acc[mi][ni][2] * A2));
                __half q3 = __float2half_rn(ex2f(acc[mi][ni][3] * A2));
                *(__half2*)&EHz[(long long)r0 * TT + c] = __halves2half2(q0, q1);
                *(__half2*)&EHz[(long long)r1 * TT + c] = __halves2half2(q2, q3);
                ps[mi][0] += __half2float(q0) + __half2float(q1);
                ps[mi][1] += __half2float(q2) + __half2float(q3);
            }
        }
        __syncthreads();
    }

    // final rowsum atomics (one per row per warp)
#pragma unroll
    for (int mi = 0; mi < 4; mi++) {
        float p0 = ps[mi][0], p1 = ps[mi][1];
        p0 += __shfl_xor_sync(0xffffffffu, p0, 1);
        p0 += __shfl_xor_sync(0xffffffffu, p0, 2);
        p1 += __shfl_xor_sync(0xffffffffu, p1, 1);
        p1 += __shfl_xor_sync(0xffffffffu, p1, 2);
        if (tg == 0) {
            const int r0 = m0 + wm * 64 + mi * 16 + g;
            atomicAdd(&rowsumz[r0], p0);
            atomicAdd(&rowsumz[r0 + 8], p1);
        }
    }
}

// ---------------------------------------------------------------------------
// AV kernel: mh[b,m,h,:] = inv_row * (exph[m,:] @ V^T)   (unchanged from R14)
// ---------------------------------------------------------------------------
__global__ __launch_bounds__(256, 2) void mma_av(
    const __half* __restrict__ exph, const float* __restrict__ Vt,
    const float* __restrict__ invr,
    float* __restrict__ attn, float* __restrict__ mh)
{
    constexpr int WROW = 20;
    constexpr int AW0 = 0, AW1 = 2560;
    constexpr int BR0 = 5120, BR1 = 7168;
    constexpr int BVH = 9216, BVL = 10496;
    constexpr int MI = 2, NI = 4;

    extern __shared__ char smem[];
    uint32_t* sw = (uint32_t*)smem;
    const uint32_t sb = smem_u32(smem);

    const int z = blockIdx.y;
    const int b = z / HH, h = z % HH;
    const int m0 = blockIdx.x * 128;

    const __half* EHz = exph + (long long)z * TT * TT;
    const float*  Vz  = Vt + (long long)z * DD * TT;
    float* AWz = attn + (long long)z * TT * TT;
    float* mhz = mh + (long long)b * TT * EE + h * DD;
    const float* invz = invr + (long long)z * TT;

    const int tid  = threadIdx.x;
    const int warp = tid >> 5;
    const int lane = tid & 31;
    const int wm   = warp & 3;
    const int wn   = warp >> 2;
    const int g    = lane >> 2;
    const int tg   = lane & 3;

    const float inv0s = invz[m0 + (tid >> 2)];
    const float inv1s = invz[m0 + (tid >> 2) + 64];

    uint32_t a_off[2][MI];
    uint32_t b_addr[2][2];
    {
        const int lm  = lane & 7;
        const int l8  = (lane >> 3) & 1;
        const int l16 = lane >> 4;
        const int bm  = lane >> 3;
#pragma unroll
        for (int kk2 = 0; kk2 < 2; kk2++) {
#pragma unroll
            for (int mi = 0; mi < MI; mi++) {
                const int row = wm * 32 + mi * 16 + lm + l8 * 8;
                a_off[kk2][mi] = (uint32_t)(row * WROW + kk2 * 8 + l16 * 4) * 4;
            }
#pragma unroll
            for (int np = 0; np < 2; np++) {
                const int nrow = wn * 32 + np * 16 + (bm >> 1) * 8 + lm;
                const int koff = kk2 * 8 + (bm & 1) * 4;
                b_addr[kk2][np] = sb + (uint32_t)(BVH + nrow * WROW + koff) * 4;
            }
        }
    }

    float acc[MI][NI][4];
#pragma unroll
    for (int mi = 0; mi < MI; mi++)
#pragma unroll
        for (int ni = 0; ni < NI; ni++)
#pragma unroll
            for (int r = 0; r < 4; r++) acc[mi][ni][r] = 0.f;

#pragma unroll
    for (int i = 0; i < 4; i++) {
        const int idx = tid + i * 256;
        if (idx < 512) {
            const int r = idx >> 2, ch = idx & 3;
            CP_ASYNC16(sb + AW0 * 4 + r * 80 + ch * 16, EHz + (long long)(m0 + r) * TT + ch * 8);
        } else {
            const int j = idx - 512;
            const int r = j >> 3, c4 = (j & 7) * 4;
            CP_ASYNC16(sb + BR0 * 4 + j * 16, Vz + (long long)r * TT + c4);
        }
    }
    CP_COMMIT();

    const int NIT = TT / 32;

    for (int it = 0; it < NIT; it++) {
        const bool more = (it + 1) < NIT;
        const int kbn = (it + 1) * 32;
        if (more) {
            const uint32_t adst = sb + (((it + 1) & 1) ? AW1 : AW0) * 4;
            const uint32_t bdst = sb + (((it + 1) & 1) ? BR1 : BR0) * 4;
#pragma unroll
            for (int i = 0; i < 4; i++) {
                const int idx = tid + i * 256;
                if (idx < 512) {
                    const int r = idx >> 2, ch = idx & 3;
                    CP_ASYNC16(adst + r * 80 + ch * 16, EHz + (long long)(m0 + r) * TT + kbn + ch * 8);
                } else {
                    const int j = idx - 512;
                    const int r = j >> 3, c4 = (j & 7) * 4;
                    CP_ASYNC16(bdst + j * 16, Vz + (long long)r * TT + kbn + c4);
                }
            }
            CP_COMMIT();
            CP_WAIT1();
        } else {
            CP_WAIT0();
        }

        {
            const uint32_t acur = (it & 1) ? AW1 : AW0;
            const uint32_t bcur = (it & 1) ? BR1 : BR0;
            const int kb = it * 32;
#pragma unroll
            for (int i = 0; i < 2; i++) {
                const int idx = tid + i * 256;
                const int r = idx >> 2, ch = idx & 3;
                uint4 hv = *(const uint4*)(sw + acur + r * WROW + ch * 4);
                const __half2* h2 = (const __half2*)&hv;
                const float inv = i ? inv1s : inv0s;
                float2 f0 = __half22float2(h2[0]);
                float2 f1 = __half22float2(h2[1]);
                float2 f2 = __half22float2(h2[2]);
                float2 f3 = __half22float2(h2[3]);
                float* dst = &AWz[(long long)(m0 + r) * TT + kb + ch * 8];
                *(float4*)dst       = make_float4(f0.x * inv, f0.y * inv, f1.x * inv, f1.y * inv);
                *(float4*)(dst + 4) = make_float4(f2.x * inv, f2.y * inv, f3.x * inv, f3.y * inv);
            }
#pragma unroll
            for (int i = 0; i < 2; i++) {
                const int j = tid + i * 256;
                const int r = j >> 3, c4 = (j & 7) * 4;
                float4 x = *(const float4*)(sw + bcur + j * 4);
                uint32_t* dh = sw + BVH + r * WROW + (c4 >> 1);
                split_store_f16(x, dh, dh + (BVL - BVH));
            }
        }
        __syncthreads();

        {
            const uint32_t abase = sb + ((it & 1) ? AW1 : AW0) * 4;
#pragma unroll
            for (int kk2 = 0; kk2 < 2; kk2++) {
                uint32_t bh[NI][2], bl[NI][2];
#pragma unroll
                for (int np = 0; np < 2; np++) {
                    ldsm_x4(bh[np * 2][0], bh[np * 2][1], bh[np * 2 + 1][0], bh[np * 2 + 1][1],
                            b_addr[kk2][np]);
                    ldsm_x4(bl[np * 2][0], bl[np * 2][1], bl[np * 2 + 1][0], bl[np * 2 + 1][1],
                            b_addr[kk2][np] + (BVL - BVH) * 4);
                }
#pragma unroll
                for (int mi = 0; mi < MI; mi++) {
                    uint32_t ah[4];
                    ldsm_x4(ah[0], ah[1], ah[2], ah[3], abase + a_off[kk2][mi]);
#pragma unroll
                    for (int ni = 0; ni < NI; ni++) {
                        mma16816h(acc[mi][ni], ah, bh[ni]);
                        mma16816h(acc[mi][ni], ah, bl[ni]);
                    }
                }
            }
        }
        if (more) __syncthreads();
    }

#pragma unroll
    for (int mi = 0; mi < MI; mi++) {
        const int r0 = m0 + wm * 32 + mi * 16 + g;
        const int r1 = r0 + 8;
        const float i0 = invz[r0];
        const float i1 = invz[r1];
#pragma unroll
        for (int ni = 0; ni < NI; ni++) {
            const int c = wn * 32 + ni * 8 + tg * 2;
            *(float2*)&mhz[(long long)r0 * EE + c] =
                make_float2(acc[mi][ni][0] * i0, acc[mi][ni][1] * i0);
            *(float2*)&mhz[(long long)r1 * EE + c] =
                make_float2(acc[mi][ni][2] * i1, acc[mi][ni][3] * i1);
        }
    }
}

// ---------------------------------------------------------------------------
// rowsum helpers
// ---------------------------------------------------------------------------
__global__ void zero_rowsum(float* rs) {
    rs[blockIdx.x * 256 + threadIdx.x] = 0.f;
}
__global__ void invert_rowsum(float* rs) {
    const int i = blockIdx.x * 256 + threadIdx.x;
    rs[i] = 1.f / rs[i];
}

// ---------------------------------------------------------------------------
// Transposes
// ---------------------------------------------------------------------------
__global__ __launch_bounds__(256) void transpose_v(const float* __restrict__ v,
                                                   float* __restrict__ vt)
{
    __shared__ float tile[32][33];
    const int z = blockIdx.z;
    const int b = z / HH, h = z % HH;
    const int m0 = blockIdx.x * 32;
    const int d0 = blockIdx.y * 32;
    const int tx = threadIdx.x & 31;
    const int ty0 = threadIdx.x >> 5;
#pragma unroll
    for (int ty = ty0; ty < 32; ty += 8)
        tile[ty][tx] = v[((long long)b * TT + m0 + ty) * EE + h * DD + d0 + tx];
    __syncthreads();
#pragma unroll
    for (int ty = ty0; ty < 32; ty += 8)
        vt[(((long long)z) * DD + d0 + ty) * TT + m0 + tx] = tile[tx][ty];
}

__global__ __launch_bounds__(256) void transpose_pk(const float* __restrict__ pk,
                                                    float* __restrict__ pkt)
{
    __shared__ float tile[32][33];
    const int k0 = blockIdx.x * 32;
    const int o0 = blockIdx.y * 32;
    const int tx = threadIdx.x & 31;
    const int ty0 = threadIdx.x >> 5;
#pragma unroll
    for (int ty = ty0; ty < 32; ty += 8)
        tile[ty][tx] = pk[(long long)(k0 + ty) * OO + o0 + tx];
    __syncthreads();
#pragma unroll
    for (int ty = ty0; ty < 32; ty += 8)
        pkt[(long long)(o0 + ty) * EE + k0 + tx] = tile[tx][ty];
}

// ---------------------------------------------------------------------------
// Launch
// ---------------------------------------------------------------------------
extern "C" void kernel_launch(void* const* d_in, const int* in_sizes, int n_in,
                              void* d_out, int out_size)
{
    const float* query = (const float*)d_in[0];
    const float* key   = (const float*)d_in[1];
    const float* value = (const float*)d_in[2];
    const float* Wq    = (const float*)d_in[3];
    const float* Wk    = (const float*)d_in[4];
    const float* Wv    = (const float*)d_in[5];
    const float* pk    = (const float*)d_in[6];
    const float* pb    = (const float*)d_in[7];

    float *qkvp, *mhp, *vtp, *pktp, *rsp, *outs, *attns;
    __half *ehp, *qhp, *khp, *klp;
    cudaGetSymbolAddress((void**)&qkvp,  g_qkv);
    cudaGetSymbolAddress((void**)&mhp,   g_mh);
    cudaGetSymbolAddress((void**)&vtp,   g_vt);
    cudaGetSymbolAddress((void**)&pktp,  g_pkt);
    cudaGetSymbolAddress((void**)&rsp,   g_rowsum);
    cudaGetSymbolAddress((void**)&ehp,   g_exph);
    cudaGetSymbolAddress((void**)&qhp,   g_qh);
    cudaGetSymbolAddress((void**)&khp,   g_kh);
    cudaGetSymbolAddress((void**)&klp,   g_kl);
    cudaGetSymbolAddress((void**)&outs,  g_out_scratch);
    cudaGetSymbolAddress((void**)&attns, g_attn_scratch);

    const long long qkvN = (long long)BB * TT * EE;
    float* vp = qkvp + 2 * qkvN;

    const long long outN  = (long long)BB * TT * OO;
    const long long attnN = (long long)BB * HH * TT * TT;

    float* outP  = (float*)d_out;
    float* attnP;
    if ((long long)out_size >= outN + attnN) {
        attnP = outP + outN;
    } else if ((long long)out_size == attnN) {
        attnP = (float*)d_out;
        outP  = outs;
    } else {
        attnP = attns;
    }

    constexpr int SMEM128 = (2 * 256 * 32 + 256 * 40) * 4;  // 106496
    constexpr int SMEMQK  = 23040 * 4;                      // 92160
    constexpr int SMEMAV  = 11776 * 4;                      // 47104
    cudaFuncSetAttribute((const void*)mma_gemm<128, 1, 2, 0, 3>,
                         cudaFuncAttributeMaxDynamicSharedMemorySize, SMEM128);
    cudaFuncSetAttribute((const void*)mma_gemm<128, 0, 0, 1, 2>,
                         cudaFuncAttributeMaxDynamicSharedMemorySize, SMEM128);
    cudaFuncSetAttribute((const void*)mma_qk,
                         cudaFuncAttributeMaxDynamicSharedMemorySize, SMEMQK);
    cudaFuncSetAttribute((const void*)mma_av,
                         cudaFuncAttributeMaxDynamicSharedMemorySize, SMEMAV);

    // 0) zero row sums (graph-replay safe)
    zero_rowsum<<<(BB * HH * TT) / 256, 256>>>(rsp);

    // 1) Q/K/V projections (bf16 3-term, exact), epilogue writes qh / kh,kl / v
    {
        dim3 grid(EE / 128, (BB * TT) / 128, 3);
        mma_gemm<128, 1, 2, 0, 3><<<grid, 256, SMEM128>>>(
            query, key, value, EE, 1, 0, 0,
            Wq, Wk, Wv, EE, 0, 0,
            qkvp, EE, qkvN, 0,
            EE, 1.f, nullptr, qhp, khp, klp);
    }

    // transposes: V -> [b][h][d][m], pk -> [o][k]
    {
        dim3 gv(TT / 32, DD / 32, BB * HH);
        transpose_v<<<gv, 256>>>(vp, vtp);
        dim3 gp(EE / 32, OO / 32, 1);
        transpose_pk<<<gp, 256>>>(pk, pktp);
    }

    // 2) exph = fp16(exp(0.125 * q @ k^T)) — A-resident, zero-convert staging
    {
        dim3 grid(TT / 128, BB * HH);
        mma_qk<<<grid, 256, SMEMQK>>>(qhp, khp, klp, rsp, ehp);
    }

    // 3) invert row sums
    invert_rowsum<<<(BB * HH * TT) / 256, 256>>>(rsp);

    // 4) mh = inv * (exph @ vT^T); writes normalized fp32 attn once
    {
        dim3 grid(TT / 128, BB * HH);
        mma_av<<<grid, 256, SMEMAV>>>(ehp, vtp, rsp, attnP, mhp);
    }

    // 5) out = mh @ pkT^T + bias (fp16 2-term)
    {
        dim3 grid(OO / 128, (BB * TT) / 128, 1);
        mma_gemm<128, 0, 0, 1, 2><<<grid, 256, SMEM128>>>(
            mhp, nullptr, nullptr, EE, 1, 0, 0,
            pktp, nullptr, nullptr, EE, 0, 0,
            outP, OO, 0, 0, EE, 1.f, pb, nullptr, nullptr, nullptr);
    }
}

// round 16
// speedup vs baseline: 1.3944x; 1.0857x over previous
#include <cuda_runtime.h>
#include <cuda_bf16.h>
#include <cuda_fp16.h>
#include <cstdint>

// Problem dims
#define BB 2
#define TT 2048
#define HH 16
#define DD 64
#define EE 1024   // HH*DD
#define OO 1024

// Scratch (device globals)
__device__ float g_v[(size_t)BB * TT * EE];           // value (fp32, from QKV z=2)
__device__ __half g_mhh[(size_t)BB * TT * EE];        // mh fp16
__device__ __half g_vth[(size_t)BB * TT * EE];        // V^T fp16 hi: [z][d][m]
__device__ __half g_vtl[(size_t)BB * TT * EE];        // V^T fp16 lo
__device__ float g_pkt[(size_t)EE * OO];              // proj kernel transposed: [o][k]
__device__ float g_rowsum[(size_t)BB * HH * TT];      // exp row sums -> inverses
__device__ __half g_exph[(size_t)BB * HH * TT * TT];  // fp16 exp(logits)
__device__ __half g_qh[(size_t)BB * TT * EE];         // q fp16 hi
__device__ __half g_kh[(size_t)BB * TT * EE];         // k fp16 hi
__device__ __half g_kl[(size_t)BB * TT * EE];         // k fp16 lo
__device__ float g_out_scratch[(size_t)BB * TT * OO];
__device__ float g_attn_scratch[(size_t)BB * HH * TT * TT];

// ---------------------------------------------------------------------------
// PTX helpers (baseline features only)
// ---------------------------------------------------------------------------
__device__ __forceinline__ uint32_t smem_u32(const void* p) {
    uint32_t a;
    asm("{ .reg .u64 t; cvta.to.shared.u64 t, %1; cvt.u32.u64 %0, t; }" : "=r"(a) : "l"(p));
    return a;
}
#define CP_ASYNC16(dst_u32, src_ptr) \
    asm volatile("cp.async.cg.shared.global [%0], [%1], 16;" :: "r"(dst_u32), "l"(src_ptr))
#define CP_COMMIT() asm volatile("cp.async.commit_group;" ::: "memory")
#define CP_WAIT1()  asm volatile("cp.async.wait_group 1;" ::: "memory")
#define CP_WAIT0()  asm volatile("cp.async.wait_group 0;" ::: "memory")

__device__ __forceinline__ void mma16816h(float* c, const uint32_t* a, const uint32_t* b) {
    asm volatile(
        "mma.sync.aligned.m16n8k16.row.col.f32.f16.f16.f32 "
        "{%0,%1,%2,%3}, {%4,%5,%6,%7}, {%8,%9}, {%0,%1,%2,%3};"
        : "+f"(c[0]), "+f"(c[1]), "+f"(c[2]), "+f"(c[3])
        : "r"(a[0]), "r"(a[1]), "r"(a[2]), "r"(a[3]), "r"(b[0]), "r"(b[1]));
}

__device__ __forceinline__ void ldsm_x4(uint32_t& r0, uint32_t& r1, uint32_t& r2, uint32_t& r3,
                                        uint32_t addr) {
    asm volatile("ldmatrix.sync.aligned.m8n8.x4.shared.b16 {%0,%1,%2,%3}, [%4];"
                 : "=r"(r0), "=r"(r1), "=r"(r2), "=r"(r3) : "r"(addr));
}

__device__ __forceinline__ void split_store_f16(float4 x, uint32_t* dh, uint32_t* dl) {
    __half2 h0 = __floats2half2_rn(x.x, x.y);
    __half2 h1 = __floats2half2_rn(x.z, x.w);
    float2 f0 = __half22float2(h0);
    float2 f1 = __half22float2(h1);
    __half2 l0 = __floats2half2_rn(x.x - f0.x, x.y - f0.y);
    __half2 l1 = __floats2half2_rn(x.z - f1.x, x.w - f1.y);
    *(uint2*)dh = make_uint2(*(uint32_t*)&h0, *(uint32_t*)&h1);
    *(uint2*)dl = make_uint2(*(uint32_t*)&l0, *(uint32_t*)&l1);
}
__device__ __forceinline__ void store_f16_hi(float4 x, uint32_t* dh) {
    __half2 h0 = __floats2half2_rn(x.x, x.y);
    __half2 h1 = __floats2half2_rn(x.z, x.w);
    *(uint2*)dh = make_uint2(*(uint32_t*)&h0, *(uint32_t*)&h1);
}

__device__ __forceinline__ float ex2f(float x) {
    float r;
    asm("ex2.approx.f32 %0, %1;" : "=f"(r) : "f"(x));
    return r;
}

// ---------------------------------------------------------------------------
// QKV GEMM: C = A @ W^T, fp16 2-term (Ah*Bh + Ah*Bl).
// blockIdx.z: 0 -> qh (fp16 hi), 1 -> kh/kl (fp16 hi+lo), 2 -> v (fp32).
// ---------------------------------------------------------------------------
__global__ __launch_bounds__(256, 2) void mma_qkv(
    const float* __restrict__ Aq, const float* __restrict__ Ak, const float* __restrict__ Av,
    const float* __restrict__ Wq, const float* __restrict__ Wk, const float* __restrict__ Wv,
    __half* __restrict__ QHo, __half* __restrict__ KHo, __half* __restrict__ KLo,
    float* __restrict__ Vo)
{
    constexpr int WROW = 20;
    constexpr int ROWS = 256;
    constexpr int NLOOP = 8;
    constexpr int RAWW = ROWS * 32;
    constexpr int AHL = 128 * WROW;      // A hi only
    constexpr int BOFF = AHL;            // B hi
    constexpr int BHL = 128 * WROW;

    extern __shared__ char smem[];
    float*    raw0p = (float*)smem;
    float*    raw1p = (float*)(smem + RAWW * 4);
    uint32_t* bw    = (uint32_t*)(smem + 2 * RAWW * 4);
    const uint32_t raw0a = smem_u32(raw0p);
    const uint32_t raw1a = raw0a + RAWW * 4;
    const uint32_t bwa   = raw0a + 2 * RAWW * 4;

    const int z = blockIdx.z;
    const float* A  = (z == 0) ? Aq : (z == 1 ? Ak : Av);
    const float* Bm = (z == 0) ? Wq : (z == 1 ? Wk : Wv);

    const int m0 = blockIdx.y * 128;
    const int n0 = blockIdx.x * 128;

    const int tid = threadIdx.x, warp = tid >> 5, lane = tid & 31;
    const int wm = warp & 1, wn = warp >> 1;
    const int g = lane >> 2, tg = lane & 3;

    uint32_t a_addr[2][4], b_addr[2][2];
    {
        const int lm = lane & 7, l8 = (lane >> 3) & 1, l16 = lane >> 4, bm = lane >> 3;
#pragma unroll
        for (int kk2 = 0; kk2 < 2; kk2++) {
#pragma unroll
            for (int mi = 0; mi < 4; mi++)
                a_addr[kk2][mi] = bwa + (uint32_t)((wm * 64 + mi * 16 + lm + l8 * 8) * WROW
                                                   + kk2 * 8 + l16 * 4) * 4;
#pragma unroll
            for (int np = 0; np < 2; np++)
                b_addr[kk2][np] = bwa + (uint32_t)(BOFF +
                    (wn * 32 + np * 16 + (bm >> 1) * 8 + lm) * WROW + kk2 * 8 + (bm & 1) * 4) * 4;
        }
    }

    float acc[4][4][4];
#pragma unroll
    for (int mi = 0; mi < 4; mi++)
#pragma unroll
        for (int ni = 0; ni < 4; ni++)
#pragma unroll
            for (int r = 0; r < 4; r++) acc[mi][ni][r] = 0.f;

#pragma unroll
    for (int i = 0; i < NLOOP; i++) {
        const int idx = tid + i * 256;
        const bool isA = idx < 1024;
        const int r = isA ? (idx >> 3) : ((idx - 1024) >> 3);
        const int c = (idx & 7) * 4;
        const float* src = isA ? &A[(long long)(m0 + r) * EE + c]
                               : &Bm[(long long)(n0 + r) * EE + c];
        CP_ASYNC16(raw0a + idx * 16, src);
    }
    CP_COMMIT();

    for (int it = 0; it < 32; it++) {
        const bool more = it + 1 < 32;
        const int kbn = (it + 1) * 32;
        if (more) {
            const uint32_t rdst = ((it + 1) & 1) ? raw1a : raw0a;
#pragma unroll
            for (int i = 0; i < NLOOP; i++) {
                const int idx = tid + i * 256;
                const bool isA = idx < 1024;
                const int r = isA ? (idx >> 3) : ((idx - 1024) >> 3);
                const int c = (idx & 7) * 4;
                const float* src = isA ? &A[(long long)(m0 + r) * EE + kbn + c]
                                       : &Bm[(long long)(n0 + r) * EE + kbn + c];
                CP_ASYNC16(rdst + idx * 16, src);
            }
            CP_COMMIT();
            CP_WAIT1();
        } else {
            CP_WAIT0();
        }

        {
            const float* rbuf = (it & 1) ? raw1p : raw0p;
#pragma unroll
            for (int i = 0; i < NLOOP; i++) {
                const int idx = tid + i * 256;
                const bool isA = idx < 1024;
                const int r = isA ? (idx >> 3) : ((idx - 1024) >> 3);
                const int c = (idx & 7) * 4;
                float4 x = *(const float4*)(rbuf + idx * 4);
                const uint32_t w = r * WROW + (c >> 1);
                if (isA) store_f16_hi(x, bw + w);
                else     split_store_f16(x, bw + BOFF + w, bw + BOFF + w + BHL);
            }
        }
        __syncthreads();

#pragma unroll
        for (int kk2 = 0; kk2 < 2; kk2++) {
            uint32_t bh[4][2], bl[4][2];
#pragma unroll
            for (int np = 0; np < 2; np++) {
                ldsm_x4(bh[np * 2][0], bh[np * 2][1], bh[np * 2 + 1][0], bh[np * 2 + 1][1],
                        b_addr[kk2][np]);
                ldsm_x4(bl[np * 2][0], bl[np * 2][1], bl[np * 2 + 1][0], bl[np * 2 + 1][1],
                        b_addr[kk2][np] + BHL * 4);
            }
#pragma unroll
            for (int mi = 0; mi < 4; mi++) {
                uint32_t ah[4];
                ldsm_x4(ah[0], ah[1], ah[2], ah[3], a_addr[kk2][mi]);
#pragma unroll
                for (int ni = 0; ni < 4; ni++) {
                    mma16816h(acc[mi][ni], ah, bh[ni]);
                    mma16816h(acc[mi][ni], ah, bl[ni]);
                }
            }
        }
        if (more) __syncthreads();
    }

    // epilogue
#pragma unroll
    for (int mi = 0; mi < 4; mi++) {
        const int r0 = m0 + wm * 64 + mi * 16 + g;
        const int r1 = r0 + 8;
#pragma unroll
        for (int ni = 0; ni < 4; ni++) {
            const int c = n0 + wn * 32 + ni * 8 + tg * 2;
            if (z == 0) {
                *(__half2*)&QHo[(long long)r0 * EE + c] =
                    __floats2half2_rn(acc[mi][ni][0], acc[mi][ni][1]);
                *(__half2*)&QHo[(long long)r1 * EE + c] =
                    __floats2half2_rn(acc[mi][ni][2], acc[mi][ni][3]);
            } else if (z == 1) {
                __half2 h0 = __floats2half2_rn(acc[mi][ni][0], acc[mi][ni][1]);
                __half2 h1 = __floats2half2_rn(acc[mi][ni][2], acc[mi][ni][3]);
                float2 f0 = __half22float2(h0);
                float2 f1 = __half22float2(h1);
                *(__half2*)&KHo[(long long)r0 * EE + c] = h0;
                *(__half2*)&KHo[(long long)r1 * EE + c] = h1;
                *(__half2*)&KLo[(long long)r0 * EE + c] =
                    __floats2half2_rn(acc[mi][ni][0] - f0.x, acc[mi][ni][1] - f0.y);
                *(__half2*)&KLo[(long long)r1 * EE + c] =
                    __floats2half2_rn(acc[mi][ni][2] - f1.x, acc[mi][ni][3] - f1.y);
            } else {
                *(float2*)&Vo[(long long)r0 * EE + c] = make_float2(acc[mi][ni][0], acc[mi][ni][1]);
                *(float2*)&Vo[(long long)r1 * EE + c] = make_float2(acc[mi][ni][2], acc[mi][ni][3]);
            }
        }
    }
}

// ---------------------------------------------------------------------------
// A-resident logits kernel (unchanged from R15)
// ---------------------------------------------------------------------------
__global__ __launch_bounds__(256, 2) void mma_qk(
    const __half* __restrict__ qh, const __half* __restrict__ kh,
    const __half* __restrict__ kl,
    float* __restrict__ rowsum, __half* __restrict__ EH)
{
    constexpr int QROW = 36;
    constexpr int QOFF = 0;
    constexpr int KH0 = 4608, KL0 = 9216;
    constexpr int KH1 = 13824, KL1 = 18432;
    constexpr int KLOFF = 4608;

    extern __shared__ char smem[];
    const uint32_t sb = smem_u32(smem);

    const int z = blockIdx.y;
    const int b = z / HH, h = z % HH;
    const int m0 = blockIdx.x * 128;

    const __half* qz  = qh + ((long long)b * TT) * EE + h * DD;
    const __half* khz = kh + ((long long)b * TT) * EE + h * DD;
    const __half* klz = kl + ((long long)b * TT) * EE + h * DD;
    __half* EHz = EH + (long long)z * TT * TT;
    float* rowsumz = rowsum + (long long)z * TT;

    const int tid = threadIdx.x, warp = tid >> 5, lane = tid & 31;
    const int wm = warp & 1;
    const int wn = warp >> 1;
    const int g = lane >> 2, tg = lane & 3;
    const int lm = lane & 7, l8 = (lane >> 3) & 1, l16 = lane >> 4, bm = lane >> 3;

#pragma unroll
    for (int i = 0; i < 4; i++) {
        const int idx = tid + i * 256;
        const int r = idx >> 3, ch = idx & 7;
        CP_ASYNC16(sb + (uint32_t)(QOFF + r * QROW + ch * 4) * 4,
                   qz + (long long)(m0 + r) * EE + ch * 8);
    }
#pragma unroll
    for (int i = 0; i < 8; i++) {
        const int idx = tid + i * 256;
        const bool isH = idx < 1024;
        const int j = isH ? idx : idx - 1024;
        const int r = j >> 3, ch = j & 7;
        const __half* src = (isH ? khz : klz) + (long long)r * EE + ch * 8;
        CP_ASYNC16(sb + (uint32_t)((isH ? KH0 : KL0) + r * QROW + ch * 4) * 4, src);
    }
    CP_COMMIT();

    float ps[4][2];
#pragma unroll
    for (int mi = 0; mi < 4; mi++) { ps[mi][0] = 0.f; ps[mi][1] = 0.f; }

    const float A2 = 0.125f * 1.44269504f;

    for (int nt = 0; nt < 16; nt++) {
        const bool more = nt + 1 < 16;
        if (more) {
            const int nb = (nt + 1) * 128;
            const uint32_t khd = ((nt + 1) & 1) ? KH1 : KH0;
            const uint32_t kld = ((nt + 1) & 1) ? KL1 : KL0;
#pragma unroll
            for (int i = 0; i < 8; i++) {
                const int idx = tid + i * 256;
                const bool isH = idx < 1024;
                const int j = isH ? idx : idx - 1024;
                const int r = j >> 3, ch = j & 7;
                const __half* src = (isH ? khz : klz) + (long long)(nb + r) * EE + ch * 8;
                CP_ASYNC16(sb + (uint32_t)((isH ? khd : kld) + r * QROW + ch * 4) * 4, src);
            }
            CP_COMMIT();
            CP_WAIT1();
        } else {
            CP_WAIT0();
        }
        __syncthreads();

        const uint32_t khc = (nt & 1) ? KH1 : KH0;

        float acc[4][4][4];
#pragma unroll
        for (int mi = 0; mi < 4; mi++)
#pragma unroll
            for (int ni = 0; ni < 4; ni++)
#pragma unroll
                for (int r = 0; r < 4; r++) acc[mi][ni][r] = 0.f;

#pragma unroll
        for (int kk = 0; kk < 4; kk++) {
            uint32_t bh[4][2], bl[4][2];
#pragma unroll
            for (int np = 0; np < 2; np++) {
                const uint32_t addr = sb + (uint32_t)(khc +
                    (wn * 32 + np * 16 + (bm >> 1) * 8 + lm) * QROW + kk * 8 + (bm & 1) * 4) * 4;
                ldsm_x4(bh[np * 2][0], bh[np * 2][1], bh[np * 2 + 1][0], bh[np * 2 + 1][1], addr);
                ldsm_x4(bl[np * 2][0], bl[np * 2][1], bl[np * 2 + 1][0], bl[np * 2 + 1][1],
                        addr + KLOFF * 4);
            }
#pragma unroll
            for (int mi = 0; mi < 4; mi++) {
                uint32_t ah[4];
                const uint32_t aaddr = sb + (uint32_t)(QOFF +
                    (wm * 64 + mi * 16 + lm + l8 * 8) * QROW + kk * 8 + l16 * 4) * 4;
                ldsm_x4(ah[0], ah[1], ah[2], ah[3], aaddr);
#pragma unroll
                for (int ni = 0; ni < 4; ni++) {
                    mma16816h(acc[mi][ni], ah, bh[ni]);
                    mma16816h(acc[mi][ni], ah, bl[ni]);
                }
            }
        }

#pragma unroll
        for (int mi = 0; mi < 4; mi++) {
            const int r0 = m0 + wm * 64 + mi * 16 + g;
            const int r1 = r0 + 8;
#pragma unroll
            for (int ni = 0; ni < 4; ni++) {
                const int c = nt * 128 + wn * 32 + ni * 8 + tg * 2;
                __half q0 = __float2half_rn(ex2f(acc[mi][ni][0] * A2));
                __half q1 = __float2half_rn(ex2f(acc[mi][ni][1] * A2));
                __half q2 = __float2half_rn(ex2f(acc[mi][ni][2] * A2));
                __half q3 = __float2half_rn(ex2f(acc[mi][ni][3] * A2));
                *(__half2*)&EHz[(long long)r0 * TT + c] = __halves2half2(q0, q1);
                *(__half2*)&EHz[(long long)r1 * TT + c] = __halves2half2(q2, q3);
                ps[mi][0] += __half2float(q0) + __half2float(q1);
                ps[mi][1] += __half2float(q2) + __half2float(q3);
            }
        }
        __syncthreads();
    }

#pragma unroll
    for (int mi = 0; mi < 4; mi++) {
        float p0 = ps[mi][0], p1 = ps[mi][1];
        p0 += __shfl_xor_sync(0xffffffffu, p0, 1);
        p0 += __shfl_xor_sync(0xffffffffu, p0, 2);
        p1 += __shfl_xor_sync(0xffffffffu, p1, 1);
        p1 += __shfl_xor_sync(0xffffffffu, p1, 2);
        if (tg == 0) {
            const int r0 = m0 + wm * 64 + mi * 16 + g;
            atomicAdd(&rowsumz[r0], p0);
            atomicAdd(&rowsumz[r0 + 8], p1);
        }
    }
}

// ---------------------------------------------------------------------------
// AV kernel v3: A (exph) and B (vth/vtl) both fp16 direct-streamed.
// Convert phase = normalized attn writeback only. mh written as fp16.
// ---------------------------------------------------------------------------
__global__ __launch_bounds__(256, 2) void mma_av(
    const __half* __restrict__ exph,
    const __half* __restrict__ vth, const __half* __restrict__ vtl,
    const float* __restrict__ invr,
    float* __restrict__ attn, __half* __restrict__ mhh)
{
    constexpr int WROW = 20;
    constexpr int AW0 = 0, AW1 = 2560;
    constexpr int VH0 = 5120, VH1 = 6400;
    constexpr int VL0 = 7680, VL1 = 8960;   // total 10240 words
    constexpr int MI = 2, NI = 4;

    extern __shared__ char smem[];
    uint32_t* sw = (uint32_t*)smem;
    const uint32_t sb = smem_u32(smem);

    const int z = blockIdx.y;
    const int b = z / HH, h = z % HH;
    const int m0 = blockIdx.x * 128;

    const __half* EHz = exph + (long long)z * TT * TT;
    const __half* VHz = vth + (long long)z * DD * TT;
    const __half* VLz = vtl + (long long)z * DD * TT;
    float* AWz = attn + (long long)z * TT * TT;
    __half* mhz = mhh + (long long)b * TT * EE + h * DD;
    const float* invz = invr + (long long)z * TT;

    const int tid = threadIdx.x, warp = tid >> 5, lane = tid & 31;
    const int wm = warp & 3, wn = warp >> 2;
    const int g = lane >> 2, tg = lane & 3;

    const float inv0s = invz[m0 + (tid >> 2)];
    const float inv1s = invz[m0 + (tid >> 2) + 64];

    uint32_t a_off[2][MI], b_off[2][2];
    {
        const int lm = lane & 7, l8 = (lane >> 3) & 1, l16 = lane >> 4, bm = lane >> 3;
#pragma unroll
        for (int kk2 = 0; kk2 < 2; kk2++) {
#pragma unroll
            for (int mi = 0; mi < MI; mi++)
                a_off[kk2][mi] = (uint32_t)((wm * 32 + mi * 16 + lm + l8 * 8) * WROW
                                            + kk2 * 8 + l16 * 4) * 4;
#pragma unroll
            for (int np = 0; np < 2; np++)
                b_off[kk2][np] = (uint32_t)((wn * 32 + np * 16 + (bm >> 1) * 8 + lm) * WROW
                                            + kk2 * 8 + (bm & 1) * 4) * 4;
        }
    }

    float acc[MI][NI][4];
#pragma unroll
    for (int mi = 0; mi < MI; mi++)
#pragma unroll
        for (int ni = 0; ni < NI; ni++)
#pragma unroll
            for (int r = 0; r < 4; r++) acc[mi][ni][r] = 0.f;

    // group map per slab: idx<512 A (r=idx>>2, ch=idx&3);
    // idx 512..767 Vh (j=idx-512: r=j>>2 (0..63), ch=j&3);
    // idx 768..1023 Vl.
#pragma unroll
    for (int i = 0; i < 4; i++) {
        const int idx = tid + i * 256;
        if (idx < 512) {
            const int r = idx >> 2, ch = idx & 3;
            CP_ASYNC16(sb + AW0 * 4 + r * 80 + ch * 16, EHz + (long long)(m0 + r) * TT + ch * 8);
        } else if (idx < 768) {
            const int j = idx - 512;
            const int r = j >> 2, ch = j & 3;
            CP_ASYNC16(sb + VH0 * 4 + r * 80 + ch * 16, VHz + (long long)r * TT + ch * 8);
        } else {
            const int j = idx - 768;
            const int r = j >> 2, ch = j & 3;
            CP_ASYNC16(sb + VL0 * 4 + r * 80 + ch * 16, VLz + (long long)r * TT + ch * 8);
        }
    }
    CP_COMMIT();

    const int NIT = TT / 32;

    for (int it = 0; it < NIT; it++) {
        const bool more = it + 1 < NIT;
        const int kbn = (it + 1) * 32;
        if (more) {
            const uint32_t adst = sb + (((it + 1) & 1) ? AW1 : AW0) * 4;
            const uint32_t hdst = sb + (((it + 1) & 1) ? VH1 : VH0) * 4;
            const uint32_t ldst = sb + (((it + 1) & 1) ? VL1 : VL0) * 4;
#pragma unroll
            for (int i = 0; i < 4; i++) {
                const int idx = tid + i * 256;
                if (idx < 512) {
                    const int r = idx >> 2, ch = idx & 3;
                    CP_ASYNC16(adst + r * 80 + ch * 16, EHz + (long long)(m0 + r) * TT + kbn + ch * 8);
                } else if (idx < 768) {
                    const int j = idx - 512;
                    const int r = j >> 2, ch = j & 3;
                    CP_ASYNC16(hdst + r * 80 + ch * 16, VHz + (long long)r * TT + kbn + ch * 8);
                } else {
                    const int j = idx - 768;
                    const int r = j >> 2, ch = j & 3;
                    CP_ASYNC16(ldst + r * 80 + ch * 16, VLz + (long long)r * TT + kbn + ch * 8);
                }
            }
            CP_COMMIT();
            CP_WAIT1();
        } else {
            CP_WAIT0();
        }

        // convert phase: normalized attn writeback from own A groups
        {
            const uint32_t acur = (it & 1) ? AW1 : AW0;
            const int kb = it * 32;
#pragma unroll
            for (int i = 0; i < 2; i++) {
                const int idx = tid + i * 256;
                const int r = idx >> 2, ch = idx & 3;
                uint4 hv = *(const uint4*)(sw + acur + r * WROW + ch * 4);
                const __half2* h2 = (const __half2*)&hv;
                const float inv = i ? inv1s : inv0s;
                float2 f0 = __half22float2(h2[0]);
                float2 f1 = __half22float2(h2[1]);
                float2 f2 = __half22float2(h2[2]);
                float2 f3 = __half22float2(h2[3]);
                float* dst = &AWz[(long long)(m0 + r) * TT + kb + ch * 8];
                *(float4*)dst       = make_float4(f0.x * inv, f0.y * inv, f1.x * inv, f1.y * inv);
                *(float4*)(dst + 4) = make_float4(f2.x * inv, f2.y * inv, f3.x * inv, f3.y * inv);
            }
        }
        __syncthreads();

        {
            const uint32_t abase = sb + ((it & 1) ? AW1 : AW0) * 4;
            const uint32_t hbase = sb + ((it & 1) ? VH1 : VH0) * 4;
            const uint32_t lbase = sb + ((it & 1) ? VL1 : VL0) * 4;
#pragma unroll
            for (int kk2 = 0; kk2 < 2; kk2++) {
                uint32_t bh[NI][2], bl[NI][2];
#pragma unroll
                for (int np = 0; np < 2; np++) {
                    ldsm_x4(bh[np * 2][0], bh[np * 2][1], bh[np * 2 + 1][0], bh[np * 2 + 1][1],
                            hbase + b_off[kk2][np]);
                    ldsm_x4(bl[np * 2][0], bl[np * 2][1], bl[np * 2 + 1][0], bl[np * 2 + 1][1],
                            lbase + b_off[kk2][np]);
                }
#pragma unroll
                for (int mi = 0; mi < MI; mi++) {
                    uint32_t ah[4];
                    ldsm_x4(ah[0], ah[1], ah[2], ah[3], abase + a_off[kk2][mi]);
#pragma unroll
                    for (int ni = 0; ni < NI; ni++) {
                        mma16816h(acc[mi][ni], ah, bh[ni]);
                        mma16816h(acc[mi][ni], ah, bl[ni]);
                    }
                }
            }
        }
        if (more) __syncthreads();
    }

#pragma unroll
    for (int mi = 0; mi < MI; mi++) {
        const int r0 = m0 + wm * 32 + mi * 16 + g;
        const int r1 = r0 + 8;
        const float i0 = invz[r0];
        const float i1 = invz[r1];
#pragma unroll
        for (int ni = 0; ni < NI; ni++) {
            const int c = wn * 32 + ni * 8 + tg * 2;
            *(__half2*)&mhz[(long long)r0 * EE + c] =
                __floats2half2_rn(acc[mi][ni][0] * i0, acc[mi][ni][1] * i0);
            *(__half2*)&mhz[(long long)r1 * EE + c] =
                __floats2half2_rn(acc[mi][ni][2] * i1, acc[mi][ni][3] * i1);
        }
    }
}

// ---------------------------------------------------------------------------
// Proj kernel: out = mhh(fp16, direct-streamed) @ pkt^T + bias. 2-term on B.
// CTA 128x128, k-slab 32, 256 threads (2m x 4n warps).
// ---------------------------------------------------------------------------
__global__ __launch_bounds__(256, 2) void mma_proj(
    const __half* __restrict__ mhh, const float* __restrict__ pkt,
    const float* __restrict__ bias, float* __restrict__ outp)
{
    constexpr int WROW = 20;
    constexpr int AW0 = 0, AW1 = 2560;
    constexpr int BR0 = 5120, BR1 = 9216;        // raw B fp32 (4096 words each)
    constexpr int BH = 13312, BL = 15872;        // B fp16 hi/lo (2560 each) -> 18432 total
    constexpr int MI = 4, NI = 4;

    extern __shared__ char smem[];
    uint32_t* sw = (uint32_t*)smem;
    const uint32_t sb = smem_u32(smem);

    const int m0 = blockIdx.y * 128;
    const int n0 = blockIdx.x * 128;

    const int tid = threadIdx.x, warp = tid >> 5, lane = tid & 31;
    const int wm = warp & 1, wn = warp >> 1;
    const int g = lane >> 2, tg = lane & 3;

    uint32_t a_off[2][MI], b_off[2][2];
    {
        const int lm = lane & 7, l8 = (lane >> 3) & 1, l16 = lane >> 4, bm = lane >> 3;
#pragma unroll
        for (int kk2 = 0; kk2 < 2; kk2++) {
#pragma unroll
            for (int mi = 0; mi < MI; mi++)
                a_off[kk2][mi] = (uint32_t)((wm * 64 + mi * 16 + lm + l8 * 8) * WROW
                                            + kk2 * 8 + l16 * 4) * 4;
#pragma unroll
            for (int np = 0; np < 2; np++)
                b_off[kk2][np] = (uint32_t)((wn * 32 + np * 16 + (bm >> 1) * 8 + lm) * WROW
                                            + kk2 * 8 + (bm & 1) * 4) * 4;
        }
    }

    float acc[MI][NI][4];
#pragma unroll
    for (int mi = 0; mi < MI; mi++)
#pragma unroll
        for (int ni = 0; ni < NI; ni++)
#pragma unroll
            for (int r = 0; r < 4; r++) acc[mi][ni][r] = 0.f;

    // staging map: idx<512 A fp16 (r=idx>>2, ch=idx&3); idx 512..1535 B raw
    // (j=idx-512: r=j>>3 (0..127), c4=(j&7)*4)
#pragma unroll
    for (int i = 0; i < 6; i++) {
        const int idx = tid + i * 256;
        if (idx < 512) {
            const int r = idx >> 2, ch = idx & 3;
            CP_ASYNC16(sb + AW0 * 4 + r * 80 + ch * 16, mhh + (long long)(m0 + r) * EE + ch * 8);
        } else {
            const int j = idx - 512;
            const int r = j >> 3, c4 = (j & 7) * 4;
            CP_ASYNC16(sb + BR0 * 4 + j * 16, pkt + (long long)(n0 + r) * EE + c4);
        }
    }
    CP_COMMIT();

    for (int it = 0; it < 32; it++) {
        const bool more = it + 1 < 32;
        const int kbn = (it + 1) * 32;
        if (more) {
            const uint32_t adst = sb + (((it + 1) & 1) ? AW1 : AW0) * 4;
            const uint32_t bdst = sb + (((it + 1) & 1) ? BR1 : BR0) * 4;
#pragma unroll
            for (int i = 0; i < 6; i++) {
                const int idx = tid + i * 256;
                if (idx < 512) {
                    const int r = idx >> 2, ch = idx & 3;
                    CP_ASYNC16(adst + r * 80 + ch * 16,
                               mhh + (long long)(m0 + r) * EE + kbn + ch * 8);
                } else {
                    const int j = idx - 512;
                    const int r = j >> 3, c4 = (j & 7) * 4;
                    CP_ASYNC16(bdst + j * 16, pkt + (long long)(n0 + r) * EE + kbn + c4);
                }
            }
            CP_COMMIT();
            CP_WAIT1();
        } else {
            CP_WAIT0();
        }

        // convert: B fp32 -> fp16 hi/lo (self-owned groups)
        {
            const uint32_t bcur = (it & 1) ? BR1 : BR0;
#pragma unroll
            for (int i = 0; i < 4; i++) {
                const int j = tid + i * 256;
                const int r = j >> 3, c4 = (j & 7) * 4;
                float4 x = *(const float4*)(sw + bcur + j * 4);
                uint32_t* dh = sw + BH + r * WROW + (c4 >> 1);
                split_store_f16(x, dh, dh + (BL - BH));
            }
        }
        __syncthreads();

        {
            const uint32_t abase = sb + ((it & 1) ? AW1 : AW0) * 4;
#pragma unroll
            for (int kk2 = 0; kk2 < 2; kk2++) {
                uint32_t bh[NI][2], bl[NI][2];
#pragma unroll
                for (int np = 0; np < 2; np++) {
                    ldsm_x4(bh[np * 2][0], bh[np * 2][1], bh[np * 2 + 1][0], bh[np * 2 + 1][1],
                            sb + (uint32_t)BH * 4 + b_off[kk2][np]);
                    ldsm_x4(bl[np * 2][0], bl[np * 2][1], bl[np * 2 + 1][0], bl[np * 2 + 1][1],
                            sb + (uint32_t)BL * 4 + b_off[kk2][np]);
                }
#pragma unroll
                for (int mi = 0; mi < MI; mi++) {
                    uint32_t ah[4];
                    ldsm_x4(ah[0], ah[1], ah[2], ah[3], abase + a_off[kk2][mi]);
#pragma unroll
                    for (int ni = 0; ni < NI; ni++) {
                        mma16816h(acc[mi][ni], ah, bh[ni]);
                        mma16816h(acc[mi][ni], ah, bl[ni]);
                    }
                }
            }
        }
        if (more) __syncthreads();
    }

#pragma unroll
    for (int mi = 0; mi < MI; mi++) {
        const int r0 = m0 + wm * 64 + mi * 16 + g;
        const int r1 = r0 + 8;
#pragma unroll
        for (int ni = 0; ni < NI; ni++) {
            const int c = n0 + wn * 32 + ni * 8 + tg * 2;
            float2 bv = *(const float2*)&bias[c];
            *(float2*)&outp[(long long)r0 * OO + c] =
                make_float2(acc[mi][ni][0] + bv.x, acc[mi][ni][1] + bv.y);
            *(float2*)&outp[(long long)r1 * OO + c] =
                make_float2(acc[mi][ni][2] + bv.x, acc[mi][ni][3] + bv.y);
        }
    }
}

// ---------------------------------------------------------------------------
// rowsum helpers
// ---------------------------------------------------------------------------
__global__ void zero_rowsum(float* rs) {
    rs[blockIdx.x * 256 + threadIdx.x] = 0.f;
}
__global__ void invert_rowsum(float* rs) {
    const int i = blockIdx.x * 256 + threadIdx.x;
    rs[i] = 1.f / rs[i];
}

// ---------------------------------------------------------------------------
// Transposes
// ---------------------------------------------------------------------------
__global__ __launch_bounds__(256) void transpose_v(const float* __restrict__ v,
                                                   __half* __restrict__ vth,
                                                   __half* __restrict__ vtl)
{
    __shared__ float tile[32][33];
    const int z = blockIdx.z;
    const int b = z / HH, h = z % HH;
    const int m0 = blockIdx.x * 32;
    const int d0 = blockIdx.y * 32;
    const int tx = threadIdx.x & 31;
    const int ty0 = threadIdx.x >> 5;
#pragma unroll
    for (int ty = ty0; ty < 32; ty += 8)
        tile[ty][tx] = v[((long long)b * TT + m0 + ty) * EE + h * DD + d0 + tx];
    __syncthreads();
#pragma unroll
    for (int ty = ty0; ty < 32; ty += 8) {
        const float x = tile[tx][ty];
        const __half hi = __float2half_rn(x);
        const __half lo = __float2half_rn(x - __half2float(hi));
        const long long off = (((long long)z) * DD + d0 + ty) * TT + m0 + tx;
        vth[off] = hi;
        vtl[off] = lo;
    }
}

__global__ __launch_bounds__(256) void transpose_pk(const float* __restrict__ pk,
                                                    float* __restrict__ pkt)
{
    __shared__ float tile[32][33];
    const int k0 = blockIdx.x * 32;
    const int o0 = blockIdx.y * 32;
    const int tx = threadIdx.x & 31;
    const int ty0 = threadIdx.x >> 5;
#pragma unroll
    for (int ty = ty0; ty < 32; ty += 8)
        tile[ty][tx] = pk[(long long)(k0 + ty) * OO + o0 + tx];
    __syncthreads();
#pragma unroll
    for (int ty = ty0; ty < 32; ty += 8)
        pkt[(long long)(o0 + ty) * EE + k0 + tx] = tile[tx][ty];
}

// ---------------------------------------------------------------------------
// Launch
// ---------------------------------------------------------------------------
extern "C" void kernel_launch(void* const* d_in, const int* in_sizes, int n_in,
                              void* d_out, int out_size)
{
    const float* query = (const float*)d_in[0];
    const float* key   = (const float*)d_in[1];
    const float* value = (const float*)d_in[2];
    const float* Wq    = (const float*)d_in[3];
    const float* Wk    = (const float*)d_in[4];
    const float* Wv    = (const float*)d_in[5];
    const float* pk    = (const float*)d_in[6];
    const float* pb    = (const float*)d_in[7];

    float *vp, *pktp, *rsp, *outs, *attns;
    __half *ehp, *qhp, *khp, *klp, *mhhp, *vthp, *vtlp;
    cudaGetSymbolAddress((void**)&vp,    g_v);
    cudaGetSymbolAddress((void**)&mhhp,  g_mhh);
    cudaGetSymbolAddress((void**)&vthp,  g_vth);
    cudaGetSymbolAddress((void**)&vtlp,  g_vtl);
    cudaGetSymbolAddress((void**)&pktp,  g_pkt);
    cudaGetSymbolAddress((void**)&rsp,   g_rowsum);
    cudaGetSymbolAddress((void**)&ehp,   g_exph);
    cudaGetSymbolAddress((void**)&qhp,   g_qh);
    cudaGetSymbolAddress((void**)&khp,   g_kh);
    cudaGetSymbolAddress((void**)&klp,   g_kl);
    cudaGetSymbolAddress((void**)&outs,  g_out_scratch);
    cudaGetSymbolAddress((void**)&attns, g_attn_scratch);

    const long long outN  = (long long)BB * TT * OO;
    const long long attnN = (long long)BB * HH * TT * TT;

    float* outP  = (float*)d_out;
    float* attnP;
    if ((long long)out_size >= outN + attnN) {
        attnP = outP + outN;
    } else if ((long long)out_size == attnN) {
        attnP = (float*)d_out;
        outP  = outs;
    } else {
        attnP = attns;
    }

    constexpr int SMEMQKV  = (2 * 256 * 32 + 3 * 128 * 20) * 4;  // 96256
    constexpr int SMEMQK   = 23040 * 4;                          // 92160
    constexpr int SMEMAV   = 10240 * 4;                          // 40960
    constexpr int SMEMPROJ = 18432 * 4;                          // 73728
    cudaFuncSetAttribute((const void*)mma_qkv,
                         cudaFuncAttributeMaxDynamicSharedMemorySize, SMEMQKV);
    cudaFuncSetAttribute((const void*)mma_qk,
                         cudaFuncAttributeMaxDynamicSharedMemorySize, SMEMQK);
    cudaFuncSetAttribute((const void*)mma_av,
                         cudaFuncAttributeMaxDynamicSharedMemorySize, SMEMAV);
    cudaFuncSetAttribute((const void*)mma_proj,
                         cudaFuncAttributeMaxDynamicSharedMemorySize, SMEMPROJ);

    // 0) zero row sums
    zero_rowsum<<<(BB * HH * TT) / 256, 256>>>(rsp);

    // 1) QKV projections (fp16 2-term): qh / kh,kl / v
    {
        dim3 grid(EE / 128, (BB * TT) / 128, 3);
        mma_qkv<<<grid, 256, SMEMQKV>>>(query, key, value, Wq, Wk, Wv,
                                        qhp, khp, klp, vp);
    }

    // transposes: V -> fp16 hi/lo [z][d][m]; pk -> [o][k]
    {
        dim3 gv(TT / 32, DD / 32, BB * HH);
        transpose_v<<<gv, 256>>>(vp, vthp, vtlp);
        dim3 gp(EE / 32, OO / 32, 1);
        transpose_pk<<<gp, 256>>>(pk, pktp);
    }

    // 2) exph = fp16(exp(0.125 * q @ k^T))
    {
        dim3 grid(TT / 128, BB * HH);
        mma_qk<<<grid, 256, SMEMQK>>>(qhp, khp, klp, rsp, ehp);
    }

    // 3) invert row sums
    invert_rowsum<<<(BB * HH * TT) / 256, 256>>>(rsp);

    // 4) mh(fp16) = inv * (exph @ vT^T); writes normalized fp32 attn once
    {
        dim3 grid(TT / 128, BB * HH);
        mma_av<<<grid, 256, SMEMAV>>>(ehp, vthp, vtlp, rsp, attnP, mhhp);
    }

    // 5) out = mhh @ pkt^T + bias
    {
        dim3 grid(OO / 128, (BB * TT) / 128, 1);
        mma_proj<<<grid, 256, SMEMPROJ>>>(mhhp, pktp, pb, outP);
    }
}

// round 17
// speedup vs baseline: 1.4286x; 1.0245x over previous
#include <cuda_runtime.h>
#include <cuda_bf16.h>
#include <cuda_fp16.h>
#include <cstdint>

// Problem dims
#define BB 2
#define TT 2048
#define HH 16
#define DD 64
#define EE 1024   // HH*DD
#define OO 1024

// Scratch (device globals)
__device__ float g_v[(size_t)BB * TT * EE];           // value (fp32, from QKV z=2)
__device__ __half g_mhh[(size_t)BB * TT * EE];        // mh fp16
__device__ __half g_vth[(size_t)BB * TT * EE];        // V^T fp16 hi: [z][d][m]
__device__ __half g_vtl[(size_t)BB * TT * EE];        // V^T fp16 lo
__device__ float g_pkt[(size_t)EE * OO];              // proj kernel transposed: [o][k]
__device__ float g_rowsum[(size_t)BB * HH * TT];      // exp row sums -> inverses
__device__ __half g_exph[(size_t)BB * HH * TT * TT];  // fp16 exp(logits)
__device__ __half g_qh[(size_t)BB * TT * EE];         // q fp16 hi
__device__ __half g_kh[(size_t)BB * TT * EE];         // k fp16 hi
__device__ __half g_kl[(size_t)BB * TT * EE];         // k fp16 lo
__device__ float g_out_scratch[(size_t)BB * TT * OO];
__device__ float g_attn_scratch[(size_t)BB * HH * TT * TT];

// ---------------------------------------------------------------------------
// PTX helpers (baseline features only)
// ---------------------------------------------------------------------------
__device__ __forceinline__ uint32_t smem_u32(const void* p) {
    uint32_t a;
    asm("{ .reg .u64 t; cvta.to.shared.u64 t, %1; cvt.u32.u64 %0, t; }" : "=r"(a) : "l"(p));
    return a;
}
#define CP_ASYNC16(dst_u32, src_ptr) \
    asm volatile("cp.async.cg.shared.global [%0], [%1], 16;" :: "r"(dst_u32), "l"(src_ptr))
#define CP_COMMIT() asm volatile("cp.async.commit_group;" ::: "memory")
#define CP_WAIT1()  asm volatile("cp.async.wait_group 1;" ::: "memory")
#define CP_WAIT0()  asm volatile("cp.async.wait_group 0;" ::: "memory")

__device__ __forceinline__ void mma16816h(float* c, const uint32_t* a, const uint32_t* b) {
    asm volatile(
        "mma.sync.aligned.m16n8k16.row.col.f32.f16.f16.f32 "
        "{%0,%1,%2,%3}, {%4,%5,%6,%7}, {%8,%9}, {%0,%1,%2,%3};"
        : "+f"(c[0]), "+f"(c[1]), "+f"(c[2]), "+f"(c[3])
        : "r"(a[0]), "r"(a[1]), "r"(a[2]), "r"(a[3]), "r"(b[0]), "r"(b[1]));
}

__device__ __forceinline__ void ldsm_x4(uint32_t& r0, uint32_t& r1, uint32_t& r2, uint32_t& r3,
                                        uint32_t addr) {
    asm volatile("ldmatrix.sync.aligned.m8n8.x4.shared.b16 {%0,%1,%2,%3}, [%4];"
                 : "=r"(r0), "=r"(r1), "=r"(r2), "=r"(r3) : "r"(addr));
}

__device__ __forceinline__ void split_store_f16(float4 x, uint32_t* dh, uint32_t* dl) {
    __half2 h0 = __floats2half2_rn(x.x, x.y);
    __half2 h1 = __floats2half2_rn(x.z, x.w);
    float2 f0 = __half22float2(h0);
    float2 f1 = __half22float2(h1);
    __half2 l0 = __floats2half2_rn(x.x - f0.x, x.y - f0.y);
    __half2 l1 = __floats2half2_rn(x.z - f1.x, x.w - f1.y);
    *(uint2*)dh = make_uint2(*(uint32_t*)&h0, *(uint32_t*)&h1);
    *(uint2*)dl = make_uint2(*(uint32_t*)&l0, *(uint32_t*)&l1);
}
__device__ __forceinline__ void store_f16_hi(float4 x, uint32_t* dh) {
    __half2 h0 = __floats2half2_rn(x.x, x.y);
    __half2 h1 = __floats2half2_rn(x.z, x.w);
    *(uint2*)dh = make_uint2(*(uint32_t*)&h0, *(uint32_t*)&h1);
}

__device__ __forceinline__ float ex2f(float x) {
    float r;
    asm("ex2.approx.f32 %0, %1;" : "=f"(r) : "f"(x));
    return r;
}

// streaming (evict-first) float4 store for write-once data
__device__ __forceinline__ void stcs4(float* p, float4 v) {
    asm volatile("st.global.cs.v4.f32 [%0], {%1,%2,%3,%4};"
                 :: "l"(p), "f"(v.x), "f"(v.y), "f"(v.z), "f"(v.w) : "memory");
}

// ---------------------------------------------------------------------------
// QKV GEMM: C = A @ W^T, fp16 2-term (Ah*Bh + Ah*Bl).
// blockIdx.z: 0 -> qh (fp16 hi), 1 -> kh/kl (fp16 hi+lo), 2 -> v (fp32).
// ---------------------------------------------------------------------------
__global__ __launch_bounds__(256, 2) void mma_qkv(
    const float* __restrict__ Aq, const float* __restrict__ Ak, const float* __restrict__ Av,
    const float* __restrict__ Wq, const float* __restrict__ Wk, const float* __restrict__ Wv,
    __half* __restrict__ QHo, __half* __restrict__ KHo, __half* __restrict__ KLo,
    float* __restrict__ Vo)
{
    constexpr int WROW = 20;
    constexpr int ROWS = 256;
    constexpr int NLOOP = 8;
    constexpr int RAWW = ROWS * 32;
    constexpr int AHL = 128 * WROW;
    constexpr int BOFF = AHL;
    constexpr int BHL = 128 * WROW;

    extern __shared__ char smem[];
    float*    raw0p = (float*)smem;
    float*    raw1p = (float*)(smem + RAWW * 4);
    uint32_t* bw    = (uint32_t*)(smem + 2 * RAWW * 4);
    const uint32_t raw0a = smem_u32(raw0p);
    const uint32_t raw1a = raw0a + RAWW * 4;
    const uint32_t bwa   = raw0a + 2 * RAWW * 4;

    const int z = blockIdx.z;
    const float* A  = (z == 0) ? Aq : (z == 1 ? Ak : Av);
    const float* Bm = (z == 0) ? Wq : (z == 1 ? Wk : Wv);

    const int m0 = blockIdx.y * 128;
    const int n0 = blockIdx.x * 128;

    const int tid = threadIdx.x, warp = tid >> 5, lane = tid & 31;
    const int wm = warp & 1, wn = warp >> 1;
    const int g = lane >> 2, tg = lane & 3;

    uint32_t a_addr[2][4], b_addr[2][2];
    {
        const int lm = lane & 7, l8 = (lane >> 3) & 1, l16 = lane >> 4, bm = lane >> 3;
#pragma unroll
        for (int kk2 = 0; kk2 < 2; kk2++) {
#pragma unroll
            for (int mi = 0; mi < 4; mi++)
                a_addr[kk2][mi] = bwa + (uint32_t)((wm * 64 + mi * 16 + lm + l8 * 8) * WROW
                                                   + kk2 * 8 + l16 * 4) * 4;
#pragma unroll
            for (int np = 0; np < 2; np++)
                b_addr[kk2][np] = bwa + (uint32_t)(BOFF +
                    (wn * 32 + np * 16 + (bm >> 1) * 8 + lm) * WROW + kk2 * 8 + (bm & 1) * 4) * 4;
        }
    }

    float acc[4][4][4];
#pragma unroll
    for (int mi = 0; mi < 4; mi++)
#pragma unroll
        for (int ni = 0; ni < 4; ni++)
#pragma unroll
            for (int r = 0; r < 4; r++) acc[mi][ni][r] = 0.f;

#pragma unroll
    for (int i = 0; i < NLOOP; i++) {
        const int idx = tid + i * 256;
        const bool isA = idx < 1024;
        const int r = isA ? (idx >> 3) : ((idx - 1024) >> 3);
        const int c = (idx & 7) * 4;
        const float* src = isA ? &A[(long long)(m0 + r) * EE + c]
                               : &Bm[(long long)(n0 + r) * EE + c];
        CP_ASYNC16(raw0a + idx * 16, src);
    }
    CP_COMMIT();

    for (int it = 0; it < 32; it++) {
        const bool more = it + 1 < 32;
        const int kbn = (it + 1) * 32;
        if (more) {
            const uint32_t rdst = ((it + 1) & 1) ? raw1a : raw0a;
#pragma unroll
            for (int i = 0; i < NLOOP; i++) {
                const int idx = tid + i * 256;
                const bool isA = idx < 1024;
                const int r = isA ? (idx >> 3) : ((idx - 1024) >> 3);
                const int c = (idx & 7) * 4;
                const float* src = isA ? &A[(long long)(m0 + r) * EE + kbn + c]
                                       : &Bm[(long long)(n0 + r) * EE + kbn + c];
                CP_ASYNC16(rdst + idx * 16, src);
            }
            CP_COMMIT();
            CP_WAIT1();
        } else {
            CP_WAIT0();
        }

        {
            const float* rbuf = (it & 1) ? raw1p : raw0p;
#pragma unroll
            for (int i = 0; i < NLOOP; i++) {
                const int idx = tid + i * 256;
                const bool isA = idx < 1024;
                const int r = isA ? (idx >> 3) : ((idx - 1024) >> 3);
                const int c = (idx & 7) * 4;
                float4 x = *(const float4*)(rbuf + idx * 4);
                const uint32_t w = r * WROW + (c >> 1);
                if (isA) store_f16_hi(x, bw + w);
                else     split_store_f16(x, bw + BOFF + w, bw + BOFF + w + BHL);
            }
        }
        __syncthreads();

#pragma unroll
        for (int kk2 = 0; kk2 < 2; kk2++) {
            uint32_t bh[4][2], bl[4][2];
#pragma unroll
            for (int np = 0; np < 2; np++) {
                ldsm_x4(bh[np * 2][0], bh[np * 2][1], bh[np * 2 + 1][0], bh[np * 2 + 1][1],
                        b_addr[kk2][np]);
                ldsm_x4(bl[np * 2][0], bl[np * 2][1], bl[np * 2 + 1][0], bl[np * 2 + 1][1],
                        b_addr[kk2][np] + BHL * 4);
            }
#pragma unroll
            for (int mi = 0; mi < 4; mi++) {
                uint32_t ah[4];
                ldsm_x4(ah[0], ah[1], ah[2], ah[3], a_addr[kk2][mi]);
#pragma unroll
                for (int ni = 0; ni < 4; ni++) {
                    mma16816h(acc[mi][ni], ah, bh[ni]);
                    mma16816h(acc[mi][ni], ah, bl[ni]);
                }
            }
        }
        if (more) __syncthreads();
    }

#pragma unroll
    for (int mi = 0; mi < 4; mi++) {
        const int r0 = m0 + wm * 64 + mi * 16 + g;
        const int r1 = r0 + 8;
#pragma unroll
        for (int ni = 0; ni < 4; ni++) {
            const int c = n0 + wn * 32 + ni * 8 + tg * 2;
            if (z == 0) {
                *(__half2*)&QHo[(long long)r0 * EE + c] =
                    __floats2half2_rn(acc[mi][ni][0], acc[mi][ni][1]);
                *(__half2*)&QHo[(long long)r1 * EE + c] =
                    __floats2half2_rn(acc[mi][ni][2], acc[mi][ni][3]);
            } else if (z == 1) {
                __half2 h0 = __floats2half2_rn(acc[mi][ni][0], acc[mi][ni][1]);
                __half2 h1 = __floats2half2_rn(acc[mi][ni][2], acc[mi][ni][3]);
                float2 f0 = __half22float2(h0);
                float2 f1 = __half22float2(h1);
                *(__half2*)&KHo[(long long)r0 * EE + c] = h0;
                *(__half2*)&KHo[(long long)r1 * EE + c] = h1;
                *(__half2*)&KLo[(long long)r0 * EE + c] =
                    __floats2half2_rn(acc[mi][ni][0] - f0.x, acc[mi][ni][1] - f0.y);
                *(__half2*)&KLo[(long long)r1 * EE + c] =
                    __floats2half2_rn(acc[mi][ni][2] - f1.x, acc[mi][ni][3] - f1.y);
            } else {
                *(float2*)&Vo[(long long)r0 * EE + c] = make_float2(acc[mi][ni][0], acc[mi][ni][1]);
                *(float2*)&Vo[(long long)r1 * EE + c] = make_float2(acc[mi][ni][2], acc[mi][ni][3]);
            }
        }
    }
}

// ---------------------------------------------------------------------------
// A-resident logits kernel (unchanged)
// ---------------------------------------------------------------------------
__global__ __launch_bounds__(256, 2) void mma_qk(
    const __half* __restrict__ qh, const __half* __restrict__ kh,
    const __half* __restrict__ kl,
    float* __restrict__ rowsum, __half* __restrict__ EH)
{
    constexpr int QROW = 36;
    constexpr int QOFF = 0;
    constexpr int KH0 = 4608, KL0 = 9216;
    constexpr int KH1 = 13824, KL1 = 18432;
    constexpr int KLOFF = 4608;

    extern __shared__ char smem[];
    const uint32_t sb = smem_u32(smem);

    const int z = blockIdx.y;
    const int b = z / HH, h = z % HH;
    const int m0 = blockIdx.x * 128;

    const __half* qz  = qh + ((long long)b * TT) * EE + h * DD;
    const __half* khz = kh + ((long long)b * TT) * EE + h * DD;
    const __half* klz = kl + ((long long)b * TT) * EE + h * DD;
    __half* EHz = EH + (long long)z * TT * TT;
    float* rowsumz = rowsum + (long long)z * TT;

    const int tid = threadIdx.x, warp = tid >> 5, lane = tid & 31;
    const int wm = warp & 1;
    const int wn = warp >> 1;
    const int g = lane >> 2, tg = lane & 3;
    const int lm = lane & 7, l8 = (lane >> 3) & 1, l16 = lane >> 4, bm = lane >> 3;

#pragma unroll
    for (int i = 0; i < 4; i++) {
        const int idx = tid + i * 256;
        const int r = idx >> 3, ch = idx & 7;
        CP_ASYNC16(sb + (uint32_t)(QOFF + r * QROW + ch * 4) * 4,
                   qz + (long long)(m0 + r) * EE + ch * 8);
    }
#pragma unroll
    for (int i = 0; i < 8; i++) {
        const int idx = tid + i * 256;
        const bool isH = idx < 1024;
        const int j = isH ? idx : idx - 1024;
        const int r = j >> 3, ch = j & 7;
        const __half* src = (isH ? khz : klz) + (long long)r * EE + ch * 8;
        CP_ASYNC16(sb + (uint32_t)((isH ? KH0 : KL0) + r * QROW + ch * 4) * 4, src);
    }
    CP_COMMIT();

    float ps[4][2];
#pragma unroll
    for (int mi = 0; mi < 4; mi++) { ps[mi][0] = 0.f; ps[mi][1] = 0.f; }

    const float A2 = 0.125f * 1.44269504f;

    for (int nt = 0; nt < 16; nt++) {
        const bool more = nt + 1 < 16;
        if (more) {
            const int nb = (nt + 1) * 128;
            const uint32_t khd = ((nt + 1) & 1) ? KH1 : KH0;
            const uint32_t kld = ((nt + 1) & 1) ? KL1 : KL0;
#pragma unroll
            for (int i = 0; i < 8; i++) {
                const int idx = tid + i * 256;
                const bool isH = idx < 1024;
                const int j = isH ? idx : idx - 1024;
                const int r = j >> 3, ch = j & 7;
                const __half* src = (isH ? khz : klz) + (long long)(nb + r) * EE + ch * 8;
                CP_ASYNC16(sb + (uint32_t)((isH ? khd : kld) + r * QROW + ch * 4) * 4, src);
            }
            CP_COMMIT();
            CP_WAIT1();
        } else {
            CP_WAIT0();
        }
        __syncthreads();

        const uint32_t khc = (nt & 1) ? KH1 : KH0;

        float acc[4][4][4];
#pragma unroll
        for (int mi = 0; mi < 4; mi++)
#pragma unroll
            for (int ni = 0; ni < 4; ni++)
#pragma unroll
                for (int r = 0; r < 4; r++) acc[mi][ni][r] = 0.f;

#pragma unroll
        for (int kk = 0; kk < 4; kk++) {
            uint32_t bh[4][2], bl[4][2];
#pragma unroll
            for (int np = 0; np < 2; np++) {
                const uint32_t addr = sb + (uint32_t)(khc +
                    (wn * 32 + np * 16 + (bm >> 1) * 8 + lm) * QROW + kk * 8 + (bm & 1) * 4) * 4;
                ldsm_x4(bh[np * 2][0], bh[np * 2][1], bh[np * 2 + 1][0], bh[np * 2 + 1][1], addr);
                ldsm_x4(bl[np * 2][0], bl[np * 2][1], bl[np * 2 + 1][0], bl[np * 2 + 1][1],
                        addr + KLOFF * 4);
            }
#pragma unroll
            for (int mi = 0; mi < 4; mi++) {
                uint32_t ah[4];
                const uint32_t aaddr = sb + (uint32_t)(QOFF +
                    (wm * 64 + mi * 16 + lm + l8 * 8) * QROW + kk * 8 + l16 * 4) * 4;
                ldsm_x4(ah[0], ah[1], ah[2], ah[3], aaddr);
#pragma unroll
                for (int ni = 0; ni < 4; ni++) {
                    mma16816h(acc[mi][ni], ah, bh[ni]);
                    mma16816h(acc[mi][ni], ah, bl[ni]);
                }
            }
        }

#pragma unroll
        for (int mi = 0; mi < 4; mi++) {
            const int r0 = m0 + wm * 64 + mi * 16 + g;
            const int r1 = r0 + 8;
#pragma unroll
            for (int ni = 0; ni < 4; ni++) {
                const int c = nt * 128 + wn * 32 + ni * 8 + tg * 2;
                __half q0 = __float2half_rn(ex2f(acc[mi][ni][0] * A2));
                __half q1 = __float2half_rn(ex2f(acc[mi][ni][1] * A2));
                __half q2 = __float2half_rn(ex2f(acc[mi][ni][2] * A2));
                __half q3 = __float2half_rn(ex2f(acc[mi][ni][3] * A2));
                *(__half2*)&EHz[(long long)r0 * TT + c] = __halves2half2(q0, q1);
                *(__half2*)&EHz[(long long)r1 * TT + c] = __halves2half2(q2, q3);
                ps[mi][0] += __half2float(q0) + __half2float(q1);
                ps[mi][1] += __half2float(q2) + __half2float(q3);
            }
        }
        __syncthreads();
    }

#pragma unroll
    for (int mi = 0; mi < 4; mi++) {
        float p0 = ps[mi][0], p1 = ps[mi][1];
        p0 += __shfl_xor_sync(0xffffffffu, p0, 1);
        p0 += __shfl_xor_sync(0xffffffffu, p0, 2);
        p1 += __shfl_xor_sync(0xffffffffu, p1, 1);
        p1 += __shfl_xor_sync(0xffffffffu, p1, 2);
        if (tg == 0) {
            const int r0 = m0 + wm * 64 + mi * 16 + g;
            atomicAdd(&rowsumz[r0], p0);
            atomicAdd(&rowsumz[r0 + 8], p1);
        }
    }
}

// ---------------------------------------------------------------------------
// AV kernel v4: k-slab 64 (half the barriers, 4x MMA per phase), fp16
// direct-streamed A and Vh/Vl, streaming attn writeback, fp16 mh out.
// smem: A 2x4608w, V 4x2304w = 18432 words = 72KB. 2 CTAs/SM.
// ---------------------------------------------------------------------------
__global__ __launch_bounds__(256, 2) void mma_av(
    const __half* __restrict__ exph,
    const __half* __restrict__ vth, const __half* __restrict__ vtl,
    const float* __restrict__ invr,
    float* __restrict__ attn, __half* __restrict__ mhh)
{
    constexpr int VROW = 36;
    constexpr int AW0 = 0, AW1 = 4608;
    constexpr int VH0 = 9216, VL0 = 11520;
    constexpr int VH1 = 13824, VL1 = 16128;
    constexpr int MI = 2, NI = 4;

    extern __shared__ char smem[];
    uint32_t* sw = (uint32_t*)smem;
    const uint32_t sb = smem_u32(smem);

    const int z = blockIdx.y;
    const int b = z / HH, h = z % HH;
    const int m0 = blockIdx.x * 128;

    const __half* EHz = exph + (long long)z * TT * TT;
    const __half* VHz = vth + (long long)z * DD * TT;
    const __half* VLz = vtl + (long long)z * DD * TT;
    float* AWz = attn + (long long)z * TT * TT;
    __half* mhz = mhh + (long long)b * TT * EE + h * DD;
    const float* invz = invr + (long long)z * TT;

    const int tid = threadIdx.x, warp = tid >> 5, lane = tid & 31;
    const int wm = warp & 3, wn = warp >> 2;
    const int g = lane >> 2, tg = lane & 3;

    // staging inv for this thread's A rows: (tid>>3) + i*32
    float invc[4];
#pragma unroll
    for (int i = 0; i < 4; i++)
        invc[i] = invz[m0 + (tid >> 3) + i * 32];

    uint32_t a_base[MI], b_base[2];
    {
        const int lm = lane & 7, l8 = (lane >> 3) & 1, l16 = lane >> 4, bm = lane >> 3;
#pragma unroll
        for (int mi = 0; mi < MI; mi++)
            a_base[mi] = (uint32_t)((wm * 32 + mi * 16 + lm + l8 * 8) * VROW + l16 * 4) * 4;
#pragma unroll
        for (int np = 0; np < 2; np++)
            b_base[np] = (uint32_t)((wn * 32 + np * 16 + (bm >> 1) * 8 + lm) * VROW
                                    + (bm & 1) * 4) * 4;
    }

    float acc[MI][NI][4];
#pragma unroll
    for (int mi = 0; mi < MI; mi++)
#pragma unroll
        for (int ni = 0; ni < NI; ni++)
#pragma unroll
            for (int r = 0; r < 4; r++) acc[mi][ni][r] = 0.f;

    // staging map per 64-k slab: 2048 x 16B chunks
    //  idx <1024: A   (r=idx>>3 in 0..127, ch=idx&7 of 8 halves)
    //  idx <1536: Vh  (j=idx-1024: r=j>>3 in 0..63, ch=j&7)
    //  else:      Vl
#pragma unroll
    for (int i = 0; i < 8; i++) {
        const int idx = tid + i * 256;
        if (idx < 1024) {
            const int r = idx >> 3, ch = idx & 7;
            CP_ASYNC16(sb + (uint32_t)(AW0 + r * VROW + ch * 4) * 4,
                       EHz + (long long)(m0 + r) * TT + ch * 8);
        } else if (idx < 1536) {
            const int j = idx - 1024;
            const int r = j >> 3, ch = j & 7;
            CP_ASYNC16(sb + (uint32_t)(VH0 + r * VROW + ch * 4) * 4,
                       VHz + (long long)r * TT + ch * 8);
        } else {
            const int j = idx - 1536;
            const int r = j >> 3, ch = j & 7;
            CP_ASYNC16(sb + (uint32_t)(VL0 + r * VROW + ch * 4) * 4,
                       VLz + (long long)r * TT + ch * 8);
        }
    }
    CP_COMMIT();

    const int NIT = TT / 64;   // 32

    for (int it = 0; it < NIT; it++) {
        const bool more = it + 1 < NIT;
        const int kbn = (it + 1) * 64;
        if (more) {
            const uint32_t aw = ((it + 1) & 1) ? AW1 : AW0;
            const uint32_t vh = ((it + 1) & 1) ? VH1 : VH0;
            const uint32_t vl = ((it + 1) & 1) ? VL1 : VL0;
#pragma unroll
            for (int i = 0; i < 8; i++) {
                const int idx = tid + i * 256;
                if (idx < 1024) {
                    const int r = idx >> 3, ch = idx & 7;
                    CP_ASYNC16(sb + (uint32_t)(aw + r * VROW + ch * 4) * 4,
                               EHz + (long long)(m0 + r) * TT + kbn + ch * 8);
                } else if (idx < 1536) {
                    const int j = idx - 1024;
                    const int r = j >> 3, ch = j & 7;
                    CP_ASYNC16(sb + (uint32_t)(vh + r * VROW + ch * 4) * 4,
                               VHz + (long long)r * TT + kbn + ch * 8);
                } else {
                    const int j = idx - 1536;
                    const int r = j >> 3, ch = j & 7;
                    CP_ASYNC16(sb + (uint32_t)(vl + r * VROW + ch * 4) * 4,
                               VLz + (long long)r * TT + kbn + ch * 8);
                }
            }
            CP_COMMIT();
            CP_WAIT1();
        } else {
            CP_WAIT0();
        }

        // attn writeback (streaming stores) from own A groups
        {
            const uint32_t acur = (it & 1) ? AW1 : AW0;
            const int kb = it * 64;
#pragma unroll
            for (int i = 0; i < 4; i++) {
                const int idx = tid + i * 256;
                const int r = idx >> 3, ch = idx & 7;
                uint4 hv = *(const uint4*)(sw + acur + r * VROW + ch * 4);
                const __half2* h2 = (const __half2*)&hv;
                const float inv = invc[i];
                float2 f0 = __half22float2(h2[0]);
                float2 f1 = __half22float2(h2[1]);
                float2 f2 = __half22float2(h2[2]);
                float2 f3 = __half22float2(h2[3]);
                float* dst = &AWz[(long long)(m0 + r) * TT + kb + ch * 8];
                stcs4(dst,     make_float4(f0.x * inv, f0.y * inv, f1.x * inv, f1.y * inv));
                stcs4(dst + 4, make_float4(f2.x * inv, f2.y * inv, f3.x * inv, f3.y * inv));
            }
        }
        __syncthreads();

        {
            const uint32_t abase = sb + ((it & 1) ? AW1 : AW0) * 4;
            const uint32_t hbase = sb + ((it & 1) ? VH1 : VH0) * 4;
            const uint32_t lbase = sb + ((it & 1) ? VL1 : VL0) * 4;
#pragma unroll
            for (int kk2 = 0; kk2 < 4; kk2++) {
                const uint32_t koff = (uint32_t)(kk2 * 8) * 4;
                uint32_t bh[NI][2], bl[NI][2];
#pragma unroll
                for (int np = 0; np < 2; np++) {
                    ldsm_x4(bh[np * 2][0], bh[np * 2][1], bh[np * 2 + 1][0], bh[np * 2 + 1][1],
                            hbase + b_base[np] + koff);
                    ldsm_x4(bl[np * 2][0], bl[np * 2][1], bl[np * 2 + 1][0], bl[np * 2 + 1][1],
                            lbase + b_base[np] + koff);
                }
#pragma unroll
                for (int mi = 0; mi < MI; mi++) {
                    uint32_t ah[4];
                    ldsm_x4(ah[0], ah[1], ah[2], ah[3], abase + a_base[mi] + koff);
#pragma unroll
                    for (int ni = 0; ni < NI; ni++) {
                        mma16816h(acc[mi][ni], ah, bh[ni]);
                        mma16816h(acc[mi][ni], ah, bl[ni]);
                    }
                }
            }
        }
        if (more) __syncthreads();
    }

#pragma unroll
    for (int mi = 0; mi < MI; mi++) {
        const int r0 = m0 + wm * 32 + mi * 16 + g;
        const int r1 = r0 + 8;
        const float i0 = invz[r0];
        const float i1 = invz[r1];
#pragma unroll
        for (int ni = 0; ni < NI; ni++) {
            const int c = wn * 32 + ni * 8 + tg * 2;
            *(__half2*)&mhz[(long long)r0 * EE + c] =
                __floats2half2_rn(acc[mi][ni][0] * i0, acc[mi][ni][1] * i0);
            *(__half2*)&mhz[(long long)r1 * EE + c] =
                __floats2half2_rn(acc[mi][ni][2] * i1, acc[mi][ni][3] * i1);
        }
    }
}

// ---------------------------------------------------------------------------
// Proj kernel (unchanged from R16)
// ---------------------------------------------------------------------------
__global__ __launch_bounds__(256, 2) void mma_proj(
    const __half* __restrict__ mhh, const float* __restrict__ pkt,
    const float* __restrict__ bias, float* __restrict__ outp)
{
    constexpr int WROW = 20;
    constexpr int AW0 = 0, AW1 = 2560;
    constexpr int BR0 = 5120, BR1 = 9216;
    constexpr int BH = 13312, BL = 15872;
    constexpr int MI = 4, NI = 4;

    extern __shared__ char smem[];
    uint32_t* sw = (uint32_t*)smem;
    const uint32_t sb = smem_u32(smem);

    const int m0 = blockIdx.y * 128;
    const int n0 = blockIdx.x * 128;

    const int tid = threadIdx.x, warp = tid >> 5, lane = tid & 31;
    const int wm = warp & 1, wn = warp >> 1;
    const int g = lane >> 2, tg = lane & 3;

    uint32_t a_off[2][MI], b_off[2][2];
    {
        const int lm = lane & 7, l8 = (lane >> 3) & 1, l16 = lane >> 4, bm = lane >> 3;
#pragma unroll
        for (int kk2 = 0; kk2 < 2; kk2++) {
#pragma unroll
            for (int mi = 0; mi < MI; mi++)
                a_off[kk2][mi] = (uint32_t)((wm * 64 + mi * 16 + lm + l8 * 8) * WROW
                                            + kk2 * 8 + l16 * 4) * 4;
#pragma unroll
            for (int np = 0; np < 2; np++)
                b_off[kk2][np] = (uint32_t)((wn * 32 + np * 16 + (bm >> 1) * 8 + lm) * WROW
                                            + kk2 * 8 + (bm & 1) * 4) * 4;
        }
    }

    float acc[MI][NI][4];
#pragma unroll
    for (int mi = 0; mi < MI; mi++)
#pragma unroll
        for (int ni = 0; ni < NI; ni++)
#pragma unroll
            for (int r = 0; r < 4; r++) acc[mi][ni][r] = 0.f;

#pragma unroll
    for (int i = 0; i < 6; i++) {
        const int idx = tid + i * 256;
        if (idx < 512) {
            const int r = idx >> 2, ch = idx & 3;
            CP_ASYNC16(sb + AW0 * 4 + r * 80 + ch * 16, mhh + (long long)(m0 + r) * EE + ch * 8);
        } else {
            const int j = idx - 512;
            const int r = j >> 3, c4 = (j & 7) * 4;
            CP_ASYNC16(sb + BR0 * 4 + j * 16, pkt + (long long)(n0 + r) * EE + c4);
        }
    }
    CP_COMMIT();

    for (int it = 0; it < 32; it++) {
        const bool more = it + 1 < 32;
        const int kbn = (it + 1) * 32;
        if (more) {
            const uint32_t adst = sb + (((it + 1) & 1) ? AW1 : AW0) * 4;
            const uint32_t bdst = sb + (((it + 1) & 1) ? BR1 : BR0) * 4;
#pragma unroll
            for (int i = 0; i < 6; i++) {
                const int idx = tid + i * 256;
                if (idx < 512) {
                    const int r = idx >> 2, ch = idx & 3;
                    CP_ASYNC16(adst + r * 80 + ch * 16,
                               mhh + (long long)(m0 + r) * EE + kbn + ch * 8);
                } else {
                    const int j = idx - 512;
                    const int r = j >> 3, c4 = (j & 7) * 4;
                    CP_ASYNC16(bdst + j * 16, pkt + (long long)(n0 + r) * EE + kbn + c4);
                }
            }
            CP_COMMIT();
            CP_WAIT1();
        } else {
            CP_WAIT0();
        }

        {
            const uint32_t bcur = (it & 1) ? BR1 : BR0;
#pragma unroll
            for (int i = 0; i < 4; i++) {
                const int j = tid + i * 256;
                const int r = j >> 3, c4 = (j & 7) * 4;
                float4 x = *(const float4*)(sw + bcur + j * 4);
                uint32_t* dh = sw + BH + r * WROW + (c4 >> 1);
                split_store_f16(x, dh, dh + (BL - BH));
            }
        }
        __syncthreads();

        {
            const uint32_t abase = sb + ((it & 1) ? AW1 : AW0) * 4;
#pragma unroll
            for (int kk2 = 0; kk2 < 2; kk2++) {
                uint32_t bh[NI][2], bl[NI][2];
#pragma unroll
                for (int np = 0; np < 2; np++) {
                    ldsm_x4(bh[np * 2][0], bh[np * 2][1], bh[np * 2 + 1][0], bh[np * 2 + 1][1],
                            sb + (uint32_t)BH * 4 + b_off[kk2][np]);
                    ldsm_x4(bl[np * 2][0], bl[np * 2][1], bl[np * 2 + 1][0], bl[np * 2 + 1][1],
                            sb + (uint32_t)BL * 4 + b_off[kk2][np]);
                }
#pragma unroll
                for (int mi = 0; mi < MI; mi++) {
                    uint32_t ah[4];
                    ldsm_x4(ah[0], ah[1], ah[2], ah[3], abase + a_off[kk2][mi]);
#pragma unroll
                    for (int ni = 0; ni < NI; ni++) {
                        mma16816h(acc[mi][ni], ah, bh[ni]);
                        mma16816h(acc[mi][ni], ah, bl[ni]);
                    }
                }
            }
        }
        if (more) __syncthreads();
    }

#pragma unroll
    for (int mi = 0; mi < MI; mi++) {
        const int r0 = m0 + wm * 64 + mi * 16 + g;
        const int r1 = r0 + 8;
#pragma unroll
        for (int ni = 0; ni < NI; ni++) {
            const int c = n0 + wn * 32 + ni * 8 + tg * 2;
            float2 bv = *(const float2*)&bias[c];
            *(float2*)&outp[(long long)r0 * OO + c] =
                make_float2(acc[mi][ni][0] + bv.x, acc[mi][ni][1] + bv.y);
            *(float2*)&outp[(long long)r1 * OO + c] =
                make_float2(acc[mi][ni][2] + bv.x, acc[mi][ni][3] + bv.y);
        }
    }
}

// ---------------------------------------------------------------------------
// rowsum helpers
// ---------------------------------------------------------------------------
__global__ void zero_rowsum(float* rs) {
    rs[blockIdx.x * 256 + threadIdx.x] = 0.f;
}
__global__ void invert_rowsum(float* rs) {
    const int i = blockIdx.x * 256 + threadIdx.x;
    rs[i] = 1.f / rs[i];
}

// ---------------------------------------------------------------------------
// Transposes
// ---------------------------------------------------------------------------
__global__ __launch_bounds__(256) void transpose_v(const float* __restrict__ v,
                                                   __half* __restrict__ vth,
                                                   __half* __restrict__ vtl)
{
    __shared__ float tile[32][33];
    const int z = blockIdx.z;
    const int b = z / HH, h = z % HH;
    const int m0 = blockIdx.x * 32;
    const int d0 = blockIdx.y * 32;
    const int tx = threadIdx.x & 31;
    const int ty0 = threadIdx.x >> 5;
#pragma unroll
    for (int ty = ty0; ty < 32; ty += 8)
        tile[ty][tx] = v[((long long)b * TT + m0 + ty) * EE + h * DD + d0 + tx];
    __syncthreads();
#pragma unroll
    for (int ty = ty0; ty < 32; ty += 8) {
        const float x = tile[tx][ty];
        const __half hi = __float2half_rn(x);
        const __half lo = __float2half_rn(x - __half2float(hi));
        const long long off = (((long long)z) * DD + d0 + ty) * TT + m0 + tx;
        vth[off] = hi;
        vtl[off] = lo;
    }
}

__global__ __launch_bounds__(256) void transpose_pk(const float* __restrict__ pk,
                                                    float* __restrict__ pkt)
{
    __shared__ float tile[32][33];
    const int k0 = blockIdx.x * 32;
    const int o0 = blockIdx.y * 32;
    const int tx = threadIdx.x & 31;
    const int ty0 = threadIdx.x >> 5;
#pragma unroll
    for (int ty = ty0; ty < 32; ty += 8)
        tile[ty][tx] = pk[(long long)(k0 + ty) * OO + o0 + tx];
    __syncthreads();
#pragma unroll
    for (int ty = ty0; ty < 32; ty += 8)
        pkt[(long long)(o0 + ty) * EE + k0 + tx] = tile[tx][ty];
}

// ---------------------------------------------------------------------------
// Launch
// ---------------------------------------------------------------------------
extern "C" void kernel_launch(void* const* d_in, const int* in_sizes, int n_in,
                              void* d_out, int out_size)
{
    const float* query = (const float*)d_in[0];
    const float* key   = (const float*)d_in[1];
    const float* value = (const float*)d_in[2];
    const float* Wq    = (const float*)d_in[3];
    const float* Wk    = (const float*)d_in[4];
    const float* Wv    = (const float*)d_in[5];
    const float* pk    = (const float*)d_in[6];
    const float* pb    = (const float*)d_in[7];

    float *vp, *pktp, *rsp, *outs, *attns;
    __half *ehp, *qhp, *khp, *klp, *mhhp, *vthp, *vtlp;
    cudaGetSymbolAddress((void**)&vp,    g_v);
    cudaGetSymbolAddress((void**)&mhhp,  g_mhh);
    cudaGetSymbolAddress((void**)&vthp,  g_vth);
    cudaGetSymbolAddress((void**)&vtlp,  g_vtl);
    cudaGetSymbolAddress((void**)&pktp,  g_pkt);
    cudaGetSymbolAddress((void**)&rsp,   g_rowsum);
    cudaGetSymbolAddress((void**)&ehp,   g_exph);
    cudaGetSymbolAddress((void**)&qhp,   g_qh);
    cudaGetSymbolAddress((void**)&khp,   g_kh);
    cudaGetSymbolAddress((void**)&klp,   g_kl);
    cudaGetSymbolAddress((void**)&outs,  g_out_scratch);
    cudaGetSymbolAddress((void**)&attns, g_attn_scratch);

    const long long outN  = (long long)BB * TT * OO;
    const long long attnN = (long long)BB * HH * TT * TT;

    float* outP  = (float*)d_out;
    float* attnP;
    if ((long long)out_size >= outN + attnN) {
        attnP = outP + outN;
    } else if ((long long)out_size == attnN) {
        attnP = (float*)d_out;
        outP  = outs;
    } else {
        attnP = attns;
    }

    constexpr int SMEMQKV  = (2 * 256 * 32 + 3 * 128 * 20) * 4;  // 96256
    constexpr int SMEMQK   = 23040 * 4;                          // 92160
    constexpr int SMEMAV   = 18432 * 4;                          // 73728
    constexpr int SMEMPROJ = 18432 * 4;                          // 73728
    cudaFuncSetAttribute((const void*)mma_qkv,
                         cudaFuncAttributeMaxDynamicSharedMemorySize, SMEMQKV);
    cudaFuncSetAttribute((const void*)mma_qk,
                         cudaFuncAttributeMaxDynamicSharedMemorySize, SMEMQK);
    cudaFuncSetAttribute((const void*)mma_av,
                         cudaFuncAttributeMaxDynamicSharedMemorySize, SMEMAV);
    cudaFuncSetAttribute((const void*)mma_proj,
                         cudaFuncAttributeMaxDynamicSharedMemorySize, SMEMPROJ);

    // 0) zero row sums
    zero_rowsum<<<(BB * HH * TT) / 256, 256>>>(rsp);

    // 1) QKV projections (fp16 2-term): qh / kh,kl / v
    {
        dim3 grid(EE / 128, (BB * TT) / 128, 3);
        mma_qkv<<<grid, 256, SMEMQKV>>>(query, key, value, Wq, Wk, Wv,
                                        qhp, khp, klp, vp);
    }

    // transposes: V -> fp16 hi/lo [z][d][m]; pk -> [o][k]
    {
        dim3 gv(TT / 32, DD / 32, BB * HH);
        transpose_v<<<gv, 256>>>(vp, vthp, vtlp);
        dim3 gp(EE / 32, OO / 32, 1);
        transpose_pk<<<gp, 256>>>(pk, pktp);
    }

    // 2) exph = fp16(exp(0.125 * q @ k^T))
    {
        dim3 grid(TT / 128, BB * HH);
        mma_qk<<<grid, 256, SMEMQK>>>(qhp, khp, klp, rsp, ehp);
    }

    // 3) invert row sums
    invert_rowsum<<<(BB * HH * TT) / 256, 256>>>(rsp);

    // 4) mh(fp16) = inv * (exph @ vT^T); streams normalized fp32 attn once
    {
        dim3 grid(TT / 128, BB * HH);
        mma_av<<<grid, 256, SMEMAV>>>(ehp, vthp, vtlp, rsp, attnP, mhhp);
    }

    // 5) out = mhh @ pkt^T + bias
    {
        dim3 grid(OO / 128, (BB * TT) / 128, 1);
        mma_proj<<<grid, 256, SMEMPROJ>>>(mhhp, pktp, pb, outP);
    }
}